// round 9
// baseline (speedup 1.0000x reference)
#include <cuda_runtime.h>
#include <cuda_bf16.h>
#include <stdint.h>
#include <math.h>

#define Bb    2
#define Nn    1024
#define DIMM  1024
#define HEADS 16
#define HD    64
#define Mtot  (Bb * Nn)      // 2048
#define E3    (3 * DIMM)     // 3072

// ---------------- bf16 hi/lo split scratch -----------------------------------
__device__ __nv_bfloat16 g_Xr_h[Mtot * DIMM], g_Xr_l[Mtot * DIMM];
__device__ __nv_bfloat16 g_Xi_h[Mtot * DIMM], g_Xi_l[Mtot * DIMM];
__device__ __nv_bfloat16 g_Wqr_h[E3 * DIMM],  g_Wqr_l[E3 * DIMM];
__device__ __nv_bfloat16 g_Wqi_h[E3 * DIMM],  g_Wqi_l[E3 * DIMM];
__device__ __nv_bfloat16 g_Wor_h[DIMM * DIMM], g_Wor_l[DIMM * DIMM];
__device__ __nv_bfloat16 g_Woi_h[DIMM * DIMM], g_Woi_l[DIMM * DIMM];
__device__ __nv_bfloat16 g_Ar_h[Mtot * DIMM], g_Ar_l[Mtot * DIMM];
__device__ __nv_bfloat16 g_Ai_h[Mtot * DIMM], g_Ai_l[Mtot * DIMM];

// Q/K/V bf16 hi/lo, layout [b*H + h][d][n]  (n innermost)
#define QKV_SZ (Bb * HEADS * Nn * HD)
__device__ __nv_bfloat16 g_Qrh[QKV_SZ], g_Qrl[QKV_SZ], g_Qih[QKV_SZ], g_Qil[QKV_SZ];
__device__ __nv_bfloat16 g_Krh[QKV_SZ], g_Krl[QKV_SZ], g_Kih[QKV_SZ], g_Kil[QKV_SZ];
__device__ __nv_bfloat16 g_Vrh[QKV_SZ], g_Vrl[QKV_SZ], g_Vih[QKV_SZ], g_Vil[QKV_SZ];

// ---------------- helpers ----------------------------------------------------
__device__ __forceinline__ uint32_t smem_u32(const void* p) {
    uint32_t a;
    asm("{ .reg .u64 t; cvta.to.shared.u64 t, %1; cvt.u32.u64 %0, t; }"
        : "=r"(a) : "l"(p));
    return a;
}

#define CP16(dst, src) \
    asm volatile("cp.async.cg.shared.global [%0], [%1], 16;" \
                 :: "r"((uint32_t)(dst)), "l"(src) : "memory")
#define CP_COMMIT() asm volatile("cp.async.commit_group;" ::: "memory")
#define CP_WAIT(n)  asm volatile("cp.async.wait_group %0;" :: "n"(n) : "memory")

__device__ __forceinline__ void ldm_x4(uint32_t* r, uint32_t addr) {
    asm volatile("ldmatrix.sync.aligned.m8n8.x4.shared.b16 {%0,%1,%2,%3}, [%4];"
        : "=r"(r[0]), "=r"(r[1]), "=r"(r[2]), "=r"(r[3]) : "r"(addr));
}

__device__ __forceinline__ void ldm_x4_t(uint32_t* r, uint32_t addr) {
    asm volatile("ldmatrix.sync.aligned.m8n8.x4.trans.shared.b16 {%0,%1,%2,%3}, [%4];"
        : "=r"(r[0]), "=r"(r[1]), "=r"(r[2]), "=r"(r[3]) : "r"(addr));
}

__device__ __forceinline__ void mma16816(float* c, const uint32_t* a, const uint32_t* b) {
    asm volatile("mma.sync.aligned.m16n8k16.row.col.f32.bf16.bf16.f32 "
        "{%0,%1,%2,%3}, {%4,%5,%6,%7}, {%8,%9}, {%0,%1,%2,%3};"
        : "+f"(c[0]), "+f"(c[1]), "+f"(c[2]), "+f"(c[3])
        : "r"(a[0]), "r"(a[1]), "r"(a[2]), "r"(a[3]), "r"(b[0]), "r"(b[1]));
}

__device__ __forceinline__ void split2(float a, float b, uint32_t& hi, uint32_t& lo) {
    __nv_bfloat16 ah = __float2bfloat16(a), bh = __float2bfloat16(b);
    float ar = a - __bfloat162float(ah), br = b - __bfloat162float(bh);
    __nv_bfloat162 h; h.x = ah; h.y = bh;
    __nv_bfloat162 l; l.x = __float2bfloat16(ar); l.y = __float2bfloat16(br);
    hi = *(uint32_t*)&h;
    lo = *(uint32_t*)&l;
}

// ---------------- combined input split kernel --------------------------------
__global__ void __launch_bounds__(256) split_all_kernel(
    const float* __restrict__ xr,  const float* __restrict__ xi,
    const float* __restrict__ wqr, const float* __restrict__ wqi,
    const float* __restrict__ wor, const float* __restrict__ woi)
{
    const int blk = blockIdx.x;
    const float* src; __nv_bfloat16 *hi, *lo; int off;
    if      (blk <  2048) { src = xr;  hi = g_Xr_h;  lo = g_Xr_l;  off = blk; }
    else if (blk <  4096) { src = xi;  hi = g_Xi_h;  lo = g_Xi_l;  off = blk - 2048; }
    else if (blk <  7168) { src = wqr; hi = g_Wqr_h; lo = g_Wqr_l; off = blk - 4096; }
    else if (blk < 10240) { src = wqi; hi = g_Wqi_h; lo = g_Wqi_l; off = blk - 7168; }
    else if (blk < 11264) { src = wor; hi = g_Wor_h; lo = g_Wor_l; off = blk - 10240; }
    else                  { src = woi; hi = g_Woi_h; lo = g_Woi_l; off = blk - 11264; }
    const int i = (off * 256 + threadIdx.x) * 4;
    float4 x = *(const float4*)(src + i);
    uint32_t h01, l01, h23, l23;
    split2(x.x, x.y, h01, l01);
    split2(x.z, x.w, h23, l23);
    *(uint2*)(hi + i) = make_uint2(h01, h23);
    *(uint2*)(lo + i) = make_uint2(l01, l23);
}

// ---------------- mma.sync complex GEMM core (2-blocks/SM config) ------------
// Block 128(m) x 64(n), 256 threads, 8 warps as 8(m) x 1(n), warp tile 16x64.
// K-chunk 16, 3-stage cp.async pipeline, pitch 48 B (conflict-free ldmatrix).
// Stage: A[v] at v*6144 (128 rows x 48B), B[v] at 24576 + v*3072 (64 rows).
#define STG3 36864
#define GEMM_SMEM (3 * STG3)
#define NCH16 (DIMM / 16)

__device__ __forceinline__ void stage_load16(uint32_t sA,
    const __nv_bfloat16* const* Av, const __nv_bfloat16* const* Bv,
    int m0, int e0, int k0, int tid)
{
    const int r = tid >> 1, c = tid & 1;
    #pragma unroll
    for (int v = 0; v < 4; v++)
        CP16(sA + v * 6144u + r * 48 + c * 16,
             Av[v] + (size_t)(m0 + r) * DIMM + k0 + c * 8);
    if (tid < 128) {
        #pragma unroll
        for (int v = 0; v < 4; v++)
            CP16(sA + 24576u + v * 3072u + r * 48 + c * 16,
                 Bv[v] + (size_t)(e0 + r) * DIMM + k0 + c * 8);
    }
}

__device__ __forceinline__ void gemm_compute16(uint32_t ss, int lane, int wm,
    float accR[8][4], float accI[8][4])
{
    const uint32_t aRow = (uint32_t)(lane & 15);
    const uint32_t aSel = (uint32_t)(lane >> 4);
    const uint32_t nl   = (uint32_t)((lane & 7) + ((lane >> 4) << 3));
    const uint32_t ksel = (uint32_t)((lane >> 3) & 1);

    uint32_t Af[4][4];     // Arh, Arl, Aih, Ail
    const uint32_t qa = ss + (wm * 16 + aRow) * 48u + aSel * 16u;
    #pragma unroll
    for (int v = 0; v < 4; v++) ldm_x4(Af[v], qa + v * 6144u);

    #pragma unroll
    for (int h = 0; h < 4; h++) {
        uint32_t Bf[4][4];  // Brh, Brl, Bih, Bil
        const uint32_t ba = ss + 24576u + (h * 16 + nl) * 48u + ksel * 16u;
        #pragma unroll
        for (int v = 0; v < 4; v++) ldm_x4(Bf[v], ba + v * 3072u);
        uint32_t nBih[4], nBil[4];
        #pragma unroll
        for (int q = 0; q < 4; q++) {
            nBih[q] = Bf[2][q] ^ 0x80008000u;
            nBil[q] = Bf[3][q] ^ 0x80008000u;
        }
        #pragma unroll
        for (int sub = 0; sub < 2; sub++) {
            const int nf = h * 2 + sub;
            const uint32_t* Brh = &Bf[0][sub * 2];
            const uint32_t* Brl = &Bf[1][sub * 2];
            const uint32_t* Bih = &Bf[2][sub * 2];
            const uint32_t* Bil = &Bf[3][sub * 2];
            const uint32_t* mBih = &nBih[sub * 2];
            const uint32_t* mBil = &nBil[sub * 2];
            float* cr = accR[nf];
            float* ci = accI[nf];
            // real = ArBr - AiBi
            mma16816(cr, Af[0], Brh);
            mma16816(cr, Af[0], Brl);
            mma16816(cr, Af[1], Brh);
            mma16816(cr, Af[2], mBih);
            mma16816(cr, Af[2], mBil);
            mma16816(cr, Af[3], mBih);
            // imag = ArBi + AiBr
            mma16816(ci, Af[0], Bih);
            mma16816(ci, Af[0], Bil);
            mma16816(ci, Af[1], Bih);
            mma16816(ci, Af[2], Brh);
            mma16816(ci, Af[2], Brl);
            mma16816(ci, Af[3], Brh);
        }
    }
}

// Shared mainloop: 3-stage pipeline, one barrier per chunk.
#define GEMM_MAINLOOP(Av, Bv, m0, e0)                                          \
    float accR[8][4] = {}, accI[8][4] = {};                                    \
    stage_load16(sb, Av, Bv, m0, e0, 0, tid);  CP_COMMIT();                    \
    stage_load16(sb + STG3, Av, Bv, m0, e0, 16, tid); CP_COMMIT();             \
    _Pragma("unroll 1")                                                        \
    for (int c = 0; c < NCH16; c++) {                                          \
        if (c < NCH16 - 1) { CP_WAIT(1); } else { CP_WAIT(0); }                \
        __syncthreads();                                                       \
        if (c + 2 < NCH16) {                                                   \
            stage_load16(sb + ((c + 2) % 3) * STG3, Av, Bv, m0, e0,            \
                         (c + 2) * 16, tid);                                   \
            CP_COMMIT();                                                       \
        }                                                                      \
        gemm_compute16(sb + (c % 3) * STG3, lane, wm, accR, accI);             \
    }

// ---------------- qkv GEMM: smem-staged epilogue, [bh][d][n] writes ----------
__global__ void __launch_bounds__(256, 2) qkv_mma_kernel(
    const float* __restrict__ br, const float* __restrict__ bi,
    const float* __restrict__ fr, const float* __restrict__ fi)
{
    extern __shared__ char smrw[];
    const uint32_t sb = smem_u32(smrw);
    const int tid = threadIdx.x, lane = tid & 31, wm = tid >> 5;
    const int e0 = blockIdx.x * 64, m0 = blockIdx.y * 128;

    const __nv_bfloat16* Av[4] = {g_Xr_h, g_Xr_l, g_Xi_h, g_Xi_l};
    const __nv_bfloat16* Bv[4] = {g_Wqr_h, g_Wqr_l, g_Wqi_h, g_Wqi_l};

    GEMM_MAINLOOP(Av, Bv, m0, e0)
    __syncthreads();

    // ---- stage accumulators to smem as [e 64][m pitch 132] fp32 ----
    float* smr = (float*)smrw;
    float* smi = smr + 64 * 132;
    #pragma unroll
    for (int nf = 0; nf < 8; nf++)
        #pragma unroll
        for (int rp = 0; rp < 2; rp++)
            #pragma unroll
            for (int cp = 0; cp < 2; cp++) {
                const int el = nf * 8 + (lane & 3) * 2 + cp;
                const int ml = wm * 16 + (lane >> 2) + rp * 8;
                smr[el * 132 + ml] = accR[nf][rp * 2 + cp];
                smi[el * 132 + ml] = accI[nf][rp * 2 + cp];
            }
    __syncthreads();

    // ---- each thread: one e-column quarter, packed uint2 n-run stores ----
    const int el = tid >> 2, q = tid & 3;
    const int e = e0 + el;
    const int h = e / 192, rem = e % 192;
    const int d = rem / 3, which = rem % 3;
    const float bre = br[e], bie = bi[e];
    const int b = m0 >> 10, n0 = (m0 & 1023) + q * 32;
    const int bh = b * HEADS + h;
    __nv_bfloat16 *dRh, *dRl, *dIh, *dIl;
    if (which == 0)      { dRh = g_Qrh; dRl = g_Qrl; dIh = g_Qih; dIl = g_Qil; }
    else if (which == 1) { dRh = g_Krh; dRl = g_Krl; dIh = g_Kih; dIl = g_Kil; }
    else                 { dRh = g_Vrh; dRl = g_Vrl; dIh = g_Vih; dIl = g_Vil; }
    const size_t dbase = (size_t)(bh * HD + d) * Nn + n0;
    const float* smr_e = smr + el * 132 + q * 32;
    const float* smi_e = smi + el * 132 + q * 32;

    #pragma unroll 1
    for (int mc = 0; mc < 8; mc++) {
        float4 srv = *(const float4*)(smr_e + mc * 4);
        float4 siv = *(const float4*)(smi_e + mc * 4);
        float vr[4] = {srv.x + bre, srv.y + bre, srv.z + bre, srv.w + bre};
        float vi[4] = {siv.x + bie, siv.y + bie, siv.z + bie, siv.w + bie};
        if (which < 2) {
            #pragma unroll
            for (int j = 0; j < 4; j++) {
                const int n = n0 + mc * 4 + j;
                const float frv = fr[n * HD + d], fiv = fi[n * HD + d];
                const float rr = vr[j] * frv - vi[j] * fiv;
                vi[j] = vr[j] * fiv + vi[j] * frv;
                vr[j] = rr;
            }
        }
        uint32_t h01, l01, h23, l23;
        split2(vr[0], vr[1], h01, l01);
        split2(vr[2], vr[3], h23, l23);
        *(uint2*)(dRh + dbase + mc * 4) = make_uint2(h01, h23);
        *(uint2*)(dRl + dbase + mc * 4) = make_uint2(l01, l23);
        split2(vi[0], vi[1], h01, l01);
        split2(vi[2], vi[3], h23, l23);
        *(uint2*)(dIh + dbase + mc * 4) = make_uint2(h01, h23);
        *(uint2*)(dIl + dbase + mc * 4) = make_uint2(l01, l23);
    }
}

// ---------------- output GEMM (float2-packed epilogue) -----------------------
__global__ void __launch_bounds__(256, 2) out_mma_kernel(
    const float* __restrict__ br, const float* __restrict__ bi,
    float* __restrict__ out)
{
    extern __shared__ char smrw[];
    const uint32_t sb = smem_u32(smrw);
    const int tid = threadIdx.x, lane = tid & 31, wm = tid >> 5;
    const int e0 = blockIdx.x * 64, m0 = blockIdx.y * 128;

    const __nv_bfloat16* Av[4] = {g_Ar_h, g_Ar_l, g_Ai_h, g_Ai_l};
    const __nv_bfloat16* Bv[4] = {g_Wor_h, g_Wor_l, g_Woi_h, g_Woi_l};

    GEMM_MAINLOOP(Av, Bv, m0, e0)

    #pragma unroll
    for (int nf = 0; nf < 8; nf++)
        #pragma unroll
        for (int rp = 0; rp < 2; rp++) {
            const int m = m0 + wm * 16 + (lane >> 2) + rp * 8;
            const int e = e0 + nf * 8 + (lane & 3) * 2;
            float2 vr = make_float2(accR[nf][rp * 2] + br[e],
                                    accR[nf][rp * 2 + 1] + br[e + 1]);
            float2 vi = make_float2(accI[nf][rp * 2] + bi[e],
                                    accI[nf][rp * 2 + 1] + bi[e + 1]);
            *(float2*)&out[(size_t)m * DIMM + e] = vr;
            *(float2*)&out[(size_t)Mtot * DIMM + (size_t)m * DIMM + e] = vi;
        }
}

// ---------------- tensor-core flash attention ([bh][d][n] inputs) ------------
#define PCHQ 272
#define VQ   17408
#define PCHK 144
#define VKV  9216
#define SK_OFF (4 * VQ)
#define STG_KV (4 * VKV)
#define SV_OFF (SK_OFF + 2 * STG_KV)
#define ATTN_SMEM (SV_OFF + 2 * STG_KV)

__device__ __forceinline__ void load_kv(uint32_t sb,
    const __nv_bfloat16* const* Kv, const __nv_bfloat16* const* Vv,
    int k0, int s, int tid)
{
    #pragma unroll
    for (int v = 0; v < 4; v++)
        #pragma unroll
        for (int t = 0; t < 2; t++) {
            int i = tid + t * 256;
            int r = i >> 3, c = i & 7;
            CP16(sb + SK_OFF + s * STG_KV + v * VKV + r * PCHK + c * 16,
                 Kv[v] + (size_t)r * Nn + k0 + c * 8);
            CP16(sb + SV_OFF + s * STG_KV + v * VKV + r * PCHK + c * 16,
                 Vv[v] + (size_t)r * Nn + k0 + c * 8);
        }
}

__global__ void __launch_bounds__(256, 1) attn_mma_kernel()
{
    extern __shared__ char smrw[];
    const uint32_t sb = smem_u32(smrw);
    const int tid = threadIdx.x, lane = tid & 31, wid = tid >> 5;
    const int bh = blockIdx.y, q0 = blockIdx.x * 128;
    const size_t base = (size_t)bh * Nn * HD;

    const __nv_bfloat16* Qv[4] = {g_Qrh + base, g_Qrl + base, g_Qih + base, g_Qil + base};
    const __nv_bfloat16* Kv[4] = {g_Krh + base, g_Krl + base, g_Kih + base, g_Kil + base};
    const __nv_bfloat16* Vv[4] = {g_Vrh + base, g_Vrl + base, g_Vih + base, g_Vil + base};

    #pragma unroll
    for (int v = 0; v < 4; v++)
        #pragma unroll
        for (int t = 0; t < 4; t++) {
            int i = tid + t * 256;
            int r = i >> 4, c = i & 15;
            CP16(sb + v * VQ + r * PCHQ + c * 16, Qv[v] + (size_t)r * Nn + q0 + c * 8);
        }
    load_kv(sb, Kv, Vv, 0, 0, tid);
    CP_COMMIT();

    float oR[8][4] = {}, oI[8][4] = {};
    float m0 = -1e30f, m1 = -1e30f, l0 = 0.f, l1 = 0.f;
    const int r0 = wid * 16;

    #pragma unroll 1
    for (int kt = 0; kt < 16; kt++) {
        const int s = kt & 1;
        if (kt + 1 < 16) {
            load_kv(sb, Kv, Vv, (kt + 1) * 64, s ^ 1, tid);
            CP_COMMIT();
            CP_WAIT(1);
        } else {
            CP_WAIT(0);
        }
        __syncthreads();

        const uint32_t sK = sb + SK_OFF + s * STG_KV;
        const uint32_t sV = sb + SV_OFF + s * STG_KV;

        float sR[8][4] = {}, sI[8][4] = {};
        #pragma unroll
        for (int ks = 0; ks < 4; ks++) {
            uint32_t Qf[4][4];
            const uint32_t qa = sb
                + (ks * 16 + (lane & 7) + ((lane >> 4) & 1) * 8) * PCHQ
                + (r0 + ((lane >> 3) & 1) * 8) * 2;
            #pragma unroll
            for (int v = 0; v < 4; v++) ldm_x4_t(Qf[v], qa + v * VQ);
            uint32_t nQrh[4], nQrl[4];
            #pragma unroll
            for (int q = 0; q < 4; q++) {
                nQrh[q] = Qf[0][q] ^ 0x80008000u;
                nQrl[q] = Qf[1][q] ^ 0x80008000u;
            }
            #pragma unroll
            for (int np = 0; np < 4; np++) {
                uint32_t Kf[4][4];
                const uint32_t ka = sK
                    + (ks * 16 + (lane & 7) + ((lane >> 3) & 1) * 8) * PCHK
                    + (np * 16 + ((lane >> 4) & 1) * 8) * 2;
                #pragma unroll
                for (int v = 0; v < 4; v++) ldm_x4_t(Kf[v], ka + v * VKV);
                #pragma unroll
                for (int sub = 0; sub < 2; sub++) {
                    const int nt = np * 2 + sub;
                    const uint32_t* Krh = &Kf[0][sub * 2];
                    const uint32_t* Krl = &Kf[1][sub * 2];
                    const uint32_t* Kih = &Kf[2][sub * 2];
                    const uint32_t* Kil = &Kf[3][sub * 2];
                    mma16816(sR[nt], Qf[0], Krh);
                    mma16816(sR[nt], Qf[0], Krl);
                    mma16816(sR[nt], Qf[1], Krh);
                    mma16816(sR[nt], Qf[2], Kih);
                    mma16816(sR[nt], Qf[2], Kil);
                    mma16816(sR[nt], Qf[3], Kih);
                    mma16816(sI[nt], Qf[2], Krh);
                    mma16816(sI[nt], Qf[2], Krl);
                    mma16816(sI[nt], Qf[3], Krh);
                    mma16816(sI[nt], nQrh,  Kih);
                    mma16816(sI[nt], nQrh,  Kil);
                    mma16816(sI[nt], nQrl,  Kih);
                }
            }
        }

        float vm0 = -1e30f, vm1 = -1e30f;
        #pragma unroll
        for (int nt = 0; nt < 8; nt++)
            #pragma unroll
            for (int p = 0; p < 4; p++) {
                const float v = 0.125f * sqrtf(sR[nt][p] * sR[nt][p] + sI[nt][p] * sI[nt][p]);
                sR[nt][p] = v;
                if (p < 2) vm0 = fmaxf(vm0, v); else vm1 = fmaxf(vm1, v);
            }
        vm0 = fmaxf(vm0, __shfl_xor_sync(0xffffffffu, vm0, 1));
        vm0 = fmaxf(vm0, __shfl_xor_sync(0xffffffffu, vm0, 2));
        vm1 = fmaxf(vm1, __shfl_xor_sync(0xffffffffu, vm1, 1));
        vm1 = fmaxf(vm1, __shfl_xor_sync(0xffffffffu, vm1, 2));
        const float mn0 = fmaxf(m0, vm0), mn1 = fmaxf(m1, vm1);
        const float a0 = __expf(m0 - mn0), a1 = __expf(m1 - mn1);
        m0 = mn0; m1 = mn1;
        #pragma unroll
        for (int nt = 0; nt < 8; nt++)
            #pragma unroll
            for (int p = 0; p < 4; p++) {
                const float al = (p < 2) ? a0 : a1;
                oR[nt][p] *= al;
                oI[nt][p] *= al;
            }
        float s0 = 0.f, s1 = 0.f;
        #pragma unroll
        for (int nt = 0; nt < 8; nt++)
            #pragma unroll
            for (int p = 0; p < 4; p++) {
                const float pv = __expf(sR[nt][p] - ((p < 2) ? mn0 : mn1));
                sR[nt][p] = pv;
                if (p < 2) s0 += pv; else s1 += pv;
            }
        s0 += __shfl_xor_sync(0xffffffffu, s0, 1);
        s0 += __shfl_xor_sync(0xffffffffu, s0, 2);
        s1 += __shfl_xor_sync(0xffffffffu, s1, 1);
        s1 += __shfl_xor_sync(0xffffffffu, s1, 2);
        l0 = l0 * a0 + s0;
        l1 = l1 * a1 + s1;

        uint32_t Ph[4][4], Pl[4][4];
        #pragma unroll
        for (int j = 0; j < 4; j++) {
            const int t0 = 2 * j, t1 = 2 * j + 1;
            split2(sR[t0][0], sR[t0][1], Ph[j][0], Pl[j][0]);
            split2(sR[t0][2], sR[t0][3], Ph[j][1], Pl[j][1]);
            split2(sR[t1][0], sR[t1][1], Ph[j][2], Pl[j][2]);
            split2(sR[t1][2], sR[t1][3], Ph[j][3], Pl[j][3]);
        }

        #pragma unroll
        for (int j = 0; j < 4; j++) {
            #pragma unroll
            for (int g = 0; g < 4; g++) {
                uint32_t Vf[4][4];
                const uint32_t va = sV
                    + (g * 16 + (lane & 7) + ((lane >> 4) & 1) * 8) * PCHK
                    + j * 32 + ((lane >> 3) & 1) * 16;
                #pragma unroll
                for (int v = 0; v < 4; v++) ldm_x4(Vf[v], va + v * VKV);
                #pragma unroll
                for (int sub = 0; sub < 2; sub++) {
                    const int nt = g * 2 + sub;
                    const uint32_t* Vrh = &Vf[0][sub * 2];
                    const uint32_t* Vrl = &Vf[1][sub * 2];
                    const uint32_t* Vih = &Vf[2][sub * 2];
                    const uint32_t* Vil = &Vf[3][sub * 2];
                    mma16816(oR[nt], Ph[j], Vrh);
                    mma16816(oR[nt], Pl[j], Vrh);
                    mma16816(oR[nt], Ph[j], Vrl);
                    mma16816(oI[nt], Ph[j], Vih);
                    mma16816(oI[nt], Pl[j], Vih);
                    mma16816(oI[nt], Ph[j], Vil);
                }
            }
        }
        __syncthreads();
    }

    const float inv0 = 1.0f / l0, inv1 = 1.0f / l1;
    const int b = bh / HEADS, h = bh % HEADS;
    #pragma unroll
    for (int nt = 0; nt < 8; nt++)
        #pragma unroll
        for (int rp = 0; rp < 2; rp++) {
            const int n = q0 + r0 + (lane >> 2) + rp * 8;
            const int d0 = nt * 8 + (lane & 3) * 2;
            const float inv = (rp == 0) ? inv0 : inv1;
            const size_t idx = ((size_t)(b * Nn + n)) * DIMM + h * HD + d0;
            uint32_t hh, ll;
            split2(oR[nt][rp * 2] * inv, oR[nt][rp * 2 + 1] * inv, hh, ll);
            *(uint32_t*)(g_Ar_h + idx) = hh;
            *(uint32_t*)(g_Ar_l + idx) = ll;
            split2(oI[nt][rp * 2] * inv, oI[nt][rp * 2 + 1] * inv, hh, ll);
            *(uint32_t*)(g_Ai_h + idx) = hh;
            *(uint32_t*)(g_Ai_l + idx) = ll;
        }
}

// ---------------- launch ------------------------------------------------------
extern "C" void kernel_launch(void* const* d_in, const int* in_sizes, int n_in,
                              void* d_out, int out_size)
{
    const float* xr  = (const float*)d_in[0];
    const float* xi  = (const float*)d_in[1];
    const float* fr  = (const float*)d_in[2];
    const float* fi  = (const float*)d_in[3];
    const float* wqr = (const float*)d_in[4];
    const float* wqi = (const float*)d_in[5];
    const float* bqr = (const float*)d_in[6];
    const float* bqi = (const float*)d_in[7];
    const float* wor = (const float*)d_in[8];
    const float* woi = (const float*)d_in[9];
    const float* bor = (const float*)d_in[10];
    const float* boi = (const float*)d_in[11];
    float* out = (float*)d_out;

    cudaFuncSetAttribute(qkv_mma_kernel,
                         cudaFuncAttributeMaxDynamicSharedMemorySize, GEMM_SMEM);
    cudaFuncSetAttribute(out_mma_kernel,
                         cudaFuncAttributeMaxDynamicSharedMemorySize, GEMM_SMEM);
    cudaFuncSetAttribute(attn_mma_kernel,
                         cudaFuncAttributeMaxDynamicSharedMemorySize, ATTN_SMEM);

    split_all_kernel<<<12288, 256>>>(xr, xi, wqr, wqi, wor, woi);
    qkv_mma_kernel<<<dim3(E3 / 64, Mtot / 128), 256, GEMM_SMEM>>>(bqr, bqi, fr, fi);
    attn_mma_kernel<<<dim3(Nn / 128, Bb * HEADS), 256, ATTN_SMEM>>>();
    out_mma_kernel<<<dim3(DIMM / 64, Mtot / 128), 256, GEMM_SMEM>>>(bor, boi, out);
}

// round 10
// speedup vs baseline: 1.0139x; 1.0139x over previous
#include <cuda_runtime.h>
#include <cuda_bf16.h>
#include <stdint.h>
#include <math.h>

#define Bb    2
#define Nn    1024
#define DIMM  1024
#define HEADS 16
#define HD    64
#define Mtot  (Bb * Nn)      // 2048
#define E3    (3 * DIMM)     // 3072

// ---------------- bf16 hi/lo split scratch -----------------------------------
__device__ __nv_bfloat16 g_Xr_h[Mtot * DIMM], g_Xr_l[Mtot * DIMM];
__device__ __nv_bfloat16 g_Xi_h[Mtot * DIMM], g_Xi_l[Mtot * DIMM];
__device__ __nv_bfloat16 g_Wqr_h[E3 * DIMM],  g_Wqr_l[E3 * DIMM];
__device__ __nv_bfloat16 g_Wqi_h[E3 * DIMM],  g_Wqi_l[E3 * DIMM];
__device__ __nv_bfloat16 g_Wor_h[DIMM * DIMM], g_Wor_l[DIMM * DIMM];
__device__ __nv_bfloat16 g_Woi_h[DIMM * DIMM], g_Woi_l[DIMM * DIMM];
__device__ __nv_bfloat16 g_Ar_h[Mtot * DIMM], g_Ar_l[Mtot * DIMM];
__device__ __nv_bfloat16 g_Ai_h[Mtot * DIMM], g_Ai_l[Mtot * DIMM];

// Q/K/V bf16 hi/lo, layout [b*H + h][d][n]  (n innermost)
#define QKV_SZ (Bb * HEADS * Nn * HD)
__device__ __nv_bfloat16 g_Qrh[QKV_SZ], g_Qrl[QKV_SZ], g_Qih[QKV_SZ], g_Qil[QKV_SZ];
__device__ __nv_bfloat16 g_Krh[QKV_SZ], g_Krl[QKV_SZ], g_Kih[QKV_SZ], g_Kil[QKV_SZ];
__device__ __nv_bfloat16 g_Vrh[QKV_SZ], g_Vrl[QKV_SZ], g_Vih[QKV_SZ], g_Vil[QKV_SZ];

// ---------------- helpers ----------------------------------------------------
__device__ __forceinline__ uint32_t smem_u32(const void* p) {
    uint32_t a;
    asm("{ .reg .u64 t; cvta.to.shared.u64 t, %1; cvt.u32.u64 %0, t; }"
        : "=r"(a) : "l"(p));
    return a;
}

#define CP16(dst, src) \
    asm volatile("cp.async.cg.shared.global [%0], [%1], 16;" \
                 :: "r"((uint32_t)(dst)), "l"(src) : "memory")
#define CP_COMMIT() asm volatile("cp.async.commit_group;" ::: "memory")
#define CP_WAIT(n)  asm volatile("cp.async.wait_group %0;" :: "n"(n) : "memory")

__device__ __forceinline__ void ldm_x4(uint32_t* r, uint32_t addr) {
    asm volatile("ldmatrix.sync.aligned.m8n8.x4.shared.b16 {%0,%1,%2,%3}, [%4];"
        : "=r"(r[0]), "=r"(r[1]), "=r"(r[2]), "=r"(r[3]) : "r"(addr));
}

__device__ __forceinline__ void ldm_x4_t(uint32_t* r, uint32_t addr) {
    asm volatile("ldmatrix.sync.aligned.m8n8.x4.trans.shared.b16 {%0,%1,%2,%3}, [%4];"
        : "=r"(r[0]), "=r"(r[1]), "=r"(r[2]), "=r"(r[3]) : "r"(addr));
}

__device__ __forceinline__ void mma16816(float* c, const uint32_t* a, const uint32_t* b) {
    asm volatile("mma.sync.aligned.m16n8k16.row.col.f32.bf16.bf16.f32 "
        "{%0,%1,%2,%3}, {%4,%5,%6,%7}, {%8,%9}, {%0,%1,%2,%3};"
        : "+f"(c[0]), "+f"(c[1]), "+f"(c[2]), "+f"(c[3])
        : "r"(a[0]), "r"(a[1]), "r"(a[2]), "r"(a[3]), "r"(b[0]), "r"(b[1]));
}

__device__ __forceinline__ void split2(float a, float b, uint32_t& hi, uint32_t& lo) {
    __nv_bfloat16 ah = __float2bfloat16(a), bh = __float2bfloat16(b);
    float ar = a - __bfloat162float(ah), br = b - __bfloat162float(bh);
    __nv_bfloat162 h; h.x = ah; h.y = bh;
    __nv_bfloat162 l; l.x = __float2bfloat16(ar); l.y = __float2bfloat16(br);
    hi = *(uint32_t*)&h;
    lo = *(uint32_t*)&l;
}

// ---------------- combined input split kernel --------------------------------
__global__ void __launch_bounds__(256) split_all_kernel(
    const float* __restrict__ xr,  const float* __restrict__ xi,
    const float* __restrict__ wqr, const float* __restrict__ wqi,
    const float* __restrict__ wor, const float* __restrict__ woi)
{
    const int blk = blockIdx.x;
    const float* src; __nv_bfloat16 *hi, *lo; int off;
    if      (blk <  2048) { src = xr;  hi = g_Xr_h;  lo = g_Xr_l;  off = blk; }
    else if (blk <  4096) { src = xi;  hi = g_Xi_h;  lo = g_Xi_l;  off = blk - 2048; }
    else if (blk <  7168) { src = wqr; hi = g_Wqr_h; lo = g_Wqr_l; off = blk - 4096; }
    else if (blk < 10240) { src = wqi; hi = g_Wqi_h; lo = g_Wqi_l; off = blk - 7168; }
    else if (blk < 11264) { src = wor; hi = g_Wor_h; lo = g_Wor_l; off = blk - 10240; }
    else                  { src = woi; hi = g_Woi_h; lo = g_Woi_l; off = blk - 11264; }
    const int i = (off * 256 + threadIdx.x) * 4;
    float4 x = *(const float4*)(src + i);
    uint32_t h01, l01, h23, l23;
    split2(x.x, x.y, h01, l01);
    split2(x.z, x.w, h23, l23);
    *(uint2*)(hi + i) = make_uint2(h01, h23);
    *(uint2*)(lo + i) = make_uint2(l01, l23);
}

// ---------------- mma.sync complex GEMM core (R8 config) ---------------------
// Block 128x128, 256 threads, 8 warps as 4(m) x 2(n), warp tile 32x64.
#define STG 81920
#define GEMM_SMEM (2 * STG)
#define NCHUNK (DIMM / 32)

__device__ __forceinline__ void stage_load(uint32_t sA,
    const __nv_bfloat16* const* Av, const __nv_bfloat16* const* Bv,
    int m0, int e0, int k0, int tid)
{
    #pragma unroll
    for (int v = 0; v < 4; v++) {
        const __nv_bfloat16* srcA = Av[v] + (size_t)m0 * DIMM + k0;
        uint32_t dstA = sA + v * 10240u;
        #pragma unroll
        for (int t = 0; t < 2; t++) {
            int idx = tid + t * 256;
            int r = idx >> 2, c = idx & 3;
            CP16(dstA + r * 80 + c * 16, srcA + (size_t)r * DIMM + c * 8);
        }
        const __nv_bfloat16* srcB = Bv[v] + (size_t)e0 * DIMM + k0;
        uint32_t dstB = sA + 40960u + v * 10240u;
        #pragma unroll
        for (int t = 0; t < 2; t++) {
            int idx = tid + t * 256;
            int r = idx >> 2, c = idx & 3;
            CP16(dstB + r * 80 + c * 16, srcB + (size_t)r * DIMM + c * 8);
        }
    }
}

__device__ __forceinline__ void gemm_compute(uint32_t ss, int lane, int wm, int wn,
    float accR[2][8][4], float accI[2][8][4])
{
    const uint32_t aRow = (uint32_t)(lane & 15);
    const uint32_t aSel = (uint32_t)(lane >> 4);
    const uint32_t nl   = (uint32_t)((lane & 7) + ((lane >> 4) << 3));
    const uint32_t ksel = (uint32_t)((lane >> 3) & 1);

    #pragma unroll
    for (int ks = 0; ks < 2; ks++) {
        uint32_t Af[4][2][4];
        #pragma unroll
        for (int v = 0; v < 4; v++)
            #pragma unroll
            for (int mf = 0; mf < 2; mf++) {
                uint32_t addr = ss + v * 10240u
                    + (wm * 32 + mf * 16 + aRow) * 80u + aSel * 16u + ks * 32u;
                ldm_x4(Af[v][mf], addr);
            }
        uint32_t nAih[2][4], nAil[2][4];
        #pragma unroll
        for (int mf = 0; mf < 2; mf++)
            #pragma unroll
            for (int q = 0; q < 4; q++) {
                nAih[mf][q] = Af[2][mf][q] ^ 0x80008000u;
                nAil[mf][q] = Af[3][mf][q] ^ 0x80008000u;
            }
        #pragma unroll
        for (int h = 0; h < 4; h++) {
            uint32_t Bf[4][4];
            #pragma unroll
            for (int v = 0; v < 4; v++) {
                uint32_t addr = ss + 40960u + v * 10240u
                    + (wn * 64 + h * 16 + nl) * 80u + ksel * 16u + ks * 32u;
                ldm_x4(Bf[v], addr);
            }
            #pragma unroll
            for (int mf = 0; mf < 2; mf++)
                #pragma unroll
                for (int sub = 0; sub < 2; sub++) {
                    const int nf = h * 2 + sub;
                    const uint32_t* Brh = &Bf[0][sub * 2];
                    const uint32_t* Brl = &Bf[1][sub * 2];
                    const uint32_t* Bih = &Bf[2][sub * 2];
                    const uint32_t* Bil = &Bf[3][sub * 2];
                    float* cr = accR[mf][nf];
                    float* ci = accI[mf][nf];
                    mma16816(cr, Af[0][mf], Brh);
                    mma16816(cr, Af[0][mf], Brl);
                    mma16816(cr, Af[1][mf], Brh);
                    mma16816(cr, nAih[mf],  Bih);
                    mma16816(cr, nAih[mf],  Bil);
                    mma16816(cr, nAil[mf],  Bih);
                    mma16816(ci, Af[0][mf], Bih);
                    mma16816(ci, Af[0][mf], Bil);
                    mma16816(ci, Af[1][mf], Bih);
                    mma16816(ci, Af[2][mf], Brh);
                    mma16816(ci, Af[2][mf], Brl);
                    mma16816(ci, Af[3][mf], Brh);
                }
        }
    }
}

// ---------------- qkv GEMM: smem-staged epilogue, [bh][d][n] writes ----------
__global__ void __launch_bounds__(256, 1) qkv_mma_kernel(
    const float* __restrict__ br, const float* __restrict__ bi,
    const float* __restrict__ fr, const float* __restrict__ fi)
{
    extern __shared__ char smrw[];
    const uint32_t sb = smem_u32(smrw);
    const int tid = threadIdx.x, lane = tid & 31, wid = tid >> 5;
    const int wm = wid >> 1, wn = wid & 1;
    const int e0 = blockIdx.x * 128, m0 = blockIdx.y * 128;

    const __nv_bfloat16* Av[4] = {g_Xr_h, g_Xr_l, g_Xi_h, g_Xi_l};
    const __nv_bfloat16* Bv[4] = {g_Wqr_h, g_Wqr_l, g_Wqi_h, g_Wqi_l};

    float accR[2][8][4] = {}, accI[2][8][4] = {};

    stage_load(sb, Av, Bv, m0, e0, 0, tid);
    CP_COMMIT();

    #pragma unroll 1
    for (int c = 0; c < NCHUNK; c++) {
        const int s = c & 1;
        if (c + 1 < NCHUNK) {
            stage_load(sb + (s ^ 1) * STG, Av, Bv, m0, e0, (c + 1) * 32, tid);
            CP_COMMIT();
            CP_WAIT(1);
        } else {
            CP_WAIT(0);
        }
        __syncthreads();
        gemm_compute(sb + s * STG, lane, wm, wn, accR, accI);
        __syncthreads();
    }

    // ---- stage accumulators to smem as [e 128][m pitch 132] fp32 ----
    float* smr = (float*)smrw;
    float* smi = smr + 128 * 132;
    #pragma unroll
    for (int mf = 0; mf < 2; mf++)
        #pragma unroll
        for (int nf = 0; nf < 8; nf++)
            #pragma unroll
            for (int rp = 0; rp < 2; rp++)
                #pragma unroll
                for (int cp = 0; cp < 2; cp++) {
                    const int el = wn * 64 + nf * 8 + (lane & 3) * 2 + cp;
                    const int ml = wm * 32 + mf * 16 + (lane >> 2) + rp * 8;
                    smr[el * 132 + ml] = accR[mf][nf][rp * 2 + cp];
                    smi[el * 132 + ml] = accI[mf][nf][rp * 2 + cp];
                }
    __syncthreads();

    // ---- each thread: one e-column half, packed uint2 n-run stores ----
    const int el = tid >> 1, half = tid & 1;
    const int e = e0 + el;
    const int h = e / 192, rem = e % 192;
    const int d = rem / 3, which = rem % 3;
    const float bre = br[e], bie = bi[e];
    const int b = m0 >> 10, n0 = (m0 & 1023) + half * 64;
    const int bh = b * HEADS + h;
    __nv_bfloat16 *dRh, *dRl, *dIh, *dIl;
    if (which == 0)      { dRh = g_Qrh; dRl = g_Qrl; dIh = g_Qih; dIl = g_Qil; }
    else if (which == 1) { dRh = g_Krh; dRl = g_Krl; dIh = g_Kih; dIl = g_Kil; }
    else                 { dRh = g_Vrh; dRl = g_Vrl; dIh = g_Vih; dIl = g_Vil; }
    const size_t dbase = (size_t)(bh * HD + d) * Nn + n0;
    const float* smr_e = smr + el * 132 + half * 64;
    const float* smi_e = smi + el * 132 + half * 64;

    #pragma unroll 1
    for (int mc = 0; mc < 16; mc++) {
        float4 srv = *(const float4*)(smr_e + mc * 4);
        float4 siv = *(const float4*)(smi_e + mc * 4);
        float vr[4] = {srv.x + bre, srv.y + bre, srv.z + bre, srv.w + bre};
        float vi[4] = {siv.x + bie, siv.y + bie, siv.z + bie, siv.w + bie};
        if (which < 2) {
            #pragma unroll
            for (int j = 0; j < 4; j++) {
                const int n = n0 + mc * 4 + j;
                const float frv = fr[n * HD + d], fiv = fi[n * HD + d];
                const float rr = vr[j] * frv - vi[j] * fiv;
                vi[j] = vr[j] * fiv + vi[j] * frv;
                vr[j] = rr;
            }
        }
        uint32_t h01, l01, h23, l23;
        split2(vr[0], vr[1], h01, l01);
        split2(vr[2], vr[3], h23, l23);
        *(uint2*)(dRh + dbase + mc * 4) = make_uint2(h01, h23);
        *(uint2*)(dRl + dbase + mc * 4) = make_uint2(l01, l23);
        split2(vi[0], vi[1], h01, l01);
        split2(vi[2], vi[3], h23, l23);
        *(uint2*)(dIh + dbase + mc * 4) = make_uint2(h01, h23);
        *(uint2*)(dIl + dbase + mc * 4) = make_uint2(l01, l23);
    }
}

// ---------------- output GEMM (float2-packed epilogue) -----------------------
__global__ void __launch_bounds__(256, 1) out_mma_kernel(
    const float* __restrict__ br, const float* __restrict__ bi,
    float* __restrict__ out)
{
    extern __shared__ char smrw[];
    const uint32_t sb = smem_u32(smrw);
    const int tid = threadIdx.x, lane = tid & 31, wid = tid >> 5;
    const int wm = wid >> 1, wn = wid & 1;
    const int e0 = blockIdx.x * 128, m0 = blockIdx.y * 128;

    const __nv_bfloat16* Av[4] = {g_Ar_h, g_Ar_l, g_Ai_h, g_Ai_l};
    const __nv_bfloat16* Bv[4] = {g_Wor_h, g_Wor_l, g_Woi_h, g_Woi_l};

    float accR[2][8][4] = {}, accI[2][8][4] = {};

    stage_load(sb, Av, Bv, m0, e0, 0, tid);
    CP_COMMIT();

    #pragma unroll 1
    for (int c = 0; c < NCHUNK; c++) {
        const int s = c & 1;
        if (c + 1 < NCHUNK) {
            stage_load(sb + (s ^ 1) * STG, Av, Bv, m0, e0, (c + 1) * 32, tid);
            CP_COMMIT();
            CP_WAIT(1);
        } else {
            CP_WAIT(0);
        }
        __syncthreads();
        gemm_compute(sb + s * STG, lane, wm, wn, accR, accI);
        __syncthreads();
    }

    #pragma unroll
    for (int mf = 0; mf < 2; mf++)
        #pragma unroll
        for (int nf = 0; nf < 8; nf++)
            #pragma unroll
            for (int rp = 0; rp < 2; rp++) {
                const int m = m0 + wm * 32 + mf * 16 + (lane >> 2) + rp * 8;
                const int e = e0 + wn * 64 + nf * 8 + (lane & 3) * 2;
                float2 vr = make_float2(accR[mf][nf][rp * 2] + br[e],
                                        accR[mf][nf][rp * 2 + 1] + br[e + 1]);
                float2 vi = make_float2(accI[mf][nf][rp * 2] + bi[e],
                                        accI[mf][nf][rp * 2 + 1] + bi[e + 1]);
                *(float2*)&out[(size_t)m * DIMM + e] = vr;
                *(float2*)&out[(size_t)Mtot * DIMM + (size_t)m * DIMM + e] = vi;
            }
}

// ---------------- flash attention: q-tile 64, 4 warps, 2 blocks/SM -----------
// smem: Q 4x(64d x pitch144) | K 4x(...) single | V 4x(...) single = 110592 B
#define APCH 144
#define AVQ  9216
#define AK_OFF (4 * AVQ)     // 36864
#define AV_OFF (8 * AVQ)     // 73728
#define ATTN_SMEM (12 * AVQ) // 110592

__device__ __forceinline__ void attn_ld_tile(uint32_t dst,
    const __nv_bfloat16* const* Pv, int k0, int tid)
{
    #pragma unroll
    for (int v = 0; v < 4; v++)
        #pragma unroll
        for (int t = 0; t < 4; t++) {
            int i = tid + t * 128;
            int r = i >> 3, c = i & 7;
            CP16(dst + v * AVQ + r * APCH + c * 16,
                 Pv[v] + (size_t)r * Nn + k0 + c * 8);
        }
}

__global__ void __launch_bounds__(128, 2) attn_mma_kernel()
{
    extern __shared__ char smrw[];
    const uint32_t sb = smem_u32(smrw);
    const int tid = threadIdx.x, lane = tid & 31, wid = tid >> 5;
    const int bh = blockIdx.y, q0 = blockIdx.x * 64;
    const size_t base = (size_t)bh * Nn * HD;

    const __nv_bfloat16* Qv[4] = {g_Qrh + base, g_Qrl + base, g_Qih + base, g_Qil + base};
    const __nv_bfloat16* Kv[4] = {g_Krh + base, g_Krl + base, g_Kih + base, g_Kil + base};
    const __nv_bfloat16* Vv[4] = {g_Vrh + base, g_Vrl + base, g_Vih + base, g_Vil + base};

    // group 1: Q + K(0);  group 2: V(0)
    attn_ld_tile(sb, Qv, q0, tid);
    attn_ld_tile(sb + AK_OFF, Kv, 0, tid);
    CP_COMMIT();
    attn_ld_tile(sb + AV_OFF, Vv, 0, tid);
    CP_COMMIT();

    float oR[8][4] = {}, oI[8][4] = {};
    float m0 = -1e30f, m1 = -1e30f, l0 = 0.f, l1 = 0.f;
    const int r0 = wid * 16;
    const uint32_t sK = sb + AK_OFF;
    const uint32_t sV = sb + AV_OFF;

    #pragma unroll 1
    for (int kt = 0; kt < 16; kt++) {
        CP_WAIT(1);              // K(kt) (+Q on kt=0) ready; V(kt) may pend
        __syncthreads();

        // ---- S = Q . conj(K) ----
        float sR[8][4] = {}, sI[8][4] = {};
        #pragma unroll
        for (int ks = 0; ks < 4; ks++) {
            uint32_t Qf[4][4];
            const uint32_t qa = sb
                + (ks * 16 + (lane & 7) + ((lane >> 4) & 1) * 8) * APCH
                + (r0 + ((lane >> 3) & 1) * 8) * 2;
            #pragma unroll
            for (int v = 0; v < 4; v++) ldm_x4_t(Qf[v], qa + v * AVQ);
            uint32_t nQrh[4], nQrl[4];
            #pragma unroll
            for (int q = 0; q < 4; q++) {
                nQrh[q] = Qf[0][q] ^ 0x80008000u;
                nQrl[q] = Qf[1][q] ^ 0x80008000u;
            }
            #pragma unroll
            for (int np = 0; np < 4; np++) {
                uint32_t Kf[4][4];
                const uint32_t ka = sK
                    + (ks * 16 + (lane & 7) + ((lane >> 3) & 1) * 8) * APCH
                    + (np * 16 + ((lane >> 4) & 1) * 8) * 2;
                #pragma unroll
                for (int v = 0; v < 4; v++) ldm_x4_t(Kf[v], ka + v * AVQ);
                #pragma unroll
                for (int sub = 0; sub < 2; sub++) {
                    const int nt = np * 2 + sub;
                    const uint32_t* Krh = &Kf[0][sub * 2];
                    const uint32_t* Krl = &Kf[1][sub * 2];
                    const uint32_t* Kih = &Kf[2][sub * 2];
                    const uint32_t* Kil = &Kf[3][sub * 2];
                    mma16816(sR[nt], Qf[0], Krh);
                    mma16816(sR[nt], Qf[0], Krl);
                    mma16816(sR[nt], Qf[1], Krh);
                    mma16816(sR[nt], Qf[2], Kih);
                    mma16816(sR[nt], Qf[2], Kil);
                    mma16816(sR[nt], Qf[3], Kih);
                    mma16816(sI[nt], Qf[2], Krh);
                    mma16816(sI[nt], Qf[2], Krl);
                    mma16816(sI[nt], Qf[3], Krh);
                    mma16816(sI[nt], nQrh,  Kih);
                    mma16816(sI[nt], nQrh,  Kil);
                    mma16816(sI[nt], nQrl,  Kih);
                }
            }
        }

        __syncthreads();         // all warps done reading K(kt)
        if (kt + 1 < 16) {
            attn_ld_tile(sK, Kv, (kt + 1) * 64, tid);
            CP_COMMIT();
        }

        // ---- online softmax on scaled |S| (per-warp, no barriers) ----
        float vm0 = -1e30f, vm1 = -1e30f;
        #pragma unroll
        for (int nt = 0; nt < 8; nt++)
            #pragma unroll
            for (int p = 0; p < 4; p++) {
                const float v = 0.125f * sqrtf(sR[nt][p] * sR[nt][p] + sI[nt][p] * sI[nt][p]);
                sR[nt][p] = v;
                if (p < 2) vm0 = fmaxf(vm0, v); else vm1 = fmaxf(vm1, v);
            }
        vm0 = fmaxf(vm0, __shfl_xor_sync(0xffffffffu, vm0, 1));
        vm0 = fmaxf(vm0, __shfl_xor_sync(0xffffffffu, vm0, 2));
        vm1 = fmaxf(vm1, __shfl_xor_sync(0xffffffffu, vm1, 1));
        vm1 = fmaxf(vm1, __shfl_xor_sync(0xffffffffu, vm1, 2));
        const float mn0 = fmaxf(m0, vm0), mn1 = fmaxf(m1, vm1);
        const float a0 = __expf(m0 - mn0), a1 = __expf(m1 - mn1);
        m0 = mn0; m1 = mn1;
        #pragma unroll
        for (int nt = 0; nt < 8; nt++)
            #pragma unroll
            for (int p = 0; p < 4; p++) {
                const float al = (p < 2) ? a0 : a1;
                oR[nt][p] *= al;
                oI[nt][p] *= al;
            }
        float s0 = 0.f, s1 = 0.f;
        #pragma unroll
        for (int nt = 0; nt < 8; nt++)
            #pragma unroll
            for (int p = 0; p < 4; p++) {
                const float pv = __expf(sR[nt][p] - ((p < 2) ? mn0 : mn1));
                sR[nt][p] = pv;
                if (p < 2) s0 += pv; else s1 += pv;
            }
        s0 += __shfl_xor_sync(0xffffffffu, s0, 1);
        s0 += __shfl_xor_sync(0xffffffffu, s0, 2);
        s1 += __shfl_xor_sync(0xffffffffu, s1, 1);
        s1 += __shfl_xor_sync(0xffffffffu, s1, 2);
        l0 = l0 * a0 + s0;
        l1 = l1 * a1 + s1;

        uint32_t Ph[4][4], Pl[4][4];
        #pragma unroll
        for (int j = 0; j < 4; j++) {
            const int t0 = 2 * j, t1 = 2 * j + 1;
            split2(sR[t0][0], sR[t0][1], Ph[j][0], Pl[j][0]);
            split2(sR[t0][2], sR[t0][3], Ph[j][1], Pl[j][1]);
            split2(sR[t1][0], sR[t1][1], Ph[j][2], Pl[j][2]);
            split2(sR[t1][2], sR[t1][3], Ph[j][3], Pl[j][3]);
        }

        // ---- wait V(kt); PV ----
        if (kt < 15) { CP_WAIT(1); } else { CP_WAIT(0); }
        __syncthreads();

        #pragma unroll
        for (int j = 0; j < 4; j++) {
            #pragma unroll
            for (int g = 0; g < 4; g++) {
                uint32_t Vf[4][4];
                const uint32_t va = sV
                    + (g * 16 + (lane & 7) + ((lane >> 4) & 1) * 8) * APCH
                    + j * 32 + ((lane >> 3) & 1) * 16;
                #pragma unroll
                for (int v = 0; v < 4; v++) ldm_x4(Vf[v], va + v * AVQ);
                #pragma unroll
                for (int sub = 0; sub < 2; sub++) {
                    const int nt = g * 2 + sub;
                    const uint32_t* Vrh = &Vf[0][sub * 2];
                    const uint32_t* Vrl = &Vf[1][sub * 2];
                    const uint32_t* Vih = &Vf[2][sub * 2];
                    const uint32_t* Vil = &Vf[3][sub * 2];
                    mma16816(oR[nt], Ph[j], Vrh);
                    mma16816(oR[nt], Pl[j], Vrh);
                    mma16816(oR[nt], Ph[j], Vrl);
                    mma16816(oI[nt], Ph[j], Vih);
                    mma16816(oI[nt], Pl[j], Vih);
                    mma16816(oI[nt], Ph[j], Vil);
                }
            }
        }

        __syncthreads();         // all warps done reading V(kt)
        if (kt + 1 < 16) {
            attn_ld_tile(sV, Vv, (kt + 1) * 64, tid);
            CP_COMMIT();
        }
    }

    // ---- normalize + packed pair writes to [b][n][h*64+d] ----
    const float inv0 = 1.0f / l0, inv1 = 1.0f / l1;
    const int b = bh / HEADS, h = bh % HEADS;
    #pragma unroll
    for (int nt = 0; nt < 8; nt++)
        #pragma unroll
        for (int rp = 0; rp < 2; rp++) {
            const int n = q0 + r0 + (lane >> 2) + rp * 8;
            const int d0 = nt * 8 + (lane & 3) * 2;
            const float inv = (rp == 0) ? inv0 : inv1;
            const size_t idx = ((size_t)(b * Nn + n)) * DIMM + h * HD + d0;
            uint32_t hh, ll;
            split2(oR[nt][rp * 2] * inv, oR[nt][rp * 2 + 1] * inv, hh, ll);
            *(uint32_t*)(g_Ar_h + idx) = hh;
            *(uint32_t*)(g_Ar_l + idx) = ll;
            split2(oI[nt][rp * 2] * inv, oI[nt][rp * 2 + 1] * inv, hh, ll);
            *(uint32_t*)(g_Ai_h + idx) = hh;
            *(uint32_t*)(g_Ai_l + idx) = ll;
        }
}

// ---------------- launch ------------------------------------------------------
extern "C" void kernel_launch(void* const* d_in, const int* in_sizes, int n_in,
                              void* d_out, int out_size)
{
    const float* xr  = (const float*)d_in[0];
    const float* xi  = (const float*)d_in[1];
    const float* fr  = (const float*)d_in[2];
    const float* fi  = (const float*)d_in[3];
    const float* wqr = (const float*)d_in[4];
    const float* wqi = (const float*)d_in[5];
    const float* bqr = (const float*)d_in[6];
    const float* bqi = (const float*)d_in[7];
    const float* wor = (const float*)d_in[8];
    const float* woi = (const float*)d_in[9];
    const float* bor = (const float*)d_in[10];
    const float* boi = (const float*)d_in[11];
    float* out = (float*)d_out;

    cudaFuncSetAttribute(qkv_mma_kernel,
                         cudaFuncAttributeMaxDynamicSharedMemorySize, GEMM_SMEM);
    cudaFuncSetAttribute(out_mma_kernel,
                         cudaFuncAttributeMaxDynamicSharedMemorySize, GEMM_SMEM);
    cudaFuncSetAttribute(attn_mma_kernel,
                         cudaFuncAttributeMaxDynamicSharedMemorySize, ATTN_SMEM);

    split_all_kernel<<<12288, 256>>>(xr, xi, wqr, wqi, wor, woi);
    qkv_mma_kernel<<<dim3(E3 / 128, Mtot / 128), 256, GEMM_SMEM>>>(bqr, bqi, fr, fi);
    attn_mma_kernel<<<dim3(Nn / 64, Bb * HEADS), 128, ATTN_SMEM>>>();
    out_mma_kernel<<<dim3(DIMM / 128, Mtot / 128), 256, GEMM_SMEM>>>(bor, boi, out);
}

// round 11
// speedup vs baseline: 1.2681x; 1.2507x over previous
#include <cuda_runtime.h>
#include <cuda_bf16.h>
#include <cuda_fp16.h>
#include <stdint.h>
#include <math.h>

#define Bb    2
#define Nn    1024
#define DIMM  1024
#define HEADS 16
#define HD    64
#define Mtot  (Bb * Nn)      // 2048
#define E3    (3 * DIMM)     // 3072

// ---------------- fp16 GEMM operand scratch ----------------------------------
__device__ __half g_Xr[Mtot * DIMM], g_Xi[Mtot * DIMM];           // A hi only
__device__ __half g_Wqr_h[E3 * DIMM],  g_Wqr_l[E3 * DIMM];
__device__ __half g_Wqi_h[E3 * DIMM],  g_Wqi_l[E3 * DIMM];
__device__ __half g_Wor_h[DIMM * DIMM], g_Wor_l[DIMM * DIMM];
__device__ __half g_Woi_h[DIMM * DIMM], g_Woi_l[DIMM * DIMM];
__device__ __half g_Ar[Mtot * DIMM], g_Ai[Mtot * DIMM];           // AO hi only

// Q/K/V bf16 hi/lo, layout [b*H + h][d][n]  (n innermost)
#define QKV_SZ (Bb * HEADS * Nn * HD)
__device__ __nv_bfloat16 g_Qrh[QKV_SZ], g_Qrl[QKV_SZ], g_Qih[QKV_SZ], g_Qil[QKV_SZ];
__device__ __nv_bfloat16 g_Krh[QKV_SZ], g_Krl[QKV_SZ], g_Kih[QKV_SZ], g_Kil[QKV_SZ];
__device__ __nv_bfloat16 g_Vrh[QKV_SZ], g_Vrl[QKV_SZ], g_Vih[QKV_SZ], g_Vil[QKV_SZ];

// ---------------- helpers ----------------------------------------------------
__device__ __forceinline__ uint32_t smem_u32(const void* p) {
    uint32_t a;
    asm("{ .reg .u64 t; cvta.to.shared.u64 t, %1; cvt.u32.u64 %0, t; }"
        : "=r"(a) : "l"(p));
    return a;
}

#define CP16(dst, src) \
    asm volatile("cp.async.cg.shared.global [%0], [%1], 16;" \
                 :: "r"((uint32_t)(dst)), "l"(src) : "memory")
#define CP_COMMIT() asm volatile("cp.async.commit_group;" ::: "memory")
#define CP_WAIT(n)  asm volatile("cp.async.wait_group %0;" :: "n"(n) : "memory")

__device__ __forceinline__ void ldm_x4(uint32_t* r, uint32_t addr) {
    asm volatile("ldmatrix.sync.aligned.m8n8.x4.shared.b16 {%0,%1,%2,%3}, [%4];"
        : "=r"(r[0]), "=r"(r[1]), "=r"(r[2]), "=r"(r[3]) : "r"(addr));
}

__device__ __forceinline__ void ldm_x4_t(uint32_t* r, uint32_t addr) {
    asm volatile("ldmatrix.sync.aligned.m8n8.x4.trans.shared.b16 {%0,%1,%2,%3}, [%4];"
        : "=r"(r[0]), "=r"(r[1]), "=r"(r[2]), "=r"(r[3]) : "r"(addr));
}

// bf16 mma (attention)
__device__ __forceinline__ void mma16816(float* c, const uint32_t* a, const uint32_t* b) {
    asm volatile("mma.sync.aligned.m16n8k16.row.col.f32.bf16.bf16.f32 "
        "{%0,%1,%2,%3}, {%4,%5,%6,%7}, {%8,%9}, {%0,%1,%2,%3};"
        : "+f"(c[0]), "+f"(c[1]), "+f"(c[2]), "+f"(c[3])
        : "r"(a[0]), "r"(a[1]), "r"(a[2]), "r"(a[3]), "r"(b[0]), "r"(b[1]));
}

// fp16 mma (GEMMs)
__device__ __forceinline__ void mma16816h(float* c, const uint32_t* a, const uint32_t* b) {
    asm volatile("mma.sync.aligned.m16n8k16.row.col.f32.f16.f16.f32 "
        "{%0,%1,%2,%3}, {%4,%5,%6,%7}, {%8,%9}, {%0,%1,%2,%3};"
        : "+f"(c[0]), "+f"(c[1]), "+f"(c[2]), "+f"(c[3])
        : "r"(a[0]), "r"(a[1]), "r"(a[2]), "r"(a[3]), "r"(b[0]), "r"(b[1]));
}

__device__ __forceinline__ void split2(float a, float b, uint32_t& hi, uint32_t& lo) {
    __nv_bfloat16 ah = __float2bfloat16(a), bh = __float2bfloat16(b);
    float ar = a - __bfloat162float(ah), br = b - __bfloat162float(bh);
    __nv_bfloat162 h; h.x = ah; h.y = bh;
    __nv_bfloat162 l; l.x = __float2bfloat16(ar); l.y = __float2bfloat16(br);
    hi = *(uint32_t*)&h;
    lo = *(uint32_t*)&l;
}

__device__ __forceinline__ void split2h(float a, float b, uint32_t& hi, uint32_t& lo) {
    __half ah = __float2half_rn(a), bh = __float2half_rn(b);
    float ar = a - __half2float(ah), br = b - __half2float(bh);
    __half2 h = __halves2half2(ah, bh);
    __half2 l = __halves2half2(__float2half_rn(ar), __float2half_rn(br));
    hi = *(uint32_t*)&h;
    lo = *(uint32_t*)&l;
}

__device__ __forceinline__ uint32_t pack2h(float a, float b) {
    __half2 h = __halves2half2(__float2half_rn(a), __float2half_rn(b));
    return *(uint32_t*)&h;
}

// ---------------- combined input split kernel --------------------------------
// X -> fp16 single; Wq, Wo -> fp16 hi/lo.
__global__ void __launch_bounds__(256) split_all_kernel(
    const float* __restrict__ xr,  const float* __restrict__ xi,
    const float* __restrict__ wqr, const float* __restrict__ wqi,
    const float* __restrict__ wor, const float* __restrict__ woi)
{
    const int blk = blockIdx.x;
    const float* src; __half *hi, *lo = nullptr; int off;
    if      (blk <  2048) { src = xr;  hi = g_Xr; off = blk; }
    else if (blk <  4096) { src = xi;  hi = g_Xi; off = blk - 2048; }
    else if (blk <  7168) { src = wqr; hi = g_Wqr_h; lo = g_Wqr_l; off = blk - 4096; }
    else if (blk < 10240) { src = wqi; hi = g_Wqi_h; lo = g_Wqi_l; off = blk - 7168; }
    else if (blk < 11264) { src = wor; hi = g_Wor_h; lo = g_Wor_l; off = blk - 10240; }
    else                  { src = woi; hi = g_Woi_h; lo = g_Woi_l; off = blk - 11264; }
    const int i = (off * 256 + threadIdx.x) * 4;
    float4 x = *(const float4*)(src + i);
    if (lo) {
        uint32_t h01, l01, h23, l23;
        split2h(x.x, x.y, h01, l01);
        split2h(x.z, x.w, h23, l23);
        *(uint2*)(hi + i) = make_uint2(h01, h23);
        *(uint2*)(lo + i) = make_uint2(l01, l23);
    } else {
        *(uint2*)(hi + i) = make_uint2(pack2h(x.x, x.y), pack2h(x.z, x.w));
    }
}

// ---------------- fp16 2-term complex GEMM core ------------------------------
// Block 128x128, 256 threads, 8 warps as 4(m) x 2(n), warp tile 32x64.
// A hi-only (2 arrays), B hi/lo (4 arrays). 8 MMAs per complex frag product.
// Stage: Ar @0, Ai @10240, B[4] @20480+v*10240. Pitch 80 B. Stage 61440 B.
#define STG 61440
#define GEMM_SMEM 135168   // max(2*STG, qkv epilogue staging 128*132*4*2)
#define NCHUNK (DIMM / 32)

__device__ __forceinline__ void stage_load(uint32_t sA,
    const __half* const* Av, const __half* const* Bv,
    int m0, int e0, int k0, int tid)
{
    #pragma unroll
    for (int v = 0; v < 2; v++) {
        const __half* srcA = Av[v] + (size_t)m0 * DIMM + k0;
        uint32_t dstA = sA + v * 10240u;
        #pragma unroll
        for (int t = 0; t < 2; t++) {
            int idx = tid + t * 256;
            int r = idx >> 2, c = idx & 3;
            CP16(dstA + r * 80 + c * 16, srcA + (size_t)r * DIMM + c * 8);
        }
    }
    #pragma unroll
    for (int v = 0; v < 4; v++) {
        const __half* srcB = Bv[v] + (size_t)e0 * DIMM + k0;
        uint32_t dstB = sA + 20480u + v * 10240u;
        #pragma unroll
        for (int t = 0; t < 2; t++) {
            int idx = tid + t * 256;
            int r = idx >> 2, c = idx & 3;
            CP16(dstB + r * 80 + c * 16, srcB + (size_t)r * DIMM + c * 8);
        }
    }
}

__device__ __forceinline__ void gemm_compute(uint32_t ss, int lane, int wm, int wn,
    float accR[2][8][4], float accI[2][8][4])
{
    const uint32_t aRow = (uint32_t)(lane & 15);
    const uint32_t aSel = (uint32_t)(lane >> 4);
    const uint32_t nl   = (uint32_t)((lane & 7) + ((lane >> 4) << 3));
    const uint32_t ksel = (uint32_t)((lane >> 3) & 1);

    #pragma unroll
    for (int ks = 0; ks < 2; ks++) {
        uint32_t Ar[2][4], Ai[2][4], nAi[2][4];
        #pragma unroll
        for (int mf = 0; mf < 2; mf++) {
            uint32_t addr = ss + (wm * 32 + mf * 16 + aRow) * 80u
                            + aSel * 16u + ks * 32u;
            ldm_x4(Ar[mf], addr);
            ldm_x4(Ai[mf], addr + 10240u);
            #pragma unroll
            for (int q = 0; q < 4; q++) nAi[mf][q] = Ai[mf][q] ^ 0x80008000u;
        }
        #pragma unroll
        for (int h = 0; h < 4; h++) {
            uint32_t Bf[4][4];   // Brh, Brl, Bih, Bil
            const uint32_t ba = ss + 20480u
                + (wn * 64 + h * 16 + nl) * 80u + ksel * 16u + ks * 32u;
            #pragma unroll
            for (int v = 0; v < 4; v++) ldm_x4(Bf[v], ba + v * 10240u);
            #pragma unroll
            for (int mf = 0; mf < 2; mf++)
                #pragma unroll
                for (int sub = 0; sub < 2; sub++) {
                    const int nf = h * 2 + sub;
                    const uint32_t* Brh = &Bf[0][sub * 2];
                    const uint32_t* Brl = &Bf[1][sub * 2];
                    const uint32_t* Bih = &Bf[2][sub * 2];
                    const uint32_t* Bil = &Bf[3][sub * 2];
                    float* cr = accR[mf][nf];
                    float* ci = accI[mf][nf];
                    // real = Ar*Br - Ai*Bi   (2-term: Ah*Bh + Ah*Bl)
                    mma16816h(cr, Ar[mf],  Brh);
                    mma16816h(cr, Ar[mf],  Brl);
                    mma16816h(cr, nAi[mf], Bih);
                    mma16816h(cr, nAi[mf], Bil);
                    // imag = Ar*Bi + Ai*Br
                    mma16816h(ci, Ar[mf],  Bih);
                    mma16816h(ci, Ar[mf],  Bil);
                    mma16816h(ci, Ai[mf],  Brh);
                    mma16816h(ci, Ai[mf],  Brl);
                }
        }
    }
}

// ---------------- qkv GEMM: smem-staged epilogue, [bh][d][n] writes ----------
__global__ void __launch_bounds__(256, 1) qkv_mma_kernel(
    const float* __restrict__ br, const float* __restrict__ bi,
    const float* __restrict__ fr, const float* __restrict__ fi)
{
    extern __shared__ char smrw[];
    const uint32_t sb = smem_u32(smrw);
    const int tid = threadIdx.x, lane = tid & 31, wid = tid >> 5;
    const int wm = wid >> 1, wn = wid & 1;
    const int e0 = blockIdx.x * 128, m0 = blockIdx.y * 128;

    const __half* Av[2] = {g_Xr, g_Xi};
    const __half* Bv[4] = {g_Wqr_h, g_Wqr_l, g_Wqi_h, g_Wqi_l};

    float accR[2][8][4] = {}, accI[2][8][4] = {};

    stage_load(sb, Av, Bv, m0, e0, 0, tid);
    CP_COMMIT();

    #pragma unroll 1
    for (int c = 0; c < NCHUNK; c++) {
        const int s = c & 1;
        if (c + 1 < NCHUNK) {
            stage_load(sb + (s ^ 1) * STG, Av, Bv, m0, e0, (c + 1) * 32, tid);
            CP_COMMIT();
            CP_WAIT(1);
        } else {
            CP_WAIT(0);
        }
        __syncthreads();
        gemm_compute(sb + s * STG, lane, wm, wn, accR, accI);
        __syncthreads();
    }

    // ---- stage accumulators to smem as [e 128][m pitch 132] fp32 ----
    float* smr = (float*)smrw;
    float* smi = smr + 128 * 132;
    #pragma unroll
    for (int mf = 0; mf < 2; mf++)
        #pragma unroll
        for (int nf = 0; nf < 8; nf++)
            #pragma unroll
            for (int rp = 0; rp < 2; rp++)
                #pragma unroll
                for (int cp = 0; cp < 2; cp++) {
                    const int el = wn * 64 + nf * 8 + (lane & 3) * 2 + cp;
                    const int ml = wm * 32 + mf * 16 + (lane >> 2) + rp * 8;
                    smr[el * 132 + ml] = accR[mf][nf][rp * 2 + cp];
                    smi[el * 132 + ml] = accI[mf][nf][rp * 2 + cp];
                }
    __syncthreads();

    // ---- each thread: one e-column half, packed uint2 n-run stores ----
    const int el = tid >> 1, half = tid & 1;
    const int e = e0 + el;
    const int h = e / 192, rem = e % 192;
    const int d = rem / 3, which = rem % 3;
    const float bre = br[e], bie = bi[e];
    const int b = m0 >> 10, n0 = (m0 & 1023) + half * 64;
    const int bh = b * HEADS + h;
    __nv_bfloat16 *dRh, *dRl, *dIh, *dIl;
    if (which == 0)      { dRh = g_Qrh; dRl = g_Qrl; dIh = g_Qih; dIl = g_Qil; }
    else if (which == 1) { dRh = g_Krh; dRl = g_Krl; dIh = g_Kih; dIl = g_Kil; }
    else                 { dRh = g_Vrh; dRl = g_Vrl; dIh = g_Vih; dIl = g_Vil; }
    const size_t dbase = (size_t)(bh * HD + d) * Nn + n0;
    const float* smr_e = smr + el * 132 + half * 64;
    const float* smi_e = smi + el * 132 + half * 64;

    #pragma unroll 1
    for (int mc = 0; mc < 16; mc++) {
        float4 srv = *(const float4*)(smr_e + mc * 4);
        float4 siv = *(const float4*)(smi_e + mc * 4);
        float vr[4] = {srv.x + bre, srv.y + bre, srv.z + bre, srv.w + bre};
        float vi[4] = {siv.x + bie, siv.y + bie, siv.z + bie, siv.w + bie};
        if (which < 2) {
            #pragma unroll
            for (int j = 0; j < 4; j++) {
                const int n = n0 + mc * 4 + j;
                const float frv = fr[n * HD + d], fiv = fi[n * HD + d];
                const float rr = vr[j] * frv - vi[j] * fiv;
                vi[j] = vr[j] * fiv + vi[j] * frv;
                vr[j] = rr;
            }
        }
        uint32_t h01, l01, h23, l23;
        split2(vr[0], vr[1], h01, l01);
        split2(vr[2], vr[3], h23, l23);
        *(uint2*)(dRh + dbase + mc * 4) = make_uint2(h01, h23);
        *(uint2*)(dRl + dbase + mc * 4) = make_uint2(l01, l23);
        split2(vi[0], vi[1], h01, l01);
        split2(vi[2], vi[3], h23, l23);
        *(uint2*)(dIh + dbase + mc * 4) = make_uint2(h01, h23);
        *(uint2*)(dIl + dbase + mc * 4) = make_uint2(l01, l23);
    }
}

// ---------------- output GEMM (float2-packed epilogue) -----------------------
__global__ void __launch_bounds__(256, 1) out_mma_kernel(
    const float* __restrict__ br, const float* __restrict__ bi,
    float* __restrict__ out)
{
    extern __shared__ char smrw[];
    const uint32_t sb = smem_u32(smrw);
    const int tid = threadIdx.x, lane = tid & 31, wid = tid >> 5;
    const int wm = wid >> 1, wn = wid & 1;
    const int e0 = blockIdx.x * 128, m0 = blockIdx.y * 128;

    const __half* Av[2] = {g_Ar, g_Ai};
    const __half* Bv[4] = {g_Wor_h, g_Wor_l, g_Woi_h, g_Woi_l};

    float accR[2][8][4] = {}, accI[2][8][4] = {};

    stage_load(sb, Av, Bv, m0, e0, 0, tid);
    CP_COMMIT();

    #pragma unroll 1
    for (int c = 0; c < NCHUNK; c++) {
        const int s = c & 1;
        if (c + 1 < NCHUNK) {
            stage_load(sb + (s ^ 1) * STG, Av, Bv, m0, e0, (c + 1) * 32, tid);
            CP_COMMIT();
            CP_WAIT(1);
        } else {
            CP_WAIT(0);
        }
        __syncthreads();
        gemm_compute(sb + s * STG, lane, wm, wn, accR, accI);
        __syncthreads();
    }

    #pragma unroll
    for (int mf = 0; mf < 2; mf++)
        #pragma unroll
        for (int nf = 0; nf < 8; nf++)
            #pragma unroll
            for (int rp = 0; rp < 2; rp++) {
                const int m = m0 + wm * 32 + mf * 16 + (lane >> 2) + rp * 8;
                const int e = e0 + wn * 64 + nf * 8 + (lane & 3) * 2;
                float2 vr = make_float2(accR[mf][nf][rp * 2] + br[e],
                                        accR[mf][nf][rp * 2 + 1] + br[e + 1]);
                float2 vi = make_float2(accI[mf][nf][rp * 2] + bi[e],
                                        accI[mf][nf][rp * 2 + 1] + bi[e + 1]);
                *(float2*)&out[(size_t)m * DIMM + e] = vr;
                *(float2*)&out[(size_t)Mtot * DIMM + (size_t)m * DIMM + e] = vi;
            }
}

// ---------------- tensor-core flash attention (R8 config, bf16) --------------
#define PCHQ 272
#define VQ   17408
#define PCHK 144
#define VKV  9216
#define SK_OFF (4 * VQ)
#define STG_KV (4 * VKV)
#define SV_OFF (SK_OFF + 2 * STG_KV)
#define ATTN_SMEM (SV_OFF + 2 * STG_KV)

__device__ __forceinline__ void load_kv(uint32_t sb,
    const __nv_bfloat16* const* Kv, const __nv_bfloat16* const* Vv,
    int k0, int s, int tid)
{
    #pragma unroll
    for (int v = 0; v < 4; v++)
        #pragma unroll
        for (int t = 0; t < 2; t++) {
            int i = tid + t * 256;
            int r = i >> 3, c = i & 7;
            CP16(sb + SK_OFF + s * STG_KV + v * VKV + r * PCHK + c * 16,
                 Kv[v] + (size_t)r * Nn + k0 + c * 8);
            CP16(sb + SV_OFF + s * STG_KV + v * VKV + r * PCHK + c * 16,
                 Vv[v] + (size_t)r * Nn + k0 + c * 8);
        }
}

__global__ void __launch_bounds__(256, 1) attn_mma_kernel()
{
    extern __shared__ char smrw[];
    const uint32_t sb = smem_u32(smrw);
    const int tid = threadIdx.x, lane = tid & 31, wid = tid >> 5;
    const int bh = blockIdx.y, q0 = blockIdx.x * 128;
    const size_t base = (size_t)bh * Nn * HD;

    const __nv_bfloat16* Qv[4] = {g_Qrh + base, g_Qrl + base, g_Qih + base, g_Qil + base};
    const __nv_bfloat16* Kv[4] = {g_Krh + base, g_Krl + base, g_Kih + base, g_Kil + base};
    const __nv_bfloat16* Vv[4] = {g_Vrh + base, g_Vrl + base, g_Vih + base, g_Vil + base};

    #pragma unroll
    for (int v = 0; v < 4; v++)
        #pragma unroll
        for (int t = 0; t < 4; t++) {
            int i = tid + t * 256;
            int r = i >> 4, c = i & 15;
            CP16(sb + v * VQ + r * PCHQ + c * 16, Qv[v] + (size_t)r * Nn + q0 + c * 8);
        }
    load_kv(sb, Kv, Vv, 0, 0, tid);
    CP_COMMIT();

    float oR[8][4] = {}, oI[8][4] = {};
    float m0 = -1e30f, m1 = -1e30f, l0 = 0.f, l1 = 0.f;
    const int r0 = wid * 16;

    #pragma unroll 1
    for (int kt = 0; kt < 16; kt++) {
        const int s = kt & 1;
        if (kt + 1 < 16) {
            load_kv(sb, Kv, Vv, (kt + 1) * 64, s ^ 1, tid);
            CP_COMMIT();
            CP_WAIT(1);
        } else {
            CP_WAIT(0);
        }
        __syncthreads();

        const uint32_t sK = sb + SK_OFF + s * STG_KV;
        const uint32_t sV = sb + SV_OFF + s * STG_KV;

        float sR[8][4] = {}, sI[8][4] = {};
        #pragma unroll
        for (int ks = 0; ks < 4; ks++) {
            uint32_t Qf[4][4];
            const uint32_t qa = sb
                + (ks * 16 + (lane & 7) + ((lane >> 4) & 1) * 8) * PCHQ
                + (r0 + ((lane >> 3) & 1) * 8) * 2;
            #pragma unroll
            for (int v = 0; v < 4; v++) ldm_x4_t(Qf[v], qa + v * VQ);
            uint32_t nQrh[4], nQrl[4];
            #pragma unroll
            for (int q = 0; q < 4; q++) {
                nQrh[q] = Qf[0][q] ^ 0x80008000u;
                nQrl[q] = Qf[1][q] ^ 0x80008000u;
            }
            #pragma unroll
            for (int np = 0; np < 4; np++) {
                uint32_t Kf[4][4];
                const uint32_t ka = sK
                    + (ks * 16 + (lane & 7) + ((lane >> 3) & 1) * 8) * PCHK
                    + (np * 16 + ((lane >> 4) & 1) * 8) * 2;
                #pragma unroll
                for (int v = 0; v < 4; v++) ldm_x4_t(Kf[v], ka + v * VKV);
                #pragma unroll
                for (int sub = 0; sub < 2; sub++) {
                    const int nt = np * 2 + sub;
                    const uint32_t* Krh = &Kf[0][sub * 2];
                    const uint32_t* Krl = &Kf[1][sub * 2];
                    const uint32_t* Kih = &Kf[2][sub * 2];
                    const uint32_t* Kil = &Kf[3][sub * 2];
                    mma16816(sR[nt], Qf[0], Krh);
                    mma16816(sR[nt], Qf[0], Krl);
                    mma16816(sR[nt], Qf[1], Krh);
                    mma16816(sR[nt], Qf[2], Kih);
                    mma16816(sR[nt], Qf[2], Kil);
                    mma16816(sR[nt], Qf[3], Kih);
                    mma16816(sI[nt], Qf[2], Krh);
                    mma16816(sI[nt], Qf[2], Krl);
                    mma16816(sI[nt], Qf[3], Krh);
                    mma16816(sI[nt], nQrh,  Kih);
                    mma16816(sI[nt], nQrh,  Kil);
                    mma16816(sI[nt], nQrl,  Kih);
                }
            }
        }

        float vm0 = -1e30f, vm1 = -1e30f;
        #pragma unroll
        for (int nt = 0; nt < 8; nt++)
            #pragma unroll
            for (int p = 0; p < 4; p++) {
                const float v = 0.125f * sqrtf(sR[nt][p] * sR[nt][p] + sI[nt][p] * sI[nt][p]);
                sR[nt][p] = v;
                if (p < 2) vm0 = fmaxf(vm0, v); else vm1 = fmaxf(vm1, v);
            }
        vm0 = fmaxf(vm0, __shfl_xor_sync(0xffffffffu, vm0, 1));
        vm0 = fmaxf(vm0, __shfl_xor_sync(0xffffffffu, vm0, 2));
        vm1 = fmaxf(vm1, __shfl_xor_sync(0xffffffffu, vm1, 1));
        vm1 = fmaxf(vm1, __shfl_xor_sync(0xffffffffu, vm1, 2));
        const float mn0 = fmaxf(m0, vm0), mn1 = fmaxf(m1, vm1);
        const float a0 = __expf(m0 - mn0), a1 = __expf(m1 - mn1);
        m0 = mn0; m1 = mn1;
        #pragma unroll
        for (int nt = 0; nt < 8; nt++)
            #pragma unroll
            for (int p = 0; p < 4; p++) {
                const float al = (p < 2) ? a0 : a1;
                oR[nt][p] *= al;
                oI[nt][p] *= al;
            }
        float s0 = 0.f, s1 = 0.f;
        #pragma unroll
        for (int nt = 0; nt < 8; nt++)
            #pragma unroll
            for (int p = 0; p < 4; p++) {
                const float pv = __expf(sR[nt][p] - ((p < 2) ? mn0 : mn1));
                sR[nt][p] = pv;
                if (p < 2) s0 += pv; else s1 += pv;
            }
        s0 += __shfl_xor_sync(0xffffffffu, s0, 1);
        s0 += __shfl_xor_sync(0xffffffffu, s0, 2);
        s1 += __shfl_xor_sync(0xffffffffu, s1, 1);
        s1 += __shfl_xor_sync(0xffffffffu, s1, 2);
        l0 = l0 * a0 + s0;
        l1 = l1 * a1 + s1;

        uint32_t Ph[4][4], Pl[4][4];
        #pragma unroll
        for (int j = 0; j < 4; j++) {
            const int t0 = 2 * j, t1 = 2 * j + 1;
            split2(sR[t0][0], sR[t0][1], Ph[j][0], Pl[j][0]);
            split2(sR[t0][2], sR[t0][3], Ph[j][1], Pl[j][1]);
            split2(sR[t1][0], sR[t1][1], Ph[j][2], Pl[j][2]);
            split2(sR[t1][2], sR[t1][3], Ph[j][3], Pl[j][3]);
        }

        #pragma unroll
        for (int j = 0; j < 4; j++) {
            #pragma unroll
            for (int g = 0; g < 4; g++) {
                uint32_t Vf[4][4];
                const uint32_t va = sV
                    + (g * 16 + (lane & 7) + ((lane >> 4) & 1) * 8) * PCHK
                    + j * 32 + ((lane >> 3) & 1) * 16;
                #pragma unroll
                for (int v = 0; v < 4; v++) ldm_x4(Vf[v], va + v * VKV);
                #pragma unroll
                for (int sub = 0; sub < 2; sub++) {
                    const int nt = g * 2 + sub;
                    const uint32_t* Vrh = &Vf[0][sub * 2];
                    const uint32_t* Vrl = &Vf[1][sub * 2];
                    const uint32_t* Vih = &Vf[2][sub * 2];
                    const uint32_t* Vil = &Vf[3][sub * 2];
                    mma16816(oR[nt], Ph[j], Vrh);
                    mma16816(oR[nt], Pl[j], Vrh);
                    mma16816(oR[nt], Ph[j], Vrl);
                    mma16816(oI[nt], Ph[j], Vih);
                    mma16816(oI[nt], Pl[j], Vih);
                    mma16816(oI[nt], Ph[j], Vil);
                }
            }
        }
        __syncthreads();
    }

    // ---- normalize + packed fp16 AO writes to [b][n][h*64+d] ----
    const float inv0 = 1.0f / l0, inv1 = 1.0f / l1;
    const int b = bh / HEADS, h = bh % HEADS;
    #pragma unroll
    for (int nt = 0; nt < 8; nt++)
        #pragma unroll
        for (int rp = 0; rp < 2; rp++) {
            const int n = q0 + r0 + (lane >> 2) + rp * 8;
            const int d0 = nt * 8 + (lane & 3) * 2;
            const float inv = (rp == 0) ? inv0 : inv1;
            const size_t idx = ((size_t)(b * Nn + n)) * DIMM + h * HD + d0;
            *(uint32_t*)(g_Ar + idx) =
                pack2h(oR[nt][rp * 2] * inv, oR[nt][rp * 2 + 1] * inv);
            *(uint32_t*)(g_Ai + idx) =
                pack2h(oI[nt][rp * 2] * inv, oI[nt][rp * 2 + 1] * inv);
        }
}

// ---------------- launch ------------------------------------------------------
extern "C" void kernel_launch(void* const* d_in, const int* in_sizes, int n_in,
                              void* d_out, int out_size)
{
    const float* xr  = (const float*)d_in[0];
    const float* xi  = (const float*)d_in[1];
    const float* fr  = (const float*)d_in[2];
    const float* fi  = (const float*)d_in[3];
    const float* wqr = (const float*)d_in[4];
    const float* wqi = (const float*)d_in[5];
    const float* bqr = (const float*)d_in[6];
    const float* bqi = (const float*)d_in[7];
    const float* wor = (const float*)d_in[8];
    const float* woi = (const float*)d_in[9];
    const float* bor = (const float*)d_in[10];
    const float* boi = (const float*)d_in[11];
    float* out = (float*)d_out;

    cudaFuncSetAttribute(qkv_mma_kernel,
                         cudaFuncAttributeMaxDynamicSharedMemorySize, GEMM_SMEM);
    cudaFuncSetAttribute(out_mma_kernel,
                         cudaFuncAttributeMaxDynamicSharedMemorySize, GEMM_SMEM);
    cudaFuncSetAttribute(attn_mma_kernel,
                         cudaFuncAttributeMaxDynamicSharedMemorySize, ATTN_SMEM);

    split_all_kernel<<<12288, 256>>>(xr, xi, wqr, wqi, wor, woi);
    qkv_mma_kernel<<<dim3(E3 / 128, Mtot / 128), 256, GEMM_SMEM>>>(bqr, bqi, fr, fi);
    attn_mma_kernel<<<dim3(Nn / 128, Bb * HEADS), 256, ATTN_SMEM>>>();
    out_mma_kernel<<<dim3(DIMM / 128, Mtot / 128), 256, GEMM_SMEM>>>(bor, boi, out);
}

// round 12
// speedup vs baseline: 1.2882x; 1.0159x over previous
#include <cuda_runtime.h>
#include <cuda_bf16.h>
#include <cuda_fp16.h>
#include <stdint.h>
#include <math.h>

#define Bb    2
#define Nn    1024
#define DIMM  1024
#define HEADS 16
#define HD    64
#define Mtot  (Bb * Nn)      // 2048
#define E3    (3 * DIMM)     // 3072

// ---------------- fp16 GEMM operand scratch ----------------------------------
__device__ __half g_Xr[Mtot * DIMM], g_Xi[Mtot * DIMM];           // A hi only
__device__ __half g_Wqr_h[E3 * DIMM],  g_Wqr_l[E3 * DIMM];
__device__ __half g_Wqi_h[E3 * DIMM],  g_Wqi_l[E3 * DIMM];
__device__ __half g_Wor_h[DIMM * DIMM], g_Wor_l[DIMM * DIMM];
__device__ __half g_Woi_h[DIMM * DIMM], g_Woi_l[DIMM * DIMM];
__device__ __half g_Ar[Mtot * DIMM], g_Ai[Mtot * DIMM];           // AO hi only

// Q/K/V bf16 hi/lo, layout [b*H + h][d][n]  (n innermost)
#define QKV_SZ (Bb * HEADS * Nn * HD)
__device__ __nv_bfloat16 g_Qrh[QKV_SZ], g_Qrl[QKV_SZ], g_Qih[QKV_SZ], g_Qil[QKV_SZ];
__device__ __nv_bfloat16 g_Krh[QKV_SZ], g_Krl[QKV_SZ], g_Kih[QKV_SZ], g_Kil[QKV_SZ];
__device__ __nv_bfloat16 g_Vrh[QKV_SZ], g_Vrl[QKV_SZ], g_Vih[QKV_SZ], g_Vil[QKV_SZ];

// ---------------- helpers ----------------------------------------------------
__device__ __forceinline__ uint32_t smem_u32(const void* p) {
    uint32_t a;
    asm("{ .reg .u64 t; cvta.to.shared.u64 t, %1; cvt.u32.u64 %0, t; }"
        : "=r"(a) : "l"(p));
    return a;
}

#define CP16(dst, src) \
    asm volatile("cp.async.cg.shared.global [%0], [%1], 16;" \
                 :: "r"((uint32_t)(dst)), "l"(src) : "memory")
#define CP_COMMIT() asm volatile("cp.async.commit_group;" ::: "memory")
#define CP_WAIT(n)  asm volatile("cp.async.wait_group %0;" :: "n"(n) : "memory")

__device__ __forceinline__ void ldm_x4(uint32_t* r, uint32_t addr) {
    asm volatile("ldmatrix.sync.aligned.m8n8.x4.shared.b16 {%0,%1,%2,%3}, [%4];"
        : "=r"(r[0]), "=r"(r[1]), "=r"(r[2]), "=r"(r[3]) : "r"(addr));
}

__device__ __forceinline__ void ldm_x4_t(uint32_t* r, uint32_t addr) {
    asm volatile("ldmatrix.sync.aligned.m8n8.x4.trans.shared.b16 {%0,%1,%2,%3}, [%4];"
        : "=r"(r[0]), "=r"(r[1]), "=r"(r[2]), "=r"(r[3]) : "r"(addr));
}

// bf16 mma (attention)
__device__ __forceinline__ void mma16816(float* c, const uint32_t* a, const uint32_t* b) {
    asm volatile("mma.sync.aligned.m16n8k16.row.col.f32.bf16.bf16.f32 "
        "{%0,%1,%2,%3}, {%4,%5,%6,%7}, {%8,%9}, {%0,%1,%2,%3};"
        : "+f"(c[0]), "+f"(c[1]), "+f"(c[2]), "+f"(c[3])
        : "r"(a[0]), "r"(a[1]), "r"(a[2]), "r"(a[3]), "r"(b[0]), "r"(b[1]));
}

// fp16 mma (GEMMs)
__device__ __forceinline__ void mma16816h(float* c, const uint32_t* a, const uint32_t* b) {
    asm volatile("mma.sync.aligned.m16n8k16.row.col.f32.f16.f16.f32 "
        "{%0,%1,%2,%3}, {%4,%5,%6,%7}, {%8,%9}, {%0,%1,%2,%3};"
        : "+f"(c[0]), "+f"(c[1]), "+f"(c[2]), "+f"(c[3])
        : "r"(a[0]), "r"(a[1]), "r"(a[2]), "r"(a[3]), "r"(b[0]), "r"(b[1]));
}

__device__ __forceinline__ void split2(float a, float b, uint32_t& hi, uint32_t& lo) {
    __nv_bfloat16 ah = __float2bfloat16(a), bh = __float2bfloat16(b);
    float ar = a - __bfloat162float(ah), br = b - __bfloat162float(bh);
    __nv_bfloat162 h; h.x = ah; h.y = bh;
    __nv_bfloat162 l; l.x = __float2bfloat16(ar); l.y = __float2bfloat16(br);
    hi = *(uint32_t*)&h;
    lo = *(uint32_t*)&l;
}

__device__ __forceinline__ void split2h(float a, float b, uint32_t& hi, uint32_t& lo) {
    __half ah = __float2half_rn(a), bh = __float2half_rn(b);
    float ar = a - __half2float(ah), br = b - __half2float(bh);
    __half2 h = __halves2half2(ah, bh);
    __half2 l = __halves2half2(__float2half_rn(ar), __float2half_rn(br));
    hi = *(uint32_t*)&h;
    lo = *(uint32_t*)&l;
}

__device__ __forceinline__ uint32_t pack2h(float a, float b) {
    __half2 h = __halves2half2(__float2half_rn(a), __float2half_rn(b));
    return *(uint32_t*)&h;
}

// ---------------- combined input split kernel --------------------------------
__global__ void __launch_bounds__(256) split_all_kernel(
    const float* __restrict__ xr,  const float* __restrict__ xi,
    const float* __restrict__ wqr, const float* __restrict__ wqi,
    const float* __restrict__ wor, const float* __restrict__ woi)
{
    const int blk = blockIdx.x;
    const float* src; __half *hi, *lo = nullptr; int off;
    if      (blk <  2048) { src = xr;  hi = g_Xr; off = blk; }
    else if (blk <  4096) { src = xi;  hi = g_Xi; off = blk - 2048; }
    else if (blk <  7168) { src = wqr; hi = g_Wqr_h; lo = g_Wqr_l; off = blk - 4096; }
    else if (blk < 10240) { src = wqi; hi = g_Wqi_h; lo = g_Wqi_l; off = blk - 7168; }
    else if (blk < 11264) { src = wor; hi = g_Wor_h; lo = g_Wor_l; off = blk - 10240; }
    else                  { src = woi; hi = g_Woi_h; lo = g_Woi_l; off = blk - 11264; }
    const int i = (off * 256 + threadIdx.x) * 4;
    float4 x = *(const float4*)(src + i);
    if (lo) {
        uint32_t h01, l01, h23, l23;
        split2h(x.x, x.y, h01, l01);
        split2h(x.z, x.w, h23, l23);
        *(uint2*)(hi + i) = make_uint2(h01, h23);
        *(uint2*)(lo + i) = make_uint2(l01, l23);
    } else {
        *(uint2*)(hi + i) = make_uint2(pack2h(x.x, x.y), pack2h(x.z, x.w));
    }
}

// ---------------- fp16 2-term complex GEMM core (2 blocks/SM) ----------------
// Block 64(m) x 128(n), 128 threads, 4 warps as 2(m) x 2(n), warp tile 32x64
// (inner loop byte-identical to the 701us version). K-chunk 32, double buffer.
// Stage: Ar @0, Ai @5120, B[4] @10240+v*10240. Pitch 80 B. Stage 51200 B.
#define STG 51200
#define GEMM_SMEM (2 * STG)   // 102400; also covers qkv epilogue staging 69632
#define NCHUNK (DIMM / 32)

__device__ __forceinline__ void stage_load(uint32_t sA,
    const __half* const* Av, const __half* const* Bv,
    int m0, int e0, int k0, int tid)
{
    #pragma unroll
    for (int v = 0; v < 2; v++) {
        const __half* srcA = Av[v] + (size_t)m0 * DIMM + k0;
        uint32_t dstA = sA + v * 5120u;
        #pragma unroll
        for (int t = 0; t < 2; t++) {
            int idx = tid + t * 128;
            int r = idx >> 2, c = idx & 3;
            CP16(dstA + r * 80 + c * 16, srcA + (size_t)r * DIMM + c * 8);
        }
    }
    #pragma unroll
    for (int v = 0; v < 4; v++) {
        const __half* srcB = Bv[v] + (size_t)e0 * DIMM + k0;
        uint32_t dstB = sA + 10240u + v * 10240u;
        #pragma unroll
        for (int t = 0; t < 4; t++) {
            int idx = tid + t * 128;
            int r = idx >> 2, c = idx & 3;
            CP16(dstB + r * 80 + c * 16, srcB + (size_t)r * DIMM + c * 8);
        }
    }
}

__device__ __forceinline__ void gemm_compute(uint32_t ss, int lane, int wm, int wn,
    float accR[2][8][4], float accI[2][8][4])
{
    const uint32_t aRow = (uint32_t)(lane & 15);
    const uint32_t aSel = (uint32_t)(lane >> 4);
    const uint32_t nl   = (uint32_t)((lane & 7) + ((lane >> 4) << 3));
    const uint32_t ksel = (uint32_t)((lane >> 3) & 1);

    #pragma unroll
    for (int ks = 0; ks < 2; ks++) {
        uint32_t Ar[2][4], Ai[2][4], nAi[2][4];
        #pragma unroll
        for (int mf = 0; mf < 2; mf++) {
            uint32_t addr = ss + (wm * 32 + mf * 16 + aRow) * 80u
                            + aSel * 16u + ks * 32u;
            ldm_x4(Ar[mf], addr);
            ldm_x4(Ai[mf], addr + 5120u);
            #pragma unroll
            for (int q = 0; q < 4; q++) nAi[mf][q] = Ai[mf][q] ^ 0x80008000u;
        }
        #pragma unroll
        for (int h = 0; h < 4; h++) {
            uint32_t Bf[4][4];   // Brh, Brl, Bih, Bil
            const uint32_t ba = ss + 10240u
                + (wn * 64 + h * 16 + nl) * 80u + ksel * 16u + ks * 32u;
            #pragma unroll
            for (int v = 0; v < 4; v++) ldm_x4(Bf[v], ba + v * 10240u);
            #pragma unroll
            for (int mf = 0; mf < 2; mf++)
                #pragma unroll
                for (int sub = 0; sub < 2; sub++) {
                    const int nf = h * 2 + sub;
                    const uint32_t* Brh = &Bf[0][sub * 2];
                    const uint32_t* Brl = &Bf[1][sub * 2];
                    const uint32_t* Bih = &Bf[2][sub * 2];
                    const uint32_t* Bil = &Bf[3][sub * 2];
                    float* cr = accR[mf][nf];
                    float* ci = accI[mf][nf];
                    // real = Ar*Br - Ai*Bi   (2-term: Ah*Bh + Ah*Bl)
                    mma16816h(cr, Ar[mf],  Brh);
                    mma16816h(cr, Ar[mf],  Brl);
                    mma16816h(cr, nAi[mf], Bih);
                    mma16816h(cr, nAi[mf], Bil);
                    // imag = Ar*Bi + Ai*Br
                    mma16816h(ci, Ar[mf],  Bih);
                    mma16816h(ci, Ar[mf],  Bil);
                    mma16816h(ci, Ai[mf],  Brh);
                    mma16816h(ci, Ai[mf],  Brl);
                }
        }
    }
}

// ---------------- qkv GEMM: smem-staged epilogue, [bh][d][n] writes ----------
__global__ void __launch_bounds__(128, 2) qkv_mma_kernel(
    const float* __restrict__ br, const float* __restrict__ bi,
    const float* __restrict__ fr, const float* __restrict__ fi)
{
    extern __shared__ char smrw[];
    const uint32_t sb = smem_u32(smrw);
    const int tid = threadIdx.x, lane = tid & 31, wid = tid >> 5;
    const int wm = wid >> 1, wn = wid & 1;
    const int e0 = blockIdx.x * 128, m0 = blockIdx.y * 64;

    const __half* Av[2] = {g_Xr, g_Xi};
    const __half* Bv[4] = {g_Wqr_h, g_Wqr_l, g_Wqi_h, g_Wqi_l};

    float accR[2][8][4] = {}, accI[2][8][4] = {};

    stage_load(sb, Av, Bv, m0, e0, 0, tid);
    CP_COMMIT();

    #pragma unroll 1
    for (int c = 0; c < NCHUNK; c++) {
        const int s = c & 1;
        if (c + 1 < NCHUNK) {
            stage_load(sb + (s ^ 1) * STG, Av, Bv, m0, e0, (c + 1) * 32, tid);
            CP_COMMIT();
            CP_WAIT(1);
        } else {
            CP_WAIT(0);
        }
        __syncthreads();
        gemm_compute(sb + s * STG, lane, wm, wn, accR, accI);
        __syncthreads();
    }

    // ---- stage accumulators to smem as [e 128][m pitch 68] fp32 ----
    float* smr = (float*)smrw;
    float* smi = smr + 128 * 68;
    #pragma unroll
    for (int mf = 0; mf < 2; mf++)
        #pragma unroll
        for (int nf = 0; nf < 8; nf++)
            #pragma unroll
            for (int rp = 0; rp < 2; rp++)
                #pragma unroll
                for (int cp = 0; cp < 2; cp++) {
                    const int el = wn * 64 + nf * 8 + (lane & 3) * 2 + cp;
                    const int ml = wm * 32 + mf * 16 + (lane >> 2) + rp * 8;
                    smr[el * 68 + ml] = accR[mf][nf][rp * 2 + cp];
                    smi[el * 68 + ml] = accI[mf][nf][rp * 2 + cp];
                }
    __syncthreads();

    // ---- each thread: one e-column, packed uint2 n-run stores (64 n) ----
    const int el = tid;
    const int e = e0 + el;
    const int h = e / 192, rem = e % 192;
    const int d = rem / 3, which = rem % 3;
    const float bre = br[e], bie = bi[e];
    const int b = m0 >> 10, n0 = m0 & 1023;
    const int bh = b * HEADS + h;
    __nv_bfloat16 *dRh, *dRl, *dIh, *dIl;
    if (which == 0)      { dRh = g_Qrh; dRl = g_Qrl; dIh = g_Qih; dIl = g_Qil; }
    else if (which == 1) { dRh = g_Krh; dRl = g_Krl; dIh = g_Kih; dIl = g_Kil; }
    else                 { dRh = g_Vrh; dRl = g_Vrl; dIh = g_Vih; dIl = g_Vil; }
    const size_t dbase = (size_t)(bh * HD + d) * Nn + n0;
    const float* smr_e = smr + el * 68;
    const float* smi_e = smi + el * 68;

    #pragma unroll 1
    for (int mc = 0; mc < 16; mc++) {
        float4 srv = *(const float4*)(smr_e + mc * 4);
        float4 siv = *(const float4*)(smi_e + mc * 4);
        float vr[4] = {srv.x + bre, srv.y + bre, srv.z + bre, srv.w + bre};
        float vi[4] = {siv.x + bie, siv.y + bie, siv.z + bie, siv.w + bie};
        if (which < 2) {
            #pragma unroll
            for (int j = 0; j < 4; j++) {
                const int n = n0 + mc * 4 + j;
                const float frv = fr[n * HD + d], fiv = fi[n * HD + d];
                const float rr = vr[j] * frv - vi[j] * fiv;
                vi[j] = vr[j] * fiv + vi[j] * frv;
                vr[j] = rr;
            }
        }
        uint32_t h01, l01, h23, l23;
        split2(vr[0], vr[1], h01, l01);
        split2(vr[2], vr[3], h23, l23);
        *(uint2*)(dRh + dbase + mc * 4) = make_uint2(h01, h23);
        *(uint2*)(dRl + dbase + mc * 4) = make_uint2(l01, l23);
        split2(vi[0], vi[1], h01, l01);
        split2(vi[2], vi[3], h23, l23);
        *(uint2*)(dIh + dbase + mc * 4) = make_uint2(h01, h23);
        *(uint2*)(dIl + dbase + mc * 4) = make_uint2(l01, l23);
    }
}

// ---------------- output GEMM (float2-packed epilogue) -----------------------
__global__ void __launch_bounds__(128, 2) out_mma_kernel(
    const float* __restrict__ br, const float* __restrict__ bi,
    float* __restrict__ out)
{
    extern __shared__ char smrw[];
    const uint32_t sb = smem_u32(smrw);
    const int tid = threadIdx.x, lane = tid & 31, wid = tid >> 5;
    const int wm = wid >> 1, wn = wid & 1;
    const int e0 = blockIdx.x * 128, m0 = blockIdx.y * 64;

    const __half* Av[2] = {g_Ar, g_Ai};
    const __half* Bv[4] = {g_Wor_h, g_Wor_l, g_Woi_h, g_Woi_l};

    float accR[2][8][4] = {}, accI[2][8][4] = {};

    stage_load(sb, Av, Bv, m0, e0, 0, tid);
    CP_COMMIT();

    #pragma unroll 1
    for (int c = 0; c < NCHUNK; c++) {
        const int s = c & 1;
        if (c + 1 < NCHUNK) {
            stage_load(sb + (s ^ 1) * STG, Av, Bv, m0, e0, (c + 1) * 32, tid);
            CP_COMMIT();
            CP_WAIT(1);
        } else {
            CP_WAIT(0);
        }
        __syncthreads();
        gemm_compute(sb + s * STG, lane, wm, wn, accR, accI);
        __syncthreads();
    }

    #pragma unroll
    for (int mf = 0; mf < 2; mf++)
        #pragma unroll
        for (int nf = 0; nf < 8; nf++)
            #pragma unroll
            for (int rp = 0; rp < 2; rp++) {
                const int m = m0 + wm * 32 + mf * 16 + (lane >> 2) + rp * 8;
                const int e = e0 + wn * 64 + nf * 8 + (lane & 3) * 2;
                float2 vr = make_float2(accR[mf][nf][rp * 2] + br[e],
                                        accR[mf][nf][rp * 2 + 1] + br[e + 1]);
                float2 vi = make_float2(accI[mf][nf][rp * 2] + bi[e],
                                        accI[mf][nf][rp * 2 + 1] + bi[e + 1]);
                *(float2*)&out[(size_t)m * DIMM + e] = vr;
                *(float2*)&out[(size_t)Mtot * DIMM + (size_t)m * DIMM + e] = vi;
            }
}

// ---------------- tensor-core flash attention (unchanged, bf16) --------------
#define PCHQ 272
#define VQ   17408
#define PCHK 144
#define VKV  9216
#define SK_OFF (4 * VQ)
#define STG_KV (4 * VKV)
#define SV_OFF (SK_OFF + 2 * STG_KV)
#define ATTN_SMEM (SV_OFF + 2 * STG_KV)

__device__ __forceinline__ void load_kv(uint32_t sb,
    const __nv_bfloat16* const* Kv, const __nv_bfloat16* const* Vv,
    int k0, int s, int tid)
{
    #pragma unroll
    for (int v = 0; v < 4; v++)
        #pragma unroll
        for (int t = 0; t < 2; t++) {
            int i = tid + t * 256;
            int r = i >> 3, c = i & 7;
            CP16(sb + SK_OFF + s * STG_KV + v * VKV + r * PCHK + c * 16,
                 Kv[v] + (size_t)r * Nn + k0 + c * 8);
            CP16(sb + SV_OFF + s * STG_KV + v * VKV + r * PCHK + c * 16,
                 Vv[v] + (size_t)r * Nn + k0 + c * 8);
        }
}

__global__ void __launch_bounds__(256, 1) attn_mma_kernel()
{
    extern __shared__ char smrw[];
    const uint32_t sb = smem_u32(smrw);
    const int tid = threadIdx.x, lane = tid & 31, wid = tid >> 5;
    const int bh = blockIdx.y, q0 = blockIdx.x * 128;
    const size_t base = (size_t)bh * Nn * HD;

    const __nv_bfloat16* Qv[4] = {g_Qrh + base, g_Qrl + base, g_Qih + base, g_Qil + base};
    const __nv_bfloat16* Kv[4] = {g_Krh + base, g_Krl + base, g_Kih + base, g_Kil + base};
    const __nv_bfloat16* Vv[4] = {g_Vrh + base, g_Vrl + base, g_Vih + base, g_Vil + base};

    #pragma unroll
    for (int v = 0; v < 4; v++)
        #pragma unroll
        for (int t = 0; t < 4; t++) {
            int i = tid + t * 256;
            int r = i >> 4, c = i & 15;
            CP16(sb + v * VQ + r * PCHQ + c * 16, Qv[v] + (size_t)r * Nn + q0 + c * 8);
        }
    load_kv(sb, Kv, Vv, 0, 0, tid);
    CP_COMMIT();

    float oR[8][4] = {}, oI[8][4] = {};
    float m0 = -1e30f, m1 = -1e30f, l0 = 0.f, l1 = 0.f;
    const int r0 = wid * 16;

    #pragma unroll 1
    for (int kt = 0; kt < 16; kt++) {
        const int s = kt & 1;
        if (kt + 1 < 16) {
            load_kv(sb, Kv, Vv, (kt + 1) * 64, s ^ 1, tid);
            CP_COMMIT();
            CP_WAIT(1);
        } else {
            CP_WAIT(0);
        }
        __syncthreads();

        const uint32_t sK = sb + SK_OFF + s * STG_KV;
        const uint32_t sV = sb + SV_OFF + s * STG_KV;

        float sR[8][4] = {}, sI[8][4] = {};
        #pragma unroll
        for (int ks = 0; ks < 4; ks++) {
            uint32_t Qf[4][4];
            const uint32_t qa = sb
                + (ks * 16 + (lane & 7) + ((lane >> 4) & 1) * 8) * PCHQ
                + (r0 + ((lane >> 3) & 1) * 8) * 2;
            #pragma unroll
            for (int v = 0; v < 4; v++) ldm_x4_t(Qf[v], qa + v * VQ);
            uint32_t nQrh[4], nQrl[4];
            #pragma unroll
            for (int q = 0; q < 4; q++) {
                nQrh[q] = Qf[0][q] ^ 0x80008000u;
                nQrl[q] = Qf[1][q] ^ 0x80008000u;
            }
            #pragma unroll
            for (int np = 0; np < 4; np++) {
                uint32_t Kf[4][4];
                const uint32_t ka = sK
                    + (ks * 16 + (lane & 7) + ((lane >> 3) & 1) * 8) * PCHK
                    + (np * 16 + ((lane >> 4) & 1) * 8) * 2;
                #pragma unroll
                for (int v = 0; v < 4; v++) ldm_x4_t(Kf[v], ka + v * VKV);
                #pragma unroll
                for (int sub = 0; sub < 2; sub++) {
                    const int nt = np * 2 + sub;
                    const uint32_t* Krh = &Kf[0][sub * 2];
                    const uint32_t* Krl = &Kf[1][sub * 2];
                    const uint32_t* Kih = &Kf[2][sub * 2];
                    const uint32_t* Kil = &Kf[3][sub * 2];
                    mma16816(sR[nt], Qf[0], Krh);
                    mma16816(sR[nt], Qf[0], Krl);
                    mma16816(sR[nt], Qf[1], Krh);
                    mma16816(sR[nt], Qf[2], Kih);
                    mma16816(sR[nt], Qf[2], Kil);
                    mma16816(sR[nt], Qf[3], Kih);
                    mma16816(sI[nt], Qf[2], Krh);
                    mma16816(sI[nt], Qf[2], Krl);
                    mma16816(sI[nt], Qf[3], Krh);
                    mma16816(sI[nt], nQrh,  Kih);
                    mma16816(sI[nt], nQrh,  Kil);
                    mma16816(sI[nt], nQrl,  Kih);
                }
            }
        }

        float vm0 = -1e30f, vm1 = -1e30f;
        #pragma unroll
        for (int nt = 0; nt < 8; nt++)
            #pragma unroll
            for (int p = 0; p < 4; p++) {
                const float v = 0.125f * sqrtf(sR[nt][p] * sR[nt][p] + sI[nt][p] * sI[nt][p]);
                sR[nt][p] = v;
                if (p < 2) vm0 = fmaxf(vm0, v); else vm1 = fmaxf(vm1, v);
            }
        vm0 = fmaxf(vm0, __shfl_xor_sync(0xffffffffu, vm0, 1));
        vm0 = fmaxf(vm0, __shfl_xor_sync(0xffffffffu, vm0, 2));
        vm1 = fmaxf(vm1, __shfl_xor_sync(0xffffffffu, vm1, 1));
        vm1 = fmaxf(vm1, __shfl_xor_sync(0xffffffffu, vm1, 2));
        const float mn0 = fmaxf(m0, vm0), mn1 = fmaxf(m1, vm1);
        const float a0 = __expf(m0 - mn0), a1 = __expf(m1 - mn1);
        m0 = mn0; m1 = mn1;
        #pragma unroll
        for (int nt = 0; nt < 8; nt++)
            #pragma unroll
            for (int p = 0; p < 4; p++) {
                const float al = (p < 2) ? a0 : a1;
                oR[nt][p] *= al;
                oI[nt][p] *= al;
            }
        float s0 = 0.f, s1 = 0.f;
        #pragma unroll
        for (int nt = 0; nt < 8; nt++)
            #pragma unroll
            for (int p = 0; p < 4; p++) {
                const float pv = __expf(sR[nt][p] - ((p < 2) ? mn0 : mn1));
                sR[nt][p] = pv;
                if (p < 2) s0 += pv; else s1 += pv;
            }
        s0 += __shfl_xor_sync(0xffffffffu, s0, 1);
        s0 += __shfl_xor_sync(0xffffffffu, s0, 2);
        s1 += __shfl_xor_sync(0xffffffffu, s1, 1);
        s1 += __shfl_xor_sync(0xffffffffu, s1, 2);
        l0 = l0 * a0 + s0;
        l1 = l1 * a1 + s1;

        uint32_t Ph[4][4], Pl[4][4];
        #pragma unroll
        for (int j = 0; j < 4; j++) {
            const int t0 = 2 * j, t1 = 2 * j + 1;
            split2(sR[t0][0], sR[t0][1], Ph[j][0], Pl[j][0]);
            split2(sR[t0][2], sR[t0][3], Ph[j][1], Pl[j][1]);
            split2(sR[t1][0], sR[t1][1], Ph[j][2], Pl[j][2]);
            split2(sR[t1][2], sR[t1][3], Ph[j][3], Pl[j][3]);
        }

        #pragma unroll
        for (int j = 0; j < 4; j++) {
            #pragma unroll
            for (int g = 0; g < 4; g++) {
                uint32_t Vf[4][4];
                const uint32_t va = sV
                    + (g * 16 + (lane & 7) + ((lane >> 4) & 1) * 8) * PCHK
                    + j * 32 + ((lane >> 3) & 1) * 16;
                #pragma unroll
                for (int v = 0; v < 4; v++) ldm_x4(Vf[v], va + v * VKV);
                #pragma unroll
                for (int sub = 0; sub < 2; sub++) {
                    const int nt = g * 2 + sub;
                    const uint32_t* Vrh = &Vf[0][sub * 2];
                    const uint32_t* Vrl = &Vf[1][sub * 2];
                    const uint32_t* Vih = &Vf[2][sub * 2];
                    const uint32_t* Vil = &Vf[3][sub * 2];
                    mma16816(oR[nt], Ph[j], Vrh);
                    mma16816(oR[nt], Pl[j], Vrh);
                    mma16816(oR[nt], Ph[j], Vrl);
                    mma16816(oI[nt], Ph[j], Vih);
                    mma16816(oI[nt], Pl[j], Vih);
                    mma16816(oI[nt], Ph[j], Vil);
                }
            }
        }
        __syncthreads();
    }

    // ---- normalize + packed fp16 AO writes to [b][n][h*64+d] ----
    const float inv0 = 1.0f / l0, inv1 = 1.0f / l1;
    const int b = bh / HEADS, h = bh % HEADS;
    #pragma unroll
    for (int nt = 0; nt < 8; nt++)
        #pragma unroll
        for (int rp = 0; rp < 2; rp++) {
            const int n = q0 + r0 + (lane >> 2) + rp * 8;
            const int d0 = nt * 8 + (lane & 3) * 2;
            const float inv = (rp == 0) ? inv0 : inv1;
            const size_t idx = ((size_t)(b * Nn + n)) * DIMM + h * HD + d0;
            *(uint32_t*)(g_Ar + idx) =
                pack2h(oR[nt][rp * 2] * inv, oR[nt][rp * 2 + 1] * inv);
            *(uint32_t*)(g_Ai + idx) =
                pack2h(oI[nt][rp * 2] * inv, oI[nt][rp * 2 + 1] * inv);
        }
}

// ---------------- launch ------------------------------------------------------
extern "C" void kernel_launch(void* const* d_in, const int* in_sizes, int n_in,
                              void* d_out, int out_size)
{
    const float* xr  = (const float*)d_in[0];
    const float* xi  = (const float*)d_in[1];
    const float* fr  = (const float*)d_in[2];
    const float* fi  = (const float*)d_in[3];
    const float* wqr = (const float*)d_in[4];
    const float* wqi = (const float*)d_in[5];
    const float* bqr = (const float*)d_in[6];
    const float* bqi = (const float*)d_in[7];
    const float* wor = (const float*)d_in[8];
    const float* woi = (const float*)d_in[9];
    const float* bor = (const float*)d_in[10];
    const float* boi = (const float*)d_in[11];
    float* out = (float*)d_out;

    cudaFuncSetAttribute(qkv_mma_kernel,
                         cudaFuncAttributeMaxDynamicSharedMemorySize, GEMM_SMEM);
    cudaFuncSetAttribute(out_mma_kernel,
                         cudaFuncAttributeMaxDynamicSharedMemorySize, GEMM_SMEM);
    cudaFuncSetAttribute(attn_mma_kernel,
                         cudaFuncAttributeMaxDynamicSharedMemorySize, ATTN_SMEM);

    split_all_kernel<<<12288, 256>>>(xr, xi, wqr, wqi, wor, woi);
    qkv_mma_kernel<<<dim3(E3 / 128, Mtot / 64), 128, GEMM_SMEM>>>(bqr, bqi, fr, fi);
    attn_mma_kernel<<<dim3(Nn / 128, Bb * HEADS), 256, ATTN_SMEM>>>();
    out_mma_kernel<<<dim3(DIMM / 128, Mtot / 64), 128, GEMM_SMEM>>>(bor, boi, out);
}

// round 13
// speedup vs baseline: 1.3264x; 1.0296x over previous
#include <cuda_runtime.h>
#include <cuda_bf16.h>
#include <cuda_fp16.h>
#include <stdint.h>
#include <math.h>

#define Bb    2
#define Nn    1024
#define DIMM  1024
#define HEADS 16
#define HD    64
#define Mtot  (Bb * Nn)      // 2048
#define E3    (3 * DIMM)     // 3072

// ---------------- fp16 GEMM operand scratch ----------------------------------
__device__ __half g_Xr[Mtot * DIMM], g_Xi[Mtot * DIMM];           // A hi only
__device__ __half g_Wqr_h[E3 * DIMM],  g_Wqr_l[E3 * DIMM];
__device__ __half g_Wqi_h[E3 * DIMM],  g_Wqi_l[E3 * DIMM];
__device__ __half g_Wor_h[DIMM * DIMM], g_Wor_l[DIMM * DIMM];
__device__ __half g_Woi_h[DIMM * DIMM], g_Woi_l[DIMM * DIMM];
__device__ __half g_Ar[Mtot * DIMM], g_Ai[Mtot * DIMM];           // AO hi only

// Q/K bf16 hi/lo (+ Karatsuba sum/diff), V fp16; layout [b*H + h][d][n]
#define QKV_SZ (Bb * HEADS * Nn * HD)
__device__ __nv_bfloat16 g_Qrh[QKV_SZ], g_Qrl[QKV_SZ], g_Qih[QKV_SZ], g_Qil[QKV_SZ];
__device__ __nv_bfloat16 g_Qsh[QKV_SZ], g_Qsl[QKV_SZ];            // Qs = Qr + Qi
__device__ __nv_bfloat16 g_Krh[QKV_SZ], g_Krl[QKV_SZ], g_Kih[QKV_SZ], g_Kil[QKV_SZ];
__device__ __nv_bfloat16 g_Kdh[QKV_SZ], g_Kdl[QKV_SZ];            // Kd = Kr - Ki
__device__ __half g_Vr[QKV_SZ], g_Vi[QKV_SZ];                     // fp16 single

// ---------------- helpers ----------------------------------------------------
__device__ __forceinline__ uint32_t smem_u32(const void* p) {
    uint32_t a;
    asm("{ .reg .u64 t; cvta.to.shared.u64 t, %1; cvt.u32.u64 %0, t; }"
        : "=r"(a) : "l"(p));
    return a;
}

#define CP16(dst, src) \
    asm volatile("cp.async.cg.shared.global [%0], [%1], 16;" \
                 :: "r"((uint32_t)(dst)), "l"(src) : "memory")
#define CP_COMMIT() asm volatile("cp.async.commit_group;" ::: "memory")
#define CP_WAIT(n)  asm volatile("cp.async.wait_group %0;" :: "n"(n) : "memory")

__device__ __forceinline__ void ldm_x4(uint32_t* r, uint32_t addr) {
    asm volatile("ldmatrix.sync.aligned.m8n8.x4.shared.b16 {%0,%1,%2,%3}, [%4];"
        : "=r"(r[0]), "=r"(r[1]), "=r"(r[2]), "=r"(r[3]) : "r"(addr));
}

__device__ __forceinline__ void ldm_x4_t(uint32_t* r, uint32_t addr) {
    asm volatile("ldmatrix.sync.aligned.m8n8.x4.trans.shared.b16 {%0,%1,%2,%3}, [%4];"
        : "=r"(r[0]), "=r"(r[1]), "=r"(r[2]), "=r"(r[3]) : "r"(addr));
}

// bf16 mma (attention QK)
__device__ __forceinline__ void mma16816(float* c, const uint32_t* a, const uint32_t* b) {
    asm volatile("mma.sync.aligned.m16n8k16.row.col.f32.bf16.bf16.f32 "
        "{%0,%1,%2,%3}, {%4,%5,%6,%7}, {%8,%9}, {%0,%1,%2,%3};"
        : "+f"(c[0]), "+f"(c[1]), "+f"(c[2]), "+f"(c[3])
        : "r"(a[0]), "r"(a[1]), "r"(a[2]), "r"(a[3]), "r"(b[0]), "r"(b[1]));
}

// fp16 mma (GEMMs + attention PV)
__device__ __forceinline__ void mma16816h(float* c, const uint32_t* a, const uint32_t* b) {
    asm volatile("mma.sync.aligned.m16n8k16.row.col.f32.f16.f16.f32 "
        "{%0,%1,%2,%3}, {%4,%5,%6,%7}, {%8,%9}, {%0,%1,%2,%3};"
        : "+f"(c[0]), "+f"(c[1]), "+f"(c[2]), "+f"(c[3])
        : "r"(a[0]), "r"(a[1]), "r"(a[2]), "r"(a[3]), "r"(b[0]), "r"(b[1]));
}

__device__ __forceinline__ void split2(float a, float b, uint32_t& hi, uint32_t& lo) {
    __nv_bfloat16 ah = __float2bfloat16(a), bh = __float2bfloat16(b);
    float ar = a - __bfloat162float(ah), br = b - __bfloat162float(bh);
    __nv_bfloat162 h; h.x = ah; h.y = bh;
    __nv_bfloat162 l; l.x = __float2bfloat16(ar); l.y = __float2bfloat16(br);
    hi = *(uint32_t*)&h;
    lo = *(uint32_t*)&l;
}

__device__ __forceinline__ void split2h(float a, float b, uint32_t& hi, uint32_t& lo) {
    __half ah = __float2half_rn(a), bh = __float2half_rn(b);
    float ar = a - __half2float(ah), br = b - __half2float(bh);
    __half2 h = __halves2half2(ah, bh);
    __half2 l = __halves2half2(__float2half_rn(ar), __float2half_rn(br));
    hi = *(uint32_t*)&h;
    lo = *(uint32_t*)&l;
}

__device__ __forceinline__ uint32_t pack2h(float a, float b) {
    __half2 h = __halves2half2(__float2half_rn(a), __float2half_rn(b));
    return *(uint32_t*)&h;
}

// ---------------- combined input split kernel --------------------------------
__global__ void __launch_bounds__(256) split_all_kernel(
    const float* __restrict__ xr,  const float* __restrict__ xi,
    const float* __restrict__ wqr, const float* __restrict__ wqi,
    const float* __restrict__ wor, const float* __restrict__ woi)
{
    const int blk = blockIdx.x;
    const float* src; __half *hi, *lo = nullptr; int off;
    if      (blk <  2048) { src = xr;  hi = g_Xr; off = blk; }
    else if (blk <  4096) { src = xi;  hi = g_Xi; off = blk - 2048; }
    else if (blk <  7168) { src = wqr; hi = g_Wqr_h; lo = g_Wqr_l; off = blk - 4096; }
    else if (blk < 10240) { src = wqi; hi = g_Wqi_h; lo = g_Wqi_l; off = blk - 7168; }
    else if (blk < 11264) { src = wor; hi = g_Wor_h; lo = g_Wor_l; off = blk - 10240; }
    else                  { src = woi; hi = g_Woi_h; lo = g_Woi_l; off = blk - 11264; }
    const int i = (off * 256 + threadIdx.x) * 4;
    float4 x = *(const float4*)(src + i);
    if (lo) {
        uint32_t h01, l01, h23, l23;
        split2h(x.x, x.y, h01, l01);
        split2h(x.z, x.w, h23, l23);
        *(uint2*)(hi + i) = make_uint2(h01, h23);
        *(uint2*)(lo + i) = make_uint2(l01, l23);
    } else {
        *(uint2*)(hi + i) = make_uint2(pack2h(x.x, x.y), pack2h(x.z, x.w));
    }
}

// ---------------- fp16 2-term complex GEMM core (unchanged from 690us) -------
#define STG 51200
#define GEMM_SMEM (2 * STG)
#define NCHUNK (DIMM / 32)

__device__ __forceinline__ void stage_load(uint32_t sA,
    const __half* const* Av, const __half* const* Bv,
    int m0, int e0, int k0, int tid)
{
    #pragma unroll
    for (int v = 0; v < 2; v++) {
        const __half* srcA = Av[v] + (size_t)m0 * DIMM + k0;
        uint32_t dstA = sA + v * 5120u;
        #pragma unroll
        for (int t = 0; t < 2; t++) {
            int idx = tid + t * 128;
            int r = idx >> 2, c = idx & 3;
            CP16(dstA + r * 80 + c * 16, srcA + (size_t)r * DIMM + c * 8);
        }
    }
    #pragma unroll
    for (int v = 0; v < 4; v++) {
        const __half* srcB = Bv[v] + (size_t)e0 * DIMM + k0;
        uint32_t dstB = sA + 10240u + v * 10240u;
        #pragma unroll
        for (int t = 0; t < 4; t++) {
            int idx = tid + t * 128;
            int r = idx >> 2, c = idx & 3;
            CP16(dstB + r * 80 + c * 16, srcB + (size_t)r * DIMM + c * 8);
        }
    }
}

__device__ __forceinline__ void gemm_compute(uint32_t ss, int lane, int wm, int wn,
    float accR[2][8][4], float accI[2][8][4])
{
    const uint32_t aRow = (uint32_t)(lane & 15);
    const uint32_t aSel = (uint32_t)(lane >> 4);
    const uint32_t nl   = (uint32_t)((lane & 7) + ((lane >> 4) << 3));
    const uint32_t ksel = (uint32_t)((lane >> 3) & 1);

    #pragma unroll
    for (int ks = 0; ks < 2; ks++) {
        uint32_t Ar[2][4], Ai[2][4], nAi[2][4];
        #pragma unroll
        for (int mf = 0; mf < 2; mf++) {
            uint32_t addr = ss + (wm * 32 + mf * 16 + aRow) * 80u
                            + aSel * 16u + ks * 32u;
            ldm_x4(Ar[mf], addr);
            ldm_x4(Ai[mf], addr + 5120u);
            #pragma unroll
            for (int q = 0; q < 4; q++) nAi[mf][q] = Ai[mf][q] ^ 0x80008000u;
        }
        #pragma unroll
        for (int h = 0; h < 4; h++) {
            uint32_t Bf[4][4];
            const uint32_t ba = ss + 10240u
                + (wn * 64 + h * 16 + nl) * 80u + ksel * 16u + ks * 32u;
            #pragma unroll
            for (int v = 0; v < 4; v++) ldm_x4(Bf[v], ba + v * 10240u);
            #pragma unroll
            for (int mf = 0; mf < 2; mf++)
                #pragma unroll
                for (int sub = 0; sub < 2; sub++) {
                    const int nf = h * 2 + sub;
                    const uint32_t* Brh = &Bf[0][sub * 2];
                    const uint32_t* Brl = &Bf[1][sub * 2];
                    const uint32_t* Bih = &Bf[2][sub * 2];
                    const uint32_t* Bil = &Bf[3][sub * 2];
                    float* cr = accR[mf][nf];
                    float* ci = accI[mf][nf];
                    mma16816h(cr, Ar[mf],  Brh);
                    mma16816h(cr, Ar[mf],  Brl);
                    mma16816h(cr, nAi[mf], Bih);
                    mma16816h(cr, nAi[mf], Bil);
                    mma16816h(ci, Ar[mf],  Bih);
                    mma16816h(ci, Ar[mf],  Bil);
                    mma16816h(ci, Ai[mf],  Brh);
                    mma16816h(ci, Ai[mf],  Brl);
                }
        }
    }
}

// ---------------- qkv GEMM: epilogue writes Karatsuba operand sets -----------
__global__ void __launch_bounds__(128, 2) qkv_mma_kernel(
    const float* __restrict__ br, const float* __restrict__ bi,
    const float* __restrict__ fr, const float* __restrict__ fi)
{
    extern __shared__ char smrw[];
    const uint32_t sb = smem_u32(smrw);
    const int tid = threadIdx.x, lane = tid & 31, wid = tid >> 5;
    const int wm = wid >> 1, wn = wid & 1;
    const int e0 = blockIdx.x * 128, m0 = blockIdx.y * 64;

    const __half* Av[2] = {g_Xr, g_Xi};
    const __half* Bv[4] = {g_Wqr_h, g_Wqr_l, g_Wqi_h, g_Wqi_l};

    float accR[2][8][4] = {}, accI[2][8][4] = {};

    stage_load(sb, Av, Bv, m0, e0, 0, tid);
    CP_COMMIT();

    #pragma unroll 1
    for (int c = 0; c < NCHUNK; c++) {
        const int s = c & 1;
        if (c + 1 < NCHUNK) {
            stage_load(sb + (s ^ 1) * STG, Av, Bv, m0, e0, (c + 1) * 32, tid);
            CP_COMMIT();
            CP_WAIT(1);
        } else {
            CP_WAIT(0);
        }
        __syncthreads();
        gemm_compute(sb + s * STG, lane, wm, wn, accR, accI);
        __syncthreads();
    }

    // ---- stage accumulators to smem as [e 128][m pitch 68] fp32 ----
    float* smr = (float*)smrw;
    float* smi = smr + 128 * 68;
    #pragma unroll
    for (int mf = 0; mf < 2; mf++)
        #pragma unroll
        for (int nf = 0; nf < 8; nf++)
            #pragma unroll
            for (int rp = 0; rp < 2; rp++)
                #pragma unroll
                for (int cp = 0; cp < 2; cp++) {
                    const int el = wn * 64 + nf * 8 + (lane & 3) * 2 + cp;
                    const int ml = wm * 32 + mf * 16 + (lane >> 2) + rp * 8;
                    smr[el * 68 + ml] = accR[mf][nf][rp * 2 + cp];
                    smi[el * 68 + ml] = accI[mf][nf][rp * 2 + cp];
                }
    __syncthreads();

    // ---- each thread: one e-column, packed n-run stores ----
    const int el = tid;
    const int e = e0 + el;
    const int h = e / 192, rem = e % 192;
    const int d = rem / 3, which = rem % 3;
    const float bre = br[e], bie = bi[e];
    const int b = m0 >> 10, n0 = m0 & 1023;
    const int bh = b * HEADS + h;
    const size_t dbase = (size_t)(bh * HD + d) * Nn + n0;
    const float* smr_e = smr + el * 68;
    const float* smi_e = smi + el * 68;

    __nv_bfloat16 *dRh, *dRl, *dIh, *dIl, *dSh, *dSl;
    float sgn = 1.f;
    if (which == 0) {
        dRh = g_Qrh; dRl = g_Qrl; dIh = g_Qih; dIl = g_Qil;
        dSh = g_Qsh; dSl = g_Qsl;
    } else {
        dRh = g_Krh; dRl = g_Krl; dIh = g_Kih; dIl = g_Kil;
        dSh = g_Kdh; dSl = g_Kdl; sgn = -1.f;
    }

    #pragma unroll 1
    for (int mc = 0; mc < 16; mc++) {
        float4 srv = *(const float4*)(smr_e + mc * 4);
        float4 siv = *(const float4*)(smi_e + mc * 4);
        float vr[4] = {srv.x + bre, srv.y + bre, srv.z + bre, srv.w + bre};
        float vi[4] = {siv.x + bie, siv.y + bie, siv.z + bie, siv.w + bie};
        if (which == 2) {
            *(uint2*)(g_Vr + dbase + mc * 4) =
                make_uint2(pack2h(vr[0], vr[1]), pack2h(vr[2], vr[3]));
            *(uint2*)(g_Vi + dbase + mc * 4) =
                make_uint2(pack2h(vi[0], vi[1]), pack2h(vi[2], vi[3]));
        } else {
            float ss[4];
            #pragma unroll
            for (int j = 0; j < 4; j++) {
                const int n = n0 + mc * 4 + j;
                const float frv = fr[n * HD + d], fiv = fi[n * HD + d];
                const float rr = vr[j] * frv - vi[j] * fiv;
                vi[j] = vr[j] * fiv + vi[j] * frv;
                vr[j] = rr;
                ss[j] = vr[j] + sgn * vi[j];
            }
            uint32_t h01, l01, h23, l23;
            split2(vr[0], vr[1], h01, l01);
            split2(vr[2], vr[3], h23, l23);
            *(uint2*)(dRh + dbase + mc * 4) = make_uint2(h01, h23);
            *(uint2*)(dRl + dbase + mc * 4) = make_uint2(l01, l23);
            split2(vi[0], vi[1], h01, l01);
            split2(vi[2], vi[3], h23, l23);
            *(uint2*)(dIh + dbase + mc * 4) = make_uint2(h01, h23);
            *(uint2*)(dIl + dbase + mc * 4) = make_uint2(l01, l23);
            split2(ss[0], ss[1], h01, l01);
            split2(ss[2], ss[3], h23, l23);
            *(uint2*)(dSh + dbase + mc * 4) = make_uint2(h01, h23);
            *(uint2*)(dSl + dbase + mc * 4) = make_uint2(l01, l23);
        }
    }
}

// ---------------- output GEMM (unchanged) ------------------------------------
__global__ void __launch_bounds__(128, 2) out_mma_kernel(
    const float* __restrict__ br, const float* __restrict__ bi,
    float* __restrict__ out)
{
    extern __shared__ char smrw[];
    const uint32_t sb = smem_u32(smrw);
    const int tid = threadIdx.x, lane = tid & 31, wid = tid >> 5;
    const int wm = wid >> 1, wn = wid & 1;
    const int e0 = blockIdx.x * 128, m0 = blockIdx.y * 64;

    const __half* Av[2] = {g_Ar, g_Ai};
    const __half* Bv[4] = {g_Wor_h, g_Wor_l, g_Woi_h, g_Woi_l};

    float accR[2][8][4] = {}, accI[2][8][4] = {};

    stage_load(sb, Av, Bv, m0, e0, 0, tid);
    CP_COMMIT();

    #pragma unroll 1
    for (int c = 0; c < NCHUNK; c++) {
        const int s = c & 1;
        if (c + 1 < NCHUNK) {
            stage_load(sb + (s ^ 1) * STG, Av, Bv, m0, e0, (c + 1) * 32, tid);
            CP_COMMIT();
            CP_WAIT(1);
        } else {
            CP_WAIT(0);
        }
        __syncthreads();
        gemm_compute(sb + s * STG, lane, wm, wn, accR, accI);
        __syncthreads();
    }

    #pragma unroll
    for (int mf = 0; mf < 2; mf++)
        #pragma unroll
        for (int nf = 0; nf < 8; nf++)
            #pragma unroll
            for (int rp = 0; rp < 2; rp++) {
                const int m = m0 + wm * 32 + mf * 16 + (lane >> 2) + rp * 8;
                const int e = e0 + wn * 64 + nf * 8 + (lane & 3) * 2;
                float2 vr = make_float2(accR[mf][nf][rp * 2] + br[e],
                                        accR[mf][nf][rp * 2 + 1] + br[e + 1]);
                float2 vi = make_float2(accI[mf][nf][rp * 2] + bi[e],
                                        accI[mf][nf][rp * 2 + 1] + bi[e + 1]);
                *(float2*)&out[(size_t)m * DIMM + e] = vr;
                *(float2*)&out[(size_t)Mtot * DIMM + (size_t)m * DIMM + e] = vi;
            }
}

// ---------------- flash attention: Karatsuba QK + fp16 PV --------------------
// smem: Q 6xVQ | K 6xVKV (single) | V 2xVKV fp16 (single) = 178176 B
#define PCHQ 272
#define VQ   17408
#define PCHK 144
#define VKV  9216
#define AK_OFF (6 * VQ)                 // 104448
#define AV_OFF (AK_OFF + 6 * VKV)       // 159744
#define ATTN_SMEM (AV_OFF + 2 * VKV)    // 178176

__device__ __forceinline__ void attn_load_k(uint32_t sK,
    const __nv_bfloat16* const* Kv, int k0, int tid)
{
    #pragma unroll
    for (int v = 0; v < 6; v++)
        #pragma unroll
        for (int t = 0; t < 2; t++) {
            int i = tid + t * 256;
            int r = i >> 3, c = i & 7;
            CP16(sK + v * VKV + r * PCHK + c * 16,
                 Kv[v] + (size_t)r * Nn + k0 + c * 8);
        }
}

__device__ __forceinline__ void attn_load_v(uint32_t sV,
    const __half* const* Vv, int k0, int tid)
{
    #pragma unroll
    for (int v = 0; v < 2; v++)
        #pragma unroll
        for (int t = 0; t < 2; t++) {
            int i = tid + t * 256;
            int r = i >> 3, c = i & 7;
            CP16(sV + v * VKV + r * PCHK + c * 16,
                 Vv[v] + (size_t)r * Nn + k0 + c * 8);
        }
}

__global__ void __launch_bounds__(256, 1) attn_mma_kernel()
{
    extern __shared__ char smrw[];
    const uint32_t sb = smem_u32(smrw);
    const int tid = threadIdx.x, lane = tid & 31, wid = tid >> 5;
    const int bh = blockIdx.y, q0 = blockIdx.x * 128;
    const size_t base = (size_t)bh * Nn * HD;

    const __nv_bfloat16* Qv[6] = {g_Qrh + base, g_Qrl + base, g_Qih + base,
                                  g_Qil + base, g_Qsh + base, g_Qsl + base};
    const __nv_bfloat16* Kv[6] = {g_Krh + base, g_Krl + base, g_Kih + base,
                                  g_Kil + base, g_Kdh + base, g_Kdl + base};
    const __half* Vv[2] = {g_Vr + base, g_Vi + base};

    // Q tile (64 d rows x 128 n cols) + K(0); then V(0)
    #pragma unroll
    for (int v = 0; v < 6; v++)
        #pragma unroll
        for (int t = 0; t < 4; t++) {
            int i = tid + t * 256;
            int r = i >> 4, c = i & 15;
            CP16(sb + v * VQ + r * PCHQ + c * 16, Qv[v] + (size_t)r * Nn + q0 + c * 8);
        }
    attn_load_k(sb + AK_OFF, Kv, 0, tid);
    CP_COMMIT();
    attn_load_v(sb + AV_OFF, Vv, 0, tid);
    CP_COMMIT();

    float oR[8][4] = {}, oI[8][4] = {};
    float m0 = -1e30f, m1 = -1e30f, l0 = 0.f, l1 = 0.f;
    const int r0 = wid * 16;
    const uint32_t sK = sb + AK_OFF;
    const uint32_t sV = sb + AV_OFF;

    #pragma unroll 1
    for (int kt = 0; kt < 16; kt++) {
        CP_WAIT(1);                    // K(kt) (+Q on kt=0) ready
        __syncthreads();

        // ---- Karatsuba S = Q . conj(K): t1=QrKr, t2=QiKi, t3=Qs*Kd ----
        float t1[8][4] = {}, t2[8][4] = {}, t3[8][4] = {};
        #pragma unroll
        for (int ks = 0; ks < 4; ks++) {
            uint32_t Qf[6][4];
            const uint32_t qa = sb
                + (ks * 16 + (lane & 7) + ((lane >> 4) & 1) * 8) * PCHQ
                + (r0 + ((lane >> 3) & 1) * 8) * 2;
            #pragma unroll
            for (int v = 0; v < 6; v++) ldm_x4_t(Qf[v], qa + v * VQ);
            #pragma unroll
            for (int np = 0; np < 4; np++) {
                uint32_t Kf[6][4];
                const uint32_t ka = sK
                    + (ks * 16 + (lane & 7) + ((lane >> 3) & 1) * 8) * PCHK
                    + (np * 16 + ((lane >> 4) & 1) * 8) * 2;
                #pragma unroll
                for (int v = 0; v < 6; v++) ldm_x4_t(Kf[v], ka + v * VKV);
                #pragma unroll
                for (int sub = 0; sub < 2; sub++) {
                    const int nt = np * 2 + sub;
                    const uint32_t* Krh = &Kf[0][sub * 2];
                    const uint32_t* Krl = &Kf[1][sub * 2];
                    const uint32_t* Kih = &Kf[2][sub * 2];
                    const uint32_t* Kil = &Kf[3][sub * 2];
                    const uint32_t* Kdh = &Kf[4][sub * 2];
                    const uint32_t* Kdl = &Kf[5][sub * 2];
                    mma16816(t1[nt], Qf[0], Krh);
                    mma16816(t1[nt], Qf[0], Krl);
                    mma16816(t1[nt], Qf[1], Krh);
                    mma16816(t2[nt], Qf[2], Kih);
                    mma16816(t2[nt], Qf[2], Kil);
                    mma16816(t2[nt], Qf[3], Kih);
                    mma16816(t3[nt], Qf[4], Kdh);
                    mma16816(t3[nt], Qf[4], Kdl);
                    mma16816(t3[nt], Qf[5], Kdh);
                }
            }
        }

        __syncthreads();               // all warps done reading K(kt)
        if (kt + 1 < 16) {
            attn_load_k(sK, Kv, (kt + 1) * 64, tid);
            CP_COMMIT();
        }

        // ---- recombine + scaled abs: re=t1+t2, im=t3-t1+t2; reuse t1 as P --
        float vm0 = -1e30f, vm1 = -1e30f;
        #pragma unroll
        for (int nt = 0; nt < 8; nt++)
            #pragma unroll
            for (int p = 0; p < 4; p++) {
                const float re = t1[nt][p] + t2[nt][p];
                const float im = t3[nt][p] - t1[nt][p] + t2[nt][p];
                const float v = 0.125f * sqrtf(re * re + im * im);
                t1[nt][p] = v;
                if (p < 2) vm0 = fmaxf(vm0, v); else vm1 = fmaxf(vm1, v);
            }
        vm0 = fmaxf(vm0, __shfl_xor_sync(0xffffffffu, vm0, 1));
        vm0 = fmaxf(vm0, __shfl_xor_sync(0xffffffffu, vm0, 2));
        vm1 = fmaxf(vm1, __shfl_xor_sync(0xffffffffu, vm1, 1));
        vm1 = fmaxf(vm1, __shfl_xor_sync(0xffffffffu, vm1, 2));
        const float mn0 = fmaxf(m0, vm0), mn1 = fmaxf(m1, vm1);
        const float a0 = __expf(m0 - mn0), a1 = __expf(m1 - mn1);
        m0 = mn0; m1 = mn1;
        #pragma unroll
        for (int nt = 0; nt < 8; nt++)
            #pragma unroll
            for (int p = 0; p < 4; p++) {
                const float al = (p < 2) ? a0 : a1;
                oR[nt][p] *= al;
                oI[nt][p] *= al;
            }
        float s0 = 0.f, s1 = 0.f;
        #pragma unroll
        for (int nt = 0; nt < 8; nt++)
            #pragma unroll
            for (int p = 0; p < 4; p++) {
                const float pv = __expf(t1[nt][p] - ((p < 2) ? mn0 : mn1));
                t1[nt][p] = pv;
                if (p < 2) s0 += pv; else s1 += pv;
            }
        s0 += __shfl_xor_sync(0xffffffffu, s0, 1);
        s0 += __shfl_xor_sync(0xffffffffu, s0, 2);
        s1 += __shfl_xor_sync(0xffffffffu, s1, 1);
        s1 += __shfl_xor_sync(0xffffffffu, s1, 2);
        l0 = l0 * a0 + s0;
        l1 = l1 * a1 + s1;

        // ---- pack P into fp16 hi/lo A-fragments (exact split) ----
        uint32_t Ph[4][4], Pl[4][4];
        #pragma unroll
        for (int j = 0; j < 4; j++) {
            const int u0 = 2 * j, u1 = 2 * j + 1;
            split2h(t1[u0][0], t1[u0][1], Ph[j][0], Pl[j][0]);
            split2h(t1[u0][2], t1[u0][3], Ph[j][1], Pl[j][1]);
            split2h(t1[u1][0], t1[u1][1], Ph[j][2], Pl[j][2]);
            split2h(t1[u1][2], t1[u1][3], Ph[j][3], Pl[j][3]);
        }

        // ---- wait V(kt); PV in fp16 ----
        if (kt < 15) { CP_WAIT(1); } else { CP_WAIT(0); }
        __syncthreads();

        #pragma unroll
        for (int j = 0; j < 4; j++) {
            #pragma unroll
            for (int g = 0; g < 4; g++) {
                uint32_t Vrf[4], Vif[4];
                const uint32_t va = sV
                    + (g * 16 + (lane & 7) + ((lane >> 4) & 1) * 8) * PCHK
                    + j * 32 + ((lane >> 3) & 1) * 16;
                ldm_x4(Vrf, va);
                ldm_x4(Vif, va + VKV);
                #pragma unroll
                for (int sub = 0; sub < 2; sub++) {
                    const int nt = g * 2 + sub;
                    mma16816h(oR[nt], Ph[j], &Vrf[sub * 2]);
                    mma16816h(oR[nt], Pl[j], &Vrf[sub * 2]);
                    mma16816h(oI[nt], Ph[j], &Vif[sub * 2]);
                    mma16816h(oI[nt], Pl[j], &Vif[sub * 2]);
                }
            }
        }

        __syncthreads();               // all warps done reading V(kt)
        if (kt + 1 < 16) {
            attn_load_v(sV, Vv, (kt + 1) * 64, tid);
            CP_COMMIT();
        }
    }

    // ---- normalize + packed fp16 AO writes to [b][n][h*64+d] ----
    const float inv0 = 1.0f / l0, inv1 = 1.0f / l1;
    const int b = bh / HEADS, h = bh % HEADS;
    #pragma unroll
    for (int nt = 0; nt < 8; nt++)
        #pragma unroll
        for (int rp = 0; rp < 2; rp++) {
            const int n = q0 + r0 + (lane >> 2) + rp * 8;
            const int d0 = nt * 8 + (lane & 3) * 2;
            const float inv = (rp == 0) ? inv0 : inv1;
            const size_t idx = ((size_t)(b * Nn + n)) * DIMM + h * HD + d0;
            *(uint32_t*)(g_Ar + idx) =
                pack2h(oR[nt][rp * 2] * inv, oR[nt][rp * 2 + 1] * inv);
            *(uint32_t*)(g_Ai + idx) =
                pack2h(oI[nt][rp * 2] * inv, oI[nt][rp * 2 + 1] * inv);
        }
}

// ---------------- launch ------------------------------------------------------
extern "C" void kernel_launch(void* const* d_in, const int* in_sizes, int n_in,
                              void* d_out, int out_size)
{
    const float* xr  = (const float*)d_in[0];
    const float* xi  = (const float*)d_in[1];
    const float* fr  = (const float*)d_in[2];
    const float* fi  = (const float*)d_in[3];
    const float* wqr = (const float*)d_in[4];
    const float* wqi = (const float*)d_in[5];
    const float* bqr = (const float*)d_in[6];
    const float* bqi = (const float*)d_in[7];
    const float* wor = (const float*)d_in[8];
    const float* woi = (const float*)d_in[9];
    const float* bor = (const float*)d_in[10];
    const float* boi = (const float*)d_in[11];
    float* out = (float*)d_out;

    cudaFuncSetAttribute(qkv_mma_kernel,
                         cudaFuncAttributeMaxDynamicSharedMemorySize, GEMM_SMEM);
    cudaFuncSetAttribute(out_mma_kernel,
                         cudaFuncAttributeMaxDynamicSharedMemorySize, GEMM_SMEM);
    cudaFuncSetAttribute(attn_mma_kernel,
                         cudaFuncAttributeMaxDynamicSharedMemorySize, ATTN_SMEM);

    split_all_kernel<<<12288, 256>>>(xr, xi, wqr, wqi, wor, woi);
    qkv_mma_kernel<<<dim3(E3 / 128, Mtot / 64), 128, GEMM_SMEM>>>(bqr, bqi, fr, fi);
    attn_mma_kernel<<<dim3(Nn / 128, Bb * HEADS), 256, ATTN_SMEM>>>();
    out_mma_kernel<<<dim3(DIMM / 128, Mtot / 64), 128, GEMM_SMEM>>>(bor, boi, out);
}

// round 14
// speedup vs baseline: 1.3865x; 1.0454x over previous
#include <cuda_runtime.h>
#include <cuda_bf16.h>
#include <cuda_fp16.h>
#include <stdint.h>
#include <math.h>

#define Bb    2
#define Nn    1024
#define DIMM  1024
#define HEADS 16
#define HD    64
#define Mtot  (Bb * Nn)      // 2048
#define E3    (3 * DIMM)     // 3072

// ---------------- fp16 GEMM operand scratch ----------------------------------
__device__ __half g_Xr[Mtot * DIMM], g_Xi[Mtot * DIMM];           // A hi only
__device__ __half g_Wqr_h[E3 * DIMM],  g_Wqr_l[E3 * DIMM];
__device__ __half g_Wqi_h[E3 * DIMM],  g_Wqi_l[E3 * DIMM];
__device__ __half g_Wor_h[DIMM * DIMM], g_Wor_l[DIMM * DIMM];
__device__ __half g_Woi_h[DIMM * DIMM], g_Woi_l[DIMM * DIMM];
__device__ __half g_Ar[Mtot * DIMM], g_Ai[Mtot * DIMM];           // AO hi only

// Q/K bf16 hi/lo (+ Karatsuba sum/diff), V fp16; layout [b*H + h][d][n]
#define QKV_SZ (Bb * HEADS * Nn * HD)
__device__ __nv_bfloat16 g_Qrh[QKV_SZ], g_Qrl[QKV_SZ], g_Qih[QKV_SZ], g_Qil[QKV_SZ];
__device__ __nv_bfloat16 g_Qsh[QKV_SZ], g_Qsl[QKV_SZ];            // Qs = Qr + Qi
__device__ __nv_bfloat16 g_Krh[QKV_SZ], g_Krl[QKV_SZ], g_Kih[QKV_SZ], g_Kil[QKV_SZ];
__device__ __nv_bfloat16 g_Kdh[QKV_SZ], g_Kdl[QKV_SZ];            // Kd = Kr - Ki
__device__ __half g_Vr[QKV_SZ], g_Vi[QKV_SZ];                     // fp16 single

// ---------------- helpers ----------------------------------------------------
__device__ __forceinline__ uint32_t smem_u32(const void* p) {
    uint32_t a;
    asm("{ .reg .u64 t; cvta.to.shared.u64 t, %1; cvt.u32.u64 %0, t; }"
        : "=r"(a) : "l"(p));
    return a;
}

__device__ __forceinline__ float sqrt_approx(float x) {
    float r;
    asm("sqrt.approx.f32 %0, %1;" : "=f"(r) : "f"(x));
    return r;
}

#define CP16(dst, src) \
    asm volatile("cp.async.cg.shared.global [%0], [%1], 16;" \
                 :: "r"((uint32_t)(dst)), "l"(src) : "memory")
#define CP_COMMIT() asm volatile("cp.async.commit_group;" ::: "memory")
#define CP_WAIT(n)  asm volatile("cp.async.wait_group %0;" :: "n"(n) : "memory")

__device__ __forceinline__ void ldm_x4(uint32_t* r, uint32_t addr) {
    asm volatile("ldmatrix.sync.aligned.m8n8.x4.shared.b16 {%0,%1,%2,%3}, [%4];"
        : "=r"(r[0]), "=r"(r[1]), "=r"(r[2]), "=r"(r[3]) : "r"(addr));
}

__device__ __forceinline__ void ldm_x4_t(uint32_t* r, uint32_t addr) {
    asm volatile("ldmatrix.sync.aligned.m8n8.x4.trans.shared.b16 {%0,%1,%2,%3}, [%4];"
        : "=r"(r[0]), "=r"(r[1]), "=r"(r[2]), "=r"(r[3]) : "r"(addr));
}

// bf16 mma (attention QK)
__device__ __forceinline__ void mma16816(float* c, const uint32_t* a, const uint32_t* b) {
    asm volatile("mma.sync.aligned.m16n8k16.row.col.f32.bf16.bf16.f32 "
        "{%0,%1,%2,%3}, {%4,%5,%6,%7}, {%8,%9}, {%0,%1,%2,%3};"
        : "+f"(c[0]), "+f"(c[1]), "+f"(c[2]), "+f"(c[3])
        : "r"(a[0]), "r"(a[1]), "r"(a[2]), "r"(a[3]), "r"(b[0]), "r"(b[1]));
}

// fp16 mma (GEMMs + attention PV)
__device__ __forceinline__ void mma16816h(float* c, const uint32_t* a, const uint32_t* b) {
    asm volatile("mma.sync.aligned.m16n8k16.row.col.f32.f16.f16.f32 "
        "{%0,%1,%2,%3}, {%4,%5,%6,%7}, {%8,%9}, {%0,%1,%2,%3};"
        : "+f"(c[0]), "+f"(c[1]), "+f"(c[2]), "+f"(c[3])
        : "r"(a[0]), "r"(a[1]), "r"(a[2]), "r"(a[3]), "r"(b[0]), "r"(b[1]));
}

__device__ __forceinline__ void split2(float a, float b, uint32_t& hi, uint32_t& lo) {
    __nv_bfloat16 ah = __float2bfloat16(a), bh = __float2bfloat16(b);
    float ar = a - __bfloat162float(ah), br = b - __bfloat162float(bh);
    __nv_bfloat162 h; h.x = ah; h.y = bh;
    __nv_bfloat162 l; l.x = __float2bfloat16(ar); l.y = __float2bfloat16(br);
    hi = *(uint32_t*)&h;
    lo = *(uint32_t*)&l;
}

__device__ __forceinline__ void split2h(float a, float b, uint32_t& hi, uint32_t& lo) {
    __half ah = __float2half_rn(a), bh = __float2half_rn(b);
    float ar = a - __half2float(ah), br = b - __half2float(bh);
    __half2 h = __halves2half2(ah, bh);
    __half2 l = __halves2half2(__float2half_rn(ar), __float2half_rn(br));
    hi = *(uint32_t*)&h;
    lo = *(uint32_t*)&l;
}

__device__ __forceinline__ uint32_t pack2h(float a, float b) {
    __half2 h = __halves2half2(__float2half_rn(a), __float2half_rn(b));
    return *(uint32_t*)&h;
}

// ---------------- combined input split kernel --------------------------------
__global__ void __launch_bounds__(256) split_all_kernel(
    const float* __restrict__ xr,  const float* __restrict__ xi,
    const float* __restrict__ wqr, const float* __restrict__ wqi,
    const float* __restrict__ wor, const float* __restrict__ woi)
{
    const int blk = blockIdx.x;
    const float* src; __half *hi, *lo = nullptr; int off;
    if      (blk <  2048) { src = xr;  hi = g_Xr; off = blk; }
    else if (blk <  4096) { src = xi;  hi = g_Xi; off = blk - 2048; }
    else if (blk <  7168) { src = wqr; hi = g_Wqr_h; lo = g_Wqr_l; off = blk - 4096; }
    else if (blk < 10240) { src = wqi; hi = g_Wqi_h; lo = g_Wqi_l; off = blk - 7168; }
    else if (blk < 11264) { src = wor; hi = g_Wor_h; lo = g_Wor_l; off = blk - 10240; }
    else                  { src = woi; hi = g_Woi_h; lo = g_Woi_l; off = blk - 11264; }
    const int i = (off * 256 + threadIdx.x) * 4;
    float4 x = *(const float4*)(src + i);
    if (lo) {
        uint32_t h01, l01, h23, l23;
        split2h(x.x, x.y, h01, l01);
        split2h(x.z, x.w, h23, l23);
        *(uint2*)(hi + i) = make_uint2(h01, h23);
        *(uint2*)(lo + i) = make_uint2(l01, l23);
    } else {
        *(uint2*)(hi + i) = make_uint2(pack2h(x.x, x.y), pack2h(x.z, x.w));
    }
}

// ---------------- fp16 2-term complex GEMM core ------------------------------
#define STG 51200
#define GEMM_SMEM (2 * STG)
#define NCHUNK (DIMM / 32)

__device__ __forceinline__ void stage_load(uint32_t sA,
    const __half* const* Av, const __half* const* Bv,
    int m0, int e0, int k0, int tid)
{
    #pragma unroll
    for (int v = 0; v < 2; v++) {
        const __half* srcA = Av[v] + (size_t)m0 * DIMM + k0;
        uint32_t dstA = sA + v * 5120u;
        #pragma unroll
        for (int t = 0; t < 2; t++) {
            int idx = tid + t * 128;
            int r = idx >> 2, c = idx & 3;
            CP16(dstA + r * 80 + c * 16, srcA + (size_t)r * DIMM + c * 8);
        }
    }
    #pragma unroll
    for (int v = 0; v < 4; v++) {
        const __half* srcB = Bv[v] + (size_t)e0 * DIMM + k0;
        uint32_t dstB = sA + 10240u + v * 10240u;
        #pragma unroll
        for (int t = 0; t < 4; t++) {
            int idx = tid + t * 128;
            int r = idx >> 2, c = idx & 3;
            CP16(dstB + r * 80 + c * 16, srcB + (size_t)r * DIMM + c * 8);
        }
    }
}

__device__ __forceinline__ void gemm_compute(uint32_t ss, int lane, int wm, int wn,
    float accR[2][8][4], float accI[2][8][4])
{
    const uint32_t aRow = (uint32_t)(lane & 15);
    const uint32_t aSel = (uint32_t)(lane >> 4);
    const uint32_t nl   = (uint32_t)((lane & 7) + ((lane >> 4) << 3));
    const uint32_t ksel = (uint32_t)((lane >> 3) & 1);

    #pragma unroll
    for (int ks = 0; ks < 2; ks++) {
        uint32_t Ar[2][4], Ai[2][4], nAi[2][4];
        #pragma unroll
        for (int mf = 0; mf < 2; mf++) {
            uint32_t addr = ss + (wm * 32 + mf * 16 + aRow) * 80u
                            + aSel * 16u + ks * 32u;
            ldm_x4(Ar[mf], addr);
            ldm_x4(Ai[mf], addr + 5120u);
            #pragma unroll
            for (int q = 0; q < 4; q++) nAi[mf][q] = Ai[mf][q] ^ 0x80008000u;
        }
        #pragma unroll
        for (int h = 0; h < 4; h++) {
            uint32_t Bf[4][4];
            const uint32_t ba = ss + 10240u
                + (wn * 64 + h * 16 + nl) * 80u + ksel * 16u + ks * 32u;
            #pragma unroll
            for (int v = 0; v < 4; v++) ldm_x4(Bf[v], ba + v * 10240u);
            #pragma unroll
            for (int mf = 0; mf < 2; mf++)
                #pragma unroll
                for (int sub = 0; sub < 2; sub++) {
                    const int nf = h * 2 + sub;
                    const uint32_t* Brh = &Bf[0][sub * 2];
                    const uint32_t* Brl = &Bf[1][sub * 2];
                    const uint32_t* Bih = &Bf[2][sub * 2];
                    const uint32_t* Bil = &Bf[3][sub * 2];
                    float* cr = accR[mf][nf];
                    float* ci = accI[mf][nf];
                    mma16816h(cr, Ar[mf],  Brh);
                    mma16816h(cr, Ar[mf],  Brl);
                    mma16816h(cr, nAi[mf], Bih);
                    mma16816h(cr, nAi[mf], Bil);
                    mma16816h(ci, Ar[mf],  Bih);
                    mma16816h(ci, Ar[mf],  Bil);
                    mma16816h(ci, Ai[mf],  Brh);
                    mma16816h(ci, Ai[mf],  Brl);
                }
        }
    }
}

// ---------------- qkv GEMM: epilogue writes Karatsuba operand sets -----------
__global__ void __launch_bounds__(128, 2) qkv_mma_kernel(
    const float* __restrict__ br, const float* __restrict__ bi,
    const float* __restrict__ fr, const float* __restrict__ fi)
{
    extern __shared__ char smrw[];
    const uint32_t sb = smem_u32(smrw);
    const int tid = threadIdx.x, lane = tid & 31, wid = tid >> 5;
    const int wm = wid >> 1, wn = wid & 1;
    const int e0 = blockIdx.x * 128, m0 = blockIdx.y * 64;

    const __half* Av[2] = {g_Xr, g_Xi};
    const __half* Bv[4] = {g_Wqr_h, g_Wqr_l, g_Wqi_h, g_Wqi_l};

    float accR[2][8][4] = {}, accI[2][8][4] = {};

    stage_load(sb, Av, Bv, m0, e0, 0, tid);
    CP_COMMIT();

    #pragma unroll 1
    for (int c = 0; c < NCHUNK; c++) {
        const int s = c & 1;
        if (c + 1 < NCHUNK) {
            stage_load(sb + (s ^ 1) * STG, Av, Bv, m0, e0, (c + 1) * 32, tid);
            CP_COMMIT();
            CP_WAIT(1);
        } else {
            CP_WAIT(0);
        }
        __syncthreads();
        gemm_compute(sb + s * STG, lane, wm, wn, accR, accI);
        __syncthreads();
    }

    // ---- stage accumulators to smem as [e 128][m pitch 68] fp32 ----
    float* smr = (float*)smrw;
    float* smi = smr + 128 * 68;
    #pragma unroll
    for (int mf = 0; mf < 2; mf++)
        #pragma unroll
        for (int nf = 0; nf < 8; nf++)
            #pragma unroll
            for (int rp = 0; rp < 2; rp++)
                #pragma unroll
                for (int cp = 0; cp < 2; cp++) {
                    const int el = wn * 64 + nf * 8 + (lane & 3) * 2 + cp;
                    const int ml = wm * 32 + mf * 16 + (lane >> 2) + rp * 8;
                    smr[el * 68 + ml] = accR[mf][nf][rp * 2 + cp];
                    smi[el * 68 + ml] = accI[mf][nf][rp * 2 + cp];
                }
    __syncthreads();

    // ---- each thread: one e-column, packed n-run stores ----
    const int el = tid;
    const int e = e0 + el;
    const int h = e / 192, rem = e % 192;
    const int d = rem / 3, which = rem % 3;
    const float bre = br[e], bie = bi[e];
    const int b = m0 >> 10, n0 = m0 & 1023;
    const int bh = b * HEADS + h;
    const size_t dbase = (size_t)(bh * HD + d) * Nn + n0;
    const float* smr_e = smr + el * 68;
    const float* smi_e = smi + el * 68;

    __nv_bfloat16 *dRh, *dRl, *dIh, *dIl, *dSh, *dSl;
    float sgn = 1.f;
    if (which == 0) {
        dRh = g_Qrh; dRl = g_Qrl; dIh = g_Qih; dIl = g_Qil;
        dSh = g_Qsh; dSl = g_Qsl;
    } else {
        dRh = g_Krh; dRl = g_Krl; dIh = g_Kih; dIl = g_Kil;
        dSh = g_Kdh; dSl = g_Kdl; sgn = -1.f;
    }

    #pragma unroll 1
    for (int mc = 0; mc < 16; mc++) {
        float4 srv = *(const float4*)(smr_e + mc * 4);
        float4 siv = *(const float4*)(smi_e + mc * 4);
        float vr[4] = {srv.x + bre, srv.y + bre, srv.z + bre, srv.w + bre};
        float vi[4] = {siv.x + bie, siv.y + bie, siv.z + bie, siv.w + bie};
        if (which == 2) {
            *(uint2*)(g_Vr + dbase + mc * 4) =
                make_uint2(pack2h(vr[0], vr[1]), pack2h(vr[2], vr[3]));
            *(uint2*)(g_Vi + dbase + mc * 4) =
                make_uint2(pack2h(vi[0], vi[1]), pack2h(vi[2], vi[3]));
        } else {
            float ss[4];
            #pragma unroll
            for (int j = 0; j < 4; j++) {
                const int n = n0 + mc * 4 + j;
                const float frv = fr[n * HD + d], fiv = fi[n * HD + d];
                const float rr = vr[j] * frv - vi[j] * fiv;
                vi[j] = vr[j] * fiv + vi[j] * frv;
                vr[j] = rr;
                ss[j] = vr[j] + sgn * vi[j];
            }
            uint32_t h01, l01, h23, l23;
            split2(vr[0], vr[1], h01, l01);
            split2(vr[2], vr[3], h23, l23);
            *(uint2*)(dRh + dbase + mc * 4) = make_uint2(h01, h23);
            *(uint2*)(dRl + dbase + mc * 4) = make_uint2(l01, l23);
            split2(vi[0], vi[1], h01, l01);
            split2(vi[2], vi[3], h23, l23);
            *(uint2*)(dIh + dbase + mc * 4) = make_uint2(h01, h23);
            *(uint2*)(dIl + dbase + mc * 4) = make_uint2(l01, l23);
            split2(ss[0], ss[1], h01, l01);
            split2(ss[2], ss[3], h23, l23);
            *(uint2*)(dSh + dbase + mc * 4) = make_uint2(h01, h23);
            *(uint2*)(dSl + dbase + mc * 4) = make_uint2(l01, l23);
        }
    }
}

// ---------------- output GEMM ------------------------------------------------
__global__ void __launch_bounds__(128, 2) out_mma_kernel(
    const float* __restrict__ br, const float* __restrict__ bi,
    float* __restrict__ out)
{
    extern __shared__ char smrw[];
    const uint32_t sb = smem_u32(smrw);
    const int tid = threadIdx.x, lane = tid & 31, wid = tid >> 5;
    const int wm = wid >> 1, wn = wid & 1;
    const int e0 = blockIdx.x * 128, m0 = blockIdx.y * 64;

    const __half* Av[2] = {g_Ar, g_Ai};
    const __half* Bv[4] = {g_Wor_h, g_Wor_l, g_Woi_h, g_Woi_l};

    float accR[2][8][4] = {}, accI[2][8][4] = {};

    stage_load(sb, Av, Bv, m0, e0, 0, tid);
    CP_COMMIT();

    #pragma unroll 1
    for (int c = 0; c < NCHUNK; c++) {
        const int s = c & 1;
        if (c + 1 < NCHUNK) {
            stage_load(sb + (s ^ 1) * STG, Av, Bv, m0, e0, (c + 1) * 32, tid);
            CP_COMMIT();
            CP_WAIT(1);
        } else {
            CP_WAIT(0);
        }
        __syncthreads();
        gemm_compute(sb + s * STG, lane, wm, wn, accR, accI);
        __syncthreads();
    }

    #pragma unroll
    for (int mf = 0; mf < 2; mf++)
        #pragma unroll
        for (int nf = 0; nf < 8; nf++)
            #pragma unroll
            for (int rp = 0; rp < 2; rp++) {
                const int m = m0 + wm * 32 + mf * 16 + (lane >> 2) + rp * 8;
                const int e = e0 + wn * 64 + nf * 8 + (lane & 3) * 2;
                float2 vr = make_float2(accR[mf][nf][rp * 2] + br[e],
                                        accR[mf][nf][rp * 2 + 1] + br[e + 1]);
                float2 vi = make_float2(accI[mf][nf][rp * 2] + bi[e],
                                        accI[mf][nf][rp * 2 + 1] + bi[e + 1]);
                *(float2*)&out[(size_t)m * DIMM + e] = vr;
                *(float2*)&out[(size_t)Mtot * DIMM + (size_t)m * DIMM + e] = vi;
            }
}

// ---------------- flash attention: Karatsuba QK + fp16 PV --------------------
#define PCHQ 272
#define VQ   17408
#define PCHK 144
#define VKV  9216
#define AK_OFF (6 * VQ)                 // 104448
#define AV_OFF (AK_OFF + 6 * VKV)       // 159744
#define ATTN_SMEM (AV_OFF + 2 * VKV)    // 178176

__device__ __forceinline__ void attn_load_k(uint32_t sK,
    const __nv_bfloat16* const* Kv, int k0, int tid)
{
    #pragma unroll
    for (int v = 0; v < 6; v++)
        #pragma unroll
        for (int t = 0; t < 2; t++) {
            int i = tid + t * 256;
            int r = i >> 3, c = i & 7;
            CP16(sK + v * VKV + r * PCHK + c * 16,
                 Kv[v] + (size_t)r * Nn + k0 + c * 8);
        }
}

__device__ __forceinline__ void attn_load_v(uint32_t sV,
    const __half* const* Vv, int k0, int tid)
{
    #pragma unroll
    for (int v = 0; v < 2; v++)
        #pragma unroll
        for (int t = 0; t < 2; t++) {
            int i = tid + t * 256;
            int r = i >> 3, c = i & 7;
            CP16(sV + v * VKV + r * PCHK + c * 16,
                 Vv[v] + (size_t)r * Nn + k0 + c * 8);
        }
}

__global__ void __launch_bounds__(256, 1) attn_mma_kernel()
{
    extern __shared__ char smrw[];
    const uint32_t sb = smem_u32(smrw);
    const int tid = threadIdx.x, lane = tid & 31, wid = tid >> 5;
    const int bh = blockIdx.y, q0 = blockIdx.x * 128;
    const size_t base = (size_t)bh * Nn * HD;

    const __nv_bfloat16* Qv[6] = {g_Qrh + base, g_Qrl + base, g_Qih + base,
                                  g_Qil + base, g_Qsh + base, g_Qsl + base};
    const __nv_bfloat16* Kv[6] = {g_Krh + base, g_Krl + base, g_Kih + base,
                                  g_Kil + base, g_Kdh + base, g_Kdl + base};
    const __half* Vv[2] = {g_Vr + base, g_Vi + base};

    #pragma unroll
    for (int v = 0; v < 6; v++)
        #pragma unroll
        for (int t = 0; t < 4; t++) {
            int i = tid + t * 256;
            int r = i >> 4, c = i & 15;
            CP16(sb + v * VQ + r * PCHQ + c * 16, Qv[v] + (size_t)r * Nn + q0 + c * 8);
        }
    attn_load_k(sb + AK_OFF, Kv, 0, tid);
    CP_COMMIT();
    attn_load_v(sb + AV_OFF, Vv, 0, tid);
    CP_COMMIT();

    float oR[8][4] = {}, oI[8][4] = {};
    float m0 = -1e30f, m1 = -1e30f, l0 = 0.f, l1 = 0.f;
    const int r0 = wid * 16;
    const uint32_t sK = sb + AK_OFF;
    const uint32_t sV = sb + AV_OFF;

    #pragma unroll 1
    for (int kt = 0; kt < 16; kt++) {
        CP_WAIT(1);
        __syncthreads();

        // ---- Karatsuba S = Q . conj(K): t1=QrKr, t2=QiKi, t3=Qs*Kd ----
        float t1[8][4] = {}, t2[8][4] = {}, t3[8][4] = {};
        #pragma unroll
        for (int ks = 0; ks < 4; ks++) {
            uint32_t Qf[6][4];
            const uint32_t qa = sb
                + (ks * 16 + (lane & 7) + ((lane >> 4) & 1) * 8) * PCHQ
                + (r0 + ((lane >> 3) & 1) * 8) * 2;
            #pragma unroll
            for (int v = 0; v < 6; v++) ldm_x4_t(Qf[v], qa + v * VQ);
            #pragma unroll
            for (int np = 0; np < 4; np++) {
                uint32_t Kf[6][4];
                const uint32_t ka = sK
                    + (ks * 16 + (lane & 7) + ((lane >> 3) & 1) * 8) * PCHK
                    + (np * 16 + ((lane >> 4) & 1) * 8) * 2;
                #pragma unroll
                for (int v = 0; v < 6; v++) ldm_x4_t(Kf[v], ka + v * VKV);
                #pragma unroll
                for (int sub = 0; sub < 2; sub++) {
                    const int nt = np * 2 + sub;
                    const uint32_t* Krh = &Kf[0][sub * 2];
                    const uint32_t* Krl = &Kf[1][sub * 2];
                    const uint32_t* Kih = &Kf[2][sub * 2];
                    const uint32_t* Kil = &Kf[3][sub * 2];
                    const uint32_t* Kdh = &Kf[4][sub * 2];
                    const uint32_t* Kdl = &Kf[5][sub * 2];
                    mma16816(t1[nt], Qf[0], Krh);
                    mma16816(t1[nt], Qf[0], Krl);
                    mma16816(t1[nt], Qf[1], Krh);
                    mma16816(t2[nt], Qf[2], Kih);
                    mma16816(t2[nt], Qf[2], Kil);
                    mma16816(t2[nt], Qf[3], Kih);
                    mma16816(t3[nt], Qf[4], Kdh);
                    mma16816(t3[nt], Qf[4], Kdl);
                    mma16816(t3[nt], Qf[5], Kdh);
                }
            }
        }

        __syncthreads();
        if (kt + 1 < 16) {
            attn_load_k(sK, Kv, (kt + 1) * 64, tid);
            CP_COMMIT();
        }

        // ---- recombine + scaled abs (approx sqrt): reuse t1 as P ----
        float vm0 = -1e30f, vm1 = -1e30f;
        #pragma unroll
        for (int nt = 0; nt < 8; nt++)
            #pragma unroll
            for (int p = 0; p < 4; p++) {
                const float re = t1[nt][p] + t2[nt][p];
                const float im = t3[nt][p] - t1[nt][p] + t2[nt][p];
                const float v = 0.125f * sqrt_approx(re * re + im * im);
                t1[nt][p] = v;
                if (p < 2) vm0 = fmaxf(vm0, v); else vm1 = fmaxf(vm1, v);
            }
        vm0 = fmaxf(vm0, __shfl_xor_sync(0xffffffffu, vm0, 1));
        vm0 = fmaxf(vm0, __shfl_xor_sync(0xffffffffu, vm0, 2));
        vm1 = fmaxf(vm1, __shfl_xor_sync(0xffffffffu, vm1, 1));
        vm1 = fmaxf(vm1, __shfl_xor_sync(0xffffffffu, vm1, 2));
        const float mn0 = fmaxf(m0, vm0), mn1 = fmaxf(m1, vm1);
        const float a0 = __expf(m0 - mn0), a1 = __expf(m1 - mn1);
        m0 = mn0; m1 = mn1;
        #pragma unroll
        for (int nt = 0; nt < 8; nt++)
            #pragma unroll
            for (int p = 0; p < 4; p++) {
                const float al = (p < 2) ? a0 : a1;
                oR[nt][p] *= al;
                oI[nt][p] *= al;
            }
        float s0 = 0.f, s1 = 0.f;
        #pragma unroll
        for (int nt = 0; nt < 8; nt++)
            #pragma unroll
            for (int p = 0; p < 4; p++) {
                const float pv = __expf(t1[nt][p] - ((p < 2) ? mn0 : mn1));
                t1[nt][p] = pv;
                if (p < 2) s0 += pv; else s1 += pv;
            }
        s0 += __shfl_xor_sync(0xffffffffu, s0, 1);
        s0 += __shfl_xor_sync(0xffffffffu, s0, 2);
        s1 += __shfl_xor_sync(0xffffffffu, s1, 1);
        s1 += __shfl_xor_sync(0xffffffffu, s1, 2);
        l0 = l0 * a0 + s0;
        l1 = l1 * a1 + s1;

        uint32_t Ph[4][4], Pl[4][4];
        #pragma unroll
        for (int j = 0; j < 4; j++) {
            const int u0 = 2 * j, u1 = 2 * j + 1;
            split2h(t1[u0][0], t1[u0][1], Ph[j][0], Pl[j][0]);
            split2h(t1[u0][2], t1[u0][3], Ph[j][1], Pl[j][1]);
            split2h(t1[u1][0], t1[u1][1], Ph[j][2], Pl[j][2]);
            split2h(t1[u1][2], t1[u1][3], Ph[j][3], Pl[j][3]);
        }

        if (kt < 15) { CP_WAIT(1); } else { CP_WAIT(0); }
        __syncthreads();

        #pragma unroll
        for (int j = 0; j < 4; j++) {
            #pragma unroll
            for (int g = 0; g < 4; g++) {
                uint32_t Vrf[4], Vif[4];
                const uint32_t va = sV
                    + (g * 16 + (lane & 7) + ((lane >> 4) & 1) * 8) * PCHK
                    + j * 32 + ((lane >> 3) & 1) * 16;
                ldm_x4(Vrf, va);
                ldm_x4(Vif, va + VKV);
                #pragma unroll
                for (int sub = 0; sub < 2; sub++) {
                    const int nt = g * 2 + sub;
                    mma16816h(oR[nt], Ph[j], &Vrf[sub * 2]);
                    mma16816h(oR[nt], Pl[j], &Vrf[sub * 2]);
                    mma16816h(oI[nt], Ph[j], &Vif[sub * 2]);
                    mma16816h(oI[nt], Pl[j], &Vif[sub * 2]);
                }
            }
        }

        __syncthreads();
        if (kt + 1 < 16) {
            attn_load_v(sV, Vv, (kt + 1) * 64, tid);
            CP_COMMIT();
        }
    }

    const float inv0 = 1.0f / l0, inv1 = 1.0f / l1;
    const int b = bh / HEADS, h = bh % HEADS;
    #pragma unroll
    for (int nt = 0; nt < 8; nt++)
        #pragma unroll
        for (int rp = 0; rp < 2; rp++) {
            const int n = q0 + r0 + (lane >> 2) + rp * 8;
            const int d0 = nt * 8 + (lane & 3) * 2;
            const float inv = (rp == 0) ? inv0 : inv1;
            const size_t idx = ((size_t)(b * Nn + n)) * DIMM + h * HD + d0;
            *(uint32_t*)(g_Ar + idx) =
                pack2h(oR[nt][rp * 2] * inv, oR[nt][rp * 2 + 1] * inv);
            *(uint32_t*)(g_Ai + idx) =
                pack2h(oI[nt][rp * 2] * inv, oI[nt][rp * 2 + 1] * inv);
        }
}

// ---------------- launch ------------------------------------------------------
extern "C" void kernel_launch(void* const* d_in, const int* in_sizes, int n_in,
                              void* d_out, int out_size)
{
    const float* xr  = (const float*)d_in[0];
    const float* xi  = (const float*)d_in[1];
    const float* fr  = (const float*)d_in[2];
    const float* fi  = (const float*)d_in[3];
    const float* wqr = (const float*)d_in[4];
    const float* wqi = (const float*)d_in[5];
    const float* bqr = (const float*)d_in[6];
    const float* bqi = (const float*)d_in[7];
    const float* wor = (const float*)d_in[8];
    const float* woi = (const float*)d_in[9];
    const float* bor = (const float*)d_in[10];
    const float* boi = (const float*)d_in[11];
    float* out = (float*)d_out;

    cudaFuncSetAttribute(qkv_mma_kernel,
                         cudaFuncAttributeMaxDynamicSharedMemorySize, GEMM_SMEM);
    cudaFuncSetAttribute(out_mma_kernel,
                         cudaFuncAttributeMaxDynamicSharedMemorySize, GEMM_SMEM);
    cudaFuncSetAttribute(attn_mma_kernel,
                         cudaFuncAttributeMaxDynamicSharedMemorySize, ATTN_SMEM);

    split_all_kernel<<<12288, 256>>>(xr, xi, wqr, wqi, wor, woi);
    qkv_mma_kernel<<<dim3(E3 / 128, Mtot / 64), 128, GEMM_SMEM>>>(bqr, bqi, fr, fi);
    attn_mma_kernel<<<dim3(Nn / 128, Bb * HEADS), 256, ATTN_SMEM>>>();
    out_mma_kernel<<<dim3(DIMM / 128, Mtot / 64), 128, GEMM_SMEM>>>(bor, boi, out);
}

// round 16
// speedup vs baseline: 1.3953x; 1.0063x over previous
#include <cuda_runtime.h>
#include <cuda_bf16.h>
#include <cuda_fp16.h>
#include <stdint.h>
#include <math.h>

#define Bb    2
#define Nn    1024
#define DIMM  1024
#define HEADS 16
#define HD    64
#define Mtot  (Bb * Nn)      // 2048
#define E3    (3 * DIMM)     // 3072

// ---------------- fp16 GEMM operand scratch ----------------------------------
__device__ __half g_Xr[Mtot * DIMM], g_Xi[Mtot * DIMM];           // A hi only
__device__ __half g_Wqr_h[E3 * DIMM],  g_Wqr_l[E3 * DIMM];
__device__ __half g_Wqi_h[E3 * DIMM],  g_Wqi_l[E3 * DIMM];
__device__ __half g_Wor_h[DIMM * DIMM], g_Wor_l[DIMM * DIMM];
__device__ __half g_Woi_h[DIMM * DIMM], g_Woi_l[DIMM * DIMM];
__device__ __half g_Ar[Mtot * DIMM], g_Ai[Mtot * DIMM];           // AO hi only

// Q/K bf16 hi/lo (+ Karatsuba sum/diff), V fp16; layout [b*H + h][d][n]
#define QKV_SZ (Bb * HEADS * Nn * HD)
__device__ __nv_bfloat16 g_Qrh[QKV_SZ], g_Qrl[QKV_SZ], g_Qih[QKV_SZ], g_Qil[QKV_SZ];
__device__ __nv_bfloat16 g_Qsh[QKV_SZ], g_Qsl[QKV_SZ];            // Qs = Qr + Qi
__device__ __nv_bfloat16 g_Krh[QKV_SZ], g_Krl[QKV_SZ], g_Kih[QKV_SZ], g_Kil[QKV_SZ];
__device__ __nv_bfloat16 g_Kdh[QKV_SZ], g_Kdl[QKV_SZ];            // Kd = Kr - Ki
__device__ __half g_Vr[QKV_SZ], g_Vi[QKV_SZ];                     // fp16 single

// ---------------- helpers ----------------------------------------------------
__device__ __forceinline__ uint32_t smem_u32(const void* p) {
    uint32_t a;
    asm("{ .reg .u64 t; cvta.to.shared.u64 t, %1; cvt.u32.u64 %0, t; }"
        : "=r"(a) : "l"(p));
    return a;
}

__device__ __forceinline__ float sqrt_approx(float x) {
    float r;
    asm("sqrt.approx.f32 %0, %1;" : "=f"(r) : "f"(x));
    return r;
}

#define CP16(dst, src) \
    asm volatile("cp.async.cg.shared.global [%0], [%1], 16;" \
                 :: "r"((uint32_t)(dst)), "l"(src) : "memory")
#define CP_COMMIT() asm volatile("cp.async.commit_group;" ::: "memory")
#define CP_WAIT(n)  asm volatile("cp.async.wait_group %0;" :: "n"(n) : "memory")

__device__ __forceinline__ void ldm_x4(uint32_t* r, uint32_t addr) {
    asm volatile("ldmatrix.sync.aligned.m8n8.x4.shared.b16 {%0,%1,%2,%3}, [%4];"
        : "=r"(r[0]), "=r"(r[1]), "=r"(r[2]), "=r"(r[3]) : "r"(addr));
}

__device__ __forceinline__ void ldm_x4_t(uint32_t* r, uint32_t addr) {
    asm volatile("ldmatrix.sync.aligned.m8n8.x4.trans.shared.b16 {%0,%1,%2,%3}, [%4];"
        : "=r"(r[0]), "=r"(r[1]), "=r"(r[2]), "=r"(r[3]) : "r"(addr));
}

// bf16 mma (attention QK)
__device__ __forceinline__ void mma16816(float* c, const uint32_t* a, const uint32_t* b) {
    asm volatile("mma.sync.aligned.m16n8k16.row.col.f32.bf16.bf16.f32 "
        "{%0,%1,%2,%3}, {%4,%5,%6,%7}, {%8,%9}, {%0,%1,%2,%3};"
        : "+f"(c[0]), "+f"(c[1]), "+f"(c[2]), "+f"(c[3])
        : "r"(a[0]), "r"(a[1]), "r"(a[2]), "r"(a[3]), "r"(b[0]), "r"(b[1]));
}

// fp16 mma (GEMMs + attention PV)
__device__ __forceinline__ void mma16816h(float* c, const uint32_t* a, const uint32_t* b) {
    asm volatile("mma.sync.aligned.m16n8k16.row.col.f32.f16.f16.f32 "
        "{%0,%1,%2,%3}, {%4,%5,%6,%7}, {%8,%9}, {%0,%1,%2,%3};"
        : "+f"(c[0]), "+f"(c[1]), "+f"(c[2]), "+f"(c[3])
        : "r"(a[0]), "r"(a[1]), "r"(a[2]), "r"(a[3]), "r"(b[0]), "r"(b[1]));
}

__device__ __forceinline__ void split2(float a, float b, uint32_t& hi, uint32_t& lo) {
    __nv_bfloat16 ah = __float2bfloat16(a), bh = __float2bfloat16(b);
    float ar = a - __bfloat162float(ah), br = b - __bfloat162float(bh);
    __nv_bfloat162 h; h.x = ah; h.y = bh;
    __nv_bfloat162 l; l.x = __float2bfloat16(ar); l.y = __float2bfloat16(br);
    hi = *(uint32_t*)&h;
    lo = *(uint32_t*)&l;
}

__device__ __forceinline__ void split2h(float a, float b, uint32_t& hi, uint32_t& lo) {
    __half ah = __float2half_rn(a), bh = __float2half_rn(b);
    float ar = a - __half2float(ah), br = b - __half2float(bh);
    __half2 h = __halves2half2(ah, bh);
    __half2 l = __halves2half2(__float2half_rn(ar), __float2half_rn(br));
    hi = *(uint32_t*)&h;
    lo = *(uint32_t*)&l;
}

__device__ __forceinline__ uint32_t pack2h(float a, float b) {
    __half2 h = __halves2half2(__float2half_rn(a), __float2half_rn(b));
    return *(uint32_t*)&h;
}

// ---------------- combined input split kernel (2x work, uint4 stores) --------
__global__ void __launch_bounds__(256) split_all_kernel(
    const float* __restrict__ xr,  const float* __restrict__ xi,
    const float* __restrict__ wqr, const float* __restrict__ wqi,
    const float* __restrict__ wor, const float* __restrict__ woi)
{
    const int blk = blockIdx.x;
    const float* src; __half *hi, *lo = nullptr; int off;
    if      (blk <  1024) { src = xr;  hi = g_Xr; off = blk; }
    else if (blk <  2048) { src = xi;  hi = g_Xi; off = blk - 1024; }
    else if (blk <  3584) { src = wqr; hi = g_Wqr_h; lo = g_Wqr_l; off = blk - 2048; }
    else if (blk <  5120) { src = wqi; hi = g_Wqi_h; lo = g_Wqi_l; off = blk - 3584; }
    else if (blk <  5632) { src = wor; hi = g_Wor_h; lo = g_Wor_l; off = blk - 5120; }
    else                  { src = woi; hi = g_Woi_h; lo = g_Woi_l; off = blk - 5632; }
    const int i = (off * 256 + threadIdx.x) * 8;
    float4 x0 = *(const float4*)(src + i);
    float4 x1 = *(const float4*)(src + i + 4);
    if (lo) {
        uint32_t h0, l0, h1, l1, h2, l2, h3, l3;
        split2h(x0.x, x0.y, h0, l0);
        split2h(x0.z, x0.w, h1, l1);
        split2h(x1.x, x1.y, h2, l2);
        split2h(x1.z, x1.w, h3, l3);
        *(uint4*)(hi + i) = make_uint4(h0, h1, h2, h3);
        *(uint4*)(lo + i) = make_uint4(l0, l1, l2, l3);
    } else {
        *(uint4*)(hi + i) = make_uint4(pack2h(x0.x, x0.y), pack2h(x0.z, x0.w),
                                       pack2h(x1.x, x1.y), pack2h(x1.z, x1.w));
    }
}

// ---------------- fp16 2-term complex GEMM core ------------------------------
#define STG 51200
#define GEMM_SMEM (2 * STG)
#define NCHUNK (DIMM / 32)

__device__ __forceinline__ void stage_load(uint32_t sA,
    const __half* const* Av, const __half* const* Bv,
    int m0, int e0, int k0, int tid)
{
    #pragma unroll
    for (int v = 0; v < 2; v++) {
        const __half* srcA = Av[v] + (size_t)m0 * DIMM + k0;
        uint32_t dstA = sA + v * 5120u;
        #pragma unroll
        for (int t = 0; t < 2; t++) {
            int idx = tid + t * 128;
            int r = idx >> 2, c = idx & 3;
            CP16(dstA + r * 80 + c * 16, srcA + (size_t)r * DIMM + c * 8);
        }
    }
    #pragma unroll
    for (int v = 0; v < 4; v++) {
        const __half* srcB = Bv[v] + (size_t)e0 * DIMM + k0;
        uint32_t dstB = sA + 10240u + v * 10240u;
        #pragma unroll
        for (int t = 0; t < 4; t++) {
            int idx = tid + t * 128;
            int r = idx >> 2, c = idx & 3;
            CP16(dstB + r * 80 + c * 16, srcB + (size_t)r * DIMM + c * 8);
        }
    }
}

__device__ __forceinline__ void gemm_compute(uint32_t ss, int lane, int wm, int wn,
    float accR[2][8][4], float accI[2][8][4])
{
    const uint32_t aRow = (uint32_t)(lane & 15);
    const uint32_t aSel = (uint32_t)(lane >> 4);
    const uint32_t nl   = (uint32_t)((lane & 7) + ((lane >> 4) << 3));
    const uint32_t ksel = (uint32_t)((lane >> 3) & 1);

    #pragma unroll
    for (int ks = 0; ks < 2; ks++) {
        uint32_t Ar[2][4], Ai[2][4], nAi[2][4];
        #pragma unroll
        for (int mf = 0; mf < 2; mf++) {
            uint32_t addr = ss + (wm * 32 + mf * 16 + aRow) * 80u
                            + aSel * 16u + ks * 32u;
            ldm_x4(Ar[mf], addr);
            ldm_x4(Ai[mf], addr + 5120u);
            #pragma unroll
            for (int q = 0; q < 4; q++) nAi[mf][q] = Ai[mf][q] ^ 0x80008000u;
        }
        #pragma unroll
        for (int h = 0; h < 4; h++) {
            uint32_t Bf[4][4];
            const uint32_t ba = ss + 10240u
                + (wn * 64 + h * 16 + nl) * 80u + ksel * 16u + ks * 32u;
            #pragma unroll
            for (int v = 0; v < 4; v++) ldm_x4(Bf[v], ba + v * 10240u);
            #pragma unroll
            for (int mf = 0; mf < 2; mf++)
                #pragma unroll
                for (int sub = 0; sub < 2; sub++) {
                    const int nf = h * 2 + sub;
                    const uint32_t* Brh = &Bf[0][sub * 2];
                    const uint32_t* Brl = &Bf[1][sub * 2];
                    const uint32_t* Bih = &Bf[2][sub * 2];
                    const uint32_t* Bil = &Bf[3][sub * 2];
                    float* cr = accR[mf][nf];
                    float* ci = accI[mf][nf];
                    mma16816h(cr, Ar[mf],  Brh);
                    mma16816h(cr, Ar[mf],  Brl);
                    mma16816h(cr, nAi[mf], Bih);
                    mma16816h(cr, nAi[mf], Bil);
                    mma16816h(ci, Ar[mf],  Bih);
                    mma16816h(ci, Ar[mf],  Bil);
                    mma16816h(ci, Ai[mf],  Brh);
                    mma16816h(ci, Ai[mf],  Brl);
                }
        }
    }
}

// ---------------- qkv GEMM: epilogue writes Karatsuba operand sets -----------
__global__ void __launch_bounds__(128, 2) qkv_mma_kernel(
    const float* __restrict__ br, const float* __restrict__ bi,
    const float* __restrict__ fr, const float* __restrict__ fi)
{
    extern __shared__ char smrw[];
    const uint32_t sb = smem_u32(smrw);
    const int tid = threadIdx.x, lane = tid & 31, wid = tid >> 5;
    const int wm = wid >> 1, wn = wid & 1;
    const int e0 = blockIdx.x * 128, m0 = blockIdx.y * 64;

    const __half* Av[2] = {g_Xr, g_Xi};
    const __half* Bv[4] = {g_Wqr_h, g_Wqr_l, g_Wqi_h, g_Wqi_l};

    float accR[2][8][4] = {}, accI[2][8][4] = {};

    stage_load(sb, Av, Bv, m0, e0, 0, tid);
    CP_COMMIT();

    #pragma unroll 1
    for (int c = 0; c < NCHUNK; c++) {
        const int s = c & 1;
        if (c + 1 < NCHUNK) {
            stage_load(sb + (s ^ 1) * STG, Av, Bv, m0, e0, (c + 1) * 32, tid);
            CP_COMMIT();
            CP_WAIT(1);
        } else {
            CP_WAIT(0);
        }
        __syncthreads();
        gemm_compute(sb + s * STG, lane, wm, wn, accR, accI);
        __syncthreads();
    }

    // ---- stage accumulators to smem as [e 128][m pitch 68] fp32 ----
    float* smr = (float*)smrw;
    float* smi = smr + 128 * 68;
    #pragma unroll
    for (int mf = 0; mf < 2; mf++)
        #pragma unroll
        for (int nf = 0; nf < 8; nf++)
            #pragma unroll
            for (int rp = 0; rp < 2; rp++)
                #pragma unroll
                for (int cp = 0; cp < 2; cp++) {
                    const int el = wn * 64 + nf * 8 + (lane & 3) * 2 + cp;
                    const int ml = wm * 32 + mf * 16 + (lane >> 2) + rp * 8;
                    smr[el * 68 + ml] = accR[mf][nf][rp * 2 + cp];
                    smi[el * 68 + ml] = accI[mf][nf][rp * 2 + cp];
                }
    __syncthreads();

    // ---- each thread: one e-column, packed n-run stores ----
    const int el = tid;
    const int e = e0 + el;
    const int h = e / 192, rem = e % 192;
    const int d = rem / 3, which = rem % 3;
    const float bre = br[e], bie = bi[e];
    const int b = m0 >> 10, n0 = m0 & 1023;
    const int bh = b * HEADS + h;
    const size_t dbase = (size_t)(bh * HD + d) * Nn + n0;
    const float* smr_e = smr + el * 68;
    const float* smi_e = smi + el * 68;

    __nv_bfloat16 *dRh, *dRl, *dIh, *dIl, *dSh, *dSl;
    float sgn = 1.f;
    if (which == 0) {
        dRh = g_Qrh; dRl = g_Qrl; dIh = g_Qih; dIl = g_Qil;
        dSh = g_Qsh; dSl = g_Qsl;
    } else {
        dRh = g_Krh; dRl = g_Krl; dIh = g_Kih; dIl = g_Kil;
        dSh = g_Kdh; dSl = g_Kdl; sgn = -1.f;
    }

    #pragma unroll 1
    for (int mc = 0; mc < 16; mc++) {
        float4 srv = *(const float4*)(smr_e + mc * 4);
        float4 siv = *(const float4*)(smi_e + mc * 4);
        float vr[4] = {srv.x + bre, srv.y + bre, srv.z + bre, srv.w + bre};
        float vi[4] = {siv.x + bie, siv.y + bie, siv.z + bie, siv.w + bie};
        if (which == 2) {
            *(uint2*)(g_Vr + dbase + mc * 4) =
                make_uint2(pack2h(vr[0], vr[1]), pack2h(vr[2], vr[3]));
            *(uint2*)(g_Vi + dbase + mc * 4) =
                make_uint2(pack2h(vi[0], vi[1]), pack2h(vi[2], vi[3]));
        } else {
            float ss[4];
            #pragma unroll
            for (int j = 0; j < 4; j++) {
                const int n = n0 + mc * 4 + j;
                const float frv = fr[n * HD + d], fiv = fi[n * HD + d];
                const float rr = vr[j] * frv - vi[j] * fiv;
                vi[j] = vr[j] * fiv + vi[j] * frv;
                vr[j] = rr;
                ss[j] = vr[j] + sgn * vi[j];
            }
            uint32_t h01, l01, h23, l23;
            split2(vr[0], vr[1], h01, l01);
            split2(vr[2], vr[3], h23, l23);
            *(uint2*)(dRh + dbase + mc * 4) = make_uint2(h01, h23);
            *(uint2*)(dRl + dbase + mc * 4) = make_uint2(l01, l23);
            split2(vi[0], vi[1], h01, l01);
            split2(vi[2], vi[3], h23, l23);
            *(uint2*)(dIh + dbase + mc * 4) = make_uint2(h01, h23);
            *(uint2*)(dIl + dbase + mc * 4) = make_uint2(l01, l23);
            split2(ss[0], ss[1], h01, l01);
            split2(ss[2], ss[3], h23, l23);
            *(uint2*)(dSh + dbase + mc * 4) = make_uint2(h01, h23);
            *(uint2*)(dSl + dbase + mc * 4) = make_uint2(l01, l23);
        }
    }
}

// ---------------- output GEMM ------------------------------------------------
__global__ void __launch_bounds__(128, 2) out_mma_kernel(
    const float* __restrict__ br, const float* __restrict__ bi,
    float* __restrict__ out)
{
    extern __shared__ char smrw[];
    const uint32_t sb = smem_u32(smrw);
    const int tid = threadIdx.x, lane = tid & 31, wid = tid >> 5;
    const int wm = wid >> 1, wn = wid & 1;
    const int e0 = blockIdx.x * 128, m0 = blockIdx.y * 64;

    const __half* Av[2] = {g_Ar, g_Ai};
    const __half* Bv[4] = {g_Wor_h, g_Wor_l, g_Woi_h, g_Woi_l};

    float accR[2][8][4] = {}, accI[2][8][4] = {};

    stage_load(sb, Av, Bv, m0, e0, 0, tid);
    CP_COMMIT();

    #pragma unroll 1
    for (int c = 0; c < NCHUNK; c++) {
        const int s = c & 1;
        if (c + 1 < NCHUNK) {
            stage_load(sb + (s ^ 1) * STG, Av, Bv, m0, e0, (c + 1) * 32, tid);
            CP_COMMIT();
            CP_WAIT(1);
        } else {
            CP_WAIT(0);
        }
        __syncthreads();
        gemm_compute(sb + s * STG, lane, wm, wn, accR, accI);
        __syncthreads();
    }

    #pragma unroll
    for (int mf = 0; mf < 2; mf++)
        #pragma unroll
        for (int nf = 0; nf < 8; nf++)
            #pragma unroll
            for (int rp = 0; rp < 2; rp++) {
                const int m = m0 + wm * 32 + mf * 16 + (lane >> 2) + rp * 8;
                const int e = e0 + wn * 64 + nf * 8 + (lane & 3) * 2;
                float2 vr = make_float2(accR[mf][nf][rp * 2] + br[e],
                                        accR[mf][nf][rp * 2 + 1] + br[e + 1]);
                float2 vi = make_float2(accI[mf][nf][rp * 2] + bi[e],
                                        accI[mf][nf][rp * 2 + 1] + bi[e + 1]);
                *(float2*)&out[(size_t)m * DIMM + e] = vr;
                *(float2*)&out[(size_t)Mtot * DIMM + (size_t)m * DIMM + e] = vi;
            }
}

// ---------------- flash attention: Karatsuba QK (bf16) + fp16 PV -------------
#define PCHQ 272
#define VQ   17408
#define PCHK 144
#define VKV  9216
#define AK_OFF (6 * VQ)                 // 104448
#define AV_OFF (AK_OFF + 6 * VKV)       // 159744
#define ATTN_SMEM (AV_OFF + 2 * VKV)    // 178176

__device__ __forceinline__ void attn_load_k(uint32_t sK,
    const __nv_bfloat16* const* Kv, int k0, int tid)
{
    #pragma unroll
    for (int v = 0; v < 6; v++)
        #pragma unroll
        for (int t = 0; t < 2; t++) {
            int i = tid + t * 256;
            int r = i >> 3, c = i & 7;
            CP16(sK + v * VKV + r * PCHK + c * 16,
                 Kv[v] + (size_t)r * Nn + k0 + c * 8);
        }
}

__device__ __forceinline__ void attn_load_v(uint32_t sV,
    const __half* const* Vv, int k0, int tid)
{
    #pragma unroll
    for (int v = 0; v < 2; v++)
        #pragma unroll
        for (int t = 0; t < 2; t++) {
            int i = tid + t * 256;
            int r = i >> 3, c = i & 7;
            CP16(sV + v * VKV + r * PCHK + c * 16,
                 Vv[v] + (size_t)r * Nn + k0 + c * 8);
        }
}

__global__ void __launch_bounds__(256, 1) attn_mma_kernel()
{
    extern __shared__ char smrw[];
    const uint32_t sb = smem_u32(smrw);
    const int tid = threadIdx.x, lane = tid & 31, wid = tid >> 5;
    const int bh = blockIdx.y, q0 = blockIdx.x * 128;
    const size_t base = (size_t)bh * Nn * HD;

    const __nv_bfloat16* Qv[6] = {g_Qrh + base, g_Qrl + base, g_Qih + base,
                                  g_Qil + base, g_Qsh + base, g_Qsl + base};
    const __nv_bfloat16* Kv[6] = {g_Krh + base, g_Krl + base, g_Kih + base,
                                  g_Kil + base, g_Kdh + base, g_Kdl + base};
    const __half* Vv[2] = {g_Vr + base, g_Vi + base};

    #pragma unroll
    for (int v = 0; v < 6; v++)
        #pragma unroll
        for (int t = 0; t < 4; t++) {
            int i = tid + t * 256;
            int r = i >> 4, c = i & 15;
            CP16(sb + v * VQ + r * PCHQ + c * 16, Qv[v] + (size_t)r * Nn + q0 + c * 8);
        }
    attn_load_k(sb + AK_OFF, Kv, 0, tid);
    CP_COMMIT();
    attn_load_v(sb + AV_OFF, Vv, 0, tid);
    CP_COMMIT();

    float oR[8][4] = {}, oI[8][4] = {};
    float m0 = -1e30f, m1 = -1e30f, l0 = 0.f, l1 = 0.f;
    const int r0 = wid * 16;
    const uint32_t sK = sb + AK_OFF;
    const uint32_t sV = sb + AV_OFF;

    #pragma unroll 1
    for (int kt = 0; kt < 16; kt++) {
        CP_WAIT(1);
        __syncthreads();

        // ---- Karatsuba S = Q . conj(K): t1=QrKr, t2=QiKi, t3=Qs*Kd ----
        float t1[8][4] = {}, t2[8][4] = {}, t3[8][4] = {};
        #pragma unroll
        for (int ks = 0; ks < 4; ks++) {
            uint32_t Qf[6][4];
            const uint32_t qa = sb
                + (ks * 16 + (lane & 7) + ((lane >> 4) & 1) * 8) * PCHQ
                + (r0 + ((lane >> 3) & 1) * 8) * 2;
            #pragma unroll
            for (int v = 0; v < 6; v++) ldm_x4_t(Qf[v], qa + v * VQ);
            #pragma unroll
            for (int np = 0; np < 4; np++) {
                uint32_t Kf[6][4];
                const uint32_t ka = sK
                    + (ks * 16 + (lane & 7) + ((lane >> 3) & 1) * 8) * PCHK
                    + (np * 16 + ((lane >> 4) & 1) * 8) * 2;
                #pragma unroll
                for (int v = 0; v < 6; v++) ldm_x4_t(Kf[v], ka + v * VKV);
                #pragma unroll
                for (int sub = 0; sub < 2; sub++) {
                    const int nt = np * 2 + sub;
                    const uint32_t* Krh = &Kf[0][sub * 2];
                    const uint32_t* Krl = &Kf[1][sub * 2];
                    const uint32_t* Kih = &Kf[2][sub * 2];
                    const uint32_t* Kil = &Kf[3][sub * 2];
                    const uint32_t* Kdh = &Kf[4][sub * 2];
                    const uint32_t* Kdl = &Kf[5][sub * 2];
                    mma16816(t1[nt], Qf[0], Krh);
                    mma16816(t1[nt], Qf[0], Krl);
                    mma16816(t1[nt], Qf[1], Krh);
                    mma16816(t2[nt], Qf[2], Kih);
                    mma16816(t2[nt], Qf[2], Kil);
                    mma16816(t2[nt], Qf[3], Kih);
                    mma16816(t3[nt], Qf[4], Kdh);
                    mma16816(t3[nt], Qf[4], Kdl);
                    mma16816(t3[nt], Qf[5], Kdh);
                }
            }
        }

        __syncthreads();
        if (kt + 1 < 16) {
            attn_load_k(sK, Kv, (kt + 1) * 64, tid);
            CP_COMMIT();
        }

        // ---- recombine + scaled abs (approx sqrt): reuse t1 as P ----
        float vm0 = -1e30f, vm1 = -1e30f;
        #pragma unroll
        for (int nt = 0; nt < 8; nt++)
            #pragma unroll
            for (int p = 0; p < 4; p++) {
                const float re = t1[nt][p] + t2[nt][p];
                const float im = t3[nt][p] - t1[nt][p] + t2[nt][p];
                const float v = 0.125f * sqrt_approx(re * re + im * im);
                t1[nt][p] = v;
                if (p < 2) vm0 = fmaxf(vm0, v); else vm1 = fmaxf(vm1, v);
            }
        vm0 = fmaxf(vm0, __shfl_xor_sync(0xffffffffu, vm0, 1));
        vm0 = fmaxf(vm0, __shfl_xor_sync(0xffffffffu, vm0, 2));
        vm1 = fmaxf(vm1, __shfl_xor_sync(0xffffffffu, vm1, 1));
        vm1 = fmaxf(vm1, __shfl_xor_sync(0xffffffffu, vm1, 2));
        const float mn0 = fmaxf(m0, vm0), mn1 = fmaxf(m1, vm1);
        const float a0 = __expf(m0 - mn0), a1 = __expf(m1 - mn1);
        m0 = mn0; m1 = mn1;
        #pragma unroll
        for (int nt = 0; nt < 8; nt++)
            #pragma unroll
            for (int p = 0; p < 4; p++) {
                const float al = (p < 2) ? a0 : a1;
                oR[nt][p] *= al;
                oI[nt][p] *= al;
            }
        float s0 = 0.f, s1 = 0.f;
        #pragma unroll
        for (int nt = 0; nt < 8; nt++)
            #pragma unroll
            for (int p = 0; p < 4; p++) {
                const float pv = __expf(t1[nt][p] - ((p < 2) ? mn0 : mn1));
                t1[nt][p] = pv;
                if (p < 2) s0 += pv; else s1 += pv;
            }
        s0 += __shfl_xor_sync(0xffffffffu, s0, 1);
        s0 += __shfl_xor_sync(0xffffffffu, s0, 2);
        s1 += __shfl_xor_sync(0xffffffffu, s1, 1);
        s1 += __shfl_xor_sync(0xffffffffu, s1, 2);
        l0 = l0 * a0 + s0;
        l1 = l1 * a1 + s1;

        uint32_t Ph[4][4], Pl[4][4];
        #pragma unroll
        for (int j = 0; j < 4; j++) {
            const int u0 = 2 * j, u1 = 2 * j + 1;
            split2h(t1[u0][0], t1[u0][1], Ph[j][0], Pl[j][0]);
            split2h(t1[u0][2], t1[u0][3], Ph[j][1], Pl[j][1]);
            split2h(t1[u1][0], t1[u1][1], Ph[j][2], Pl[j][2]);
            split2h(t1[u1][2], t1[u1][3], Ph[j][3], Pl[j][3]);
        }

        if (kt < 15) { CP_WAIT(1); } else { CP_WAIT(0); }
        __syncthreads();

        #pragma unroll
        for (int j = 0; j < 4; j++) {
            #pragma unroll
            for (int g = 0; g < 4; g++) {
                uint32_t Vrf[4], Vif[4];
                const uint32_t va = sV
                    + (g * 16 + (lane & 7) + ((lane >> 4) & 1) * 8) * PCHK
                    + j * 32 + ((lane >> 3) & 1) * 16;
                ldm_x4(Vrf, va);
                ldm_x4(Vif, va + VKV);
                #pragma unroll
                for (int sub = 0; sub < 2; sub++) {
                    const int nt = g * 2 + sub;
                    mma16816h(oR[nt], Ph[j], &Vrf[sub * 2]);
                    mma16816h(oR[nt], Pl[j], &Vrf[sub * 2]);
                    mma16816h(oI[nt], Ph[j], &Vif[sub * 2]);
                    mma16816h(oI[nt], Pl[j], &Vif[sub * 2]);
                }
            }
        }

        __syncthreads();
        if (kt + 1 < 16) {
            attn_load_v(sV, Vv, (kt + 1) * 64, tid);
            CP_COMMIT();
        }
    }

    const float inv0 = 1.0f / l0, inv1 = 1.0f / l1;
    const int b = bh / HEADS, h = bh % HEADS;
    #pragma unroll
    for (int nt = 0; nt < 8; nt++)
        #pragma unroll
        for (int rp = 0; rp < 2; rp++) {
            const int n = q0 + r0 + (lane >> 2) + rp * 8;
            const int d0 = nt * 8 + (lane & 3) * 2;
            const float inv = (rp == 0) ? inv0 : inv1;
            const size_t idx = ((size_t)(b * Nn + n)) * DIMM + h * HD + d0;
            *(uint32_t*)(g_Ar + idx) =
                pack2h(oR[nt][rp * 2] * inv, oR[nt][rp * 2 + 1] * inv);
            *(uint32_t*)(g_Ai + idx) =
                pack2h(oI[nt][rp * 2] * inv, oI[nt][rp * 2 + 1] * inv);
        }
}

// ---------------- launch ------------------------------------------------------
extern "C" void kernel_launch(void* const* d_in, const int* in_sizes, int n_in,
                              void* d_out, int out_size)
{
    const float* xr  = (const float*)d_in[0];
    const float* xi  = (const float*)d_in[1];
    const float* fr  = (const float*)d_in[2];
    const float* fi  = (const float*)d_in[3];
    const float* wqr = (const float*)d_in[4];
    const float* wqi = (const float*)d_in[5];
    const float* bqr = (const float*)d_in[6];
    const float* bqi = (const float*)d_in[7];
    const float* wor = (const float*)d_in[8];
    const float* woi = (const float*)d_in[9];
    const float* bor = (const float*)d_in[10];
    const float* boi = (const float*)d_in[11];
    float* out = (float*)d_out;

    cudaFuncSetAttribute(qkv_mma_kernel,
                         cudaFuncAttributeMaxDynamicSharedMemorySize, GEMM_SMEM);
    cudaFuncSetAttribute(out_mma_kernel,
                         cudaFuncAttributeMaxDynamicSharedMemorySize, GEMM_SMEM);
    cudaFuncSetAttribute(attn_mma_kernel,
                         cudaFuncAttributeMaxDynamicSharedMemorySize, ATTN_SMEM);

    split_all_kernel<<<6144, 256>>>(xr, xi, wqr, wqi, wor, woi);
    qkv_mma_kernel<<<dim3(E3 / 128, Mtot / 64), 128, GEMM_SMEM>>>(bqr, bqi, fr, fi);
    attn_mma_kernel<<<dim3(Nn / 128, Bb * HEADS), 256, ATTN_SMEM>>>();
    out_mma_kernel<<<dim3(DIMM / 128, Mtot / 64), 128, GEMM_SMEM>>>(bor, boi, out);
}

// round 17
// speedup vs baseline: 1.4266x; 1.0224x over previous
#include <cuda_runtime.h>
#include <cuda_bf16.h>
#include <cuda_fp16.h>
#include <stdint.h>
#include <math.h>

#define Bb    2
#define Nn    1024
#define DIMM  1024
#define HEADS 16
#define HD    64
#define Mtot  (Bb * Nn)      // 2048
#define E3    (3 * DIMM)     // 3072

// ---------------- fp16 GEMM operand scratch ----------------------------------
__device__ __half g_Xr[Mtot * DIMM], g_Xi[Mtot * DIMM];           // A hi only
__device__ __half g_Wqr_h[E3 * DIMM],  g_Wqr_l[E3 * DIMM];
__device__ __half g_Wqi_h[E3 * DIMM],  g_Wqi_l[E3 * DIMM];
__device__ __half g_Wor_h[DIMM * DIMM], g_Wor_l[DIMM * DIMM];
__device__ __half g_Woi_h[DIMM * DIMM], g_Woi_l[DIMM * DIMM];
__device__ __half g_Ar[Mtot * DIMM], g_Ai[Mtot * DIMM];           // AO hi only

// Q/K bf16 hi/lo (+ Karatsuba sum/diff), V fp16; layout [b*H + h][d][n]
#define QKV_SZ (Bb * HEADS * Nn * HD)
__device__ __nv_bfloat16 g_Qrh[QKV_SZ], g_Qrl[QKV_SZ], g_Qih[QKV_SZ], g_Qil[QKV_SZ];
__device__ __nv_bfloat16 g_Qsh[QKV_SZ], g_Qsl[QKV_SZ];            // Qs = Qr + Qi
__device__ __nv_bfloat16 g_Krh[QKV_SZ], g_Krl[QKV_SZ], g_Kih[QKV_SZ], g_Kil[QKV_SZ];
__device__ __nv_bfloat16 g_Kdh[QKV_SZ], g_Kdl[QKV_SZ];            // Kd = Kr - Ki
__device__ __half g_Vr[QKV_SZ], g_Vi[QKV_SZ];                     // fp16 single

// ---------------- helpers ----------------------------------------------------
__device__ __forceinline__ uint32_t smem_u32(const void* p) {
    uint32_t a;
    asm("{ .reg .u64 t; cvta.to.shared.u64 t, %1; cvt.u32.u64 %0, t; }"
        : "=r"(a) : "l"(p));
    return a;
}

__device__ __forceinline__ float sqrt_approx(float x) {
    float r;
    asm("sqrt.approx.f32 %0, %1;" : "=f"(r) : "f"(x));
    return r;
}

#define CP16(dst, src) \
    asm volatile("cp.async.cg.shared.global [%0], [%1], 16;" \
                 :: "r"((uint32_t)(dst)), "l"(src) : "memory")
#define CP_COMMIT() asm volatile("cp.async.commit_group;" ::: "memory")
#define CP_WAIT(n)  asm volatile("cp.async.wait_group %0;" :: "n"(n) : "memory")

__device__ __forceinline__ void ldm_x4(uint32_t* r, uint32_t addr) {
    asm volatile("ldmatrix.sync.aligned.m8n8.x4.shared.b16 {%0,%1,%2,%3}, [%4];"
        : "=r"(r[0]), "=r"(r[1]), "=r"(r[2]), "=r"(r[3]) : "r"(addr));
}

__device__ __forceinline__ void ldm_x4_t(uint32_t* r, uint32_t addr) {
    asm volatile("ldmatrix.sync.aligned.m8n8.x4.trans.shared.b16 {%0,%1,%2,%3}, [%4];"
        : "=r"(r[0]), "=r"(r[1]), "=r"(r[2]), "=r"(r[3]) : "r"(addr));
}

// bf16 mma (attention QK)
__device__ __forceinline__ void mma16816(float* c, const uint32_t* a, const uint32_t* b) {
    asm volatile("mma.sync.aligned.m16n8k16.row.col.f32.bf16.bf16.f32 "
        "{%0,%1,%2,%3}, {%4,%5,%6,%7}, {%8,%9}, {%0,%1,%2,%3};"
        : "+f"(c[0]), "+f"(c[1]), "+f"(c[2]), "+f"(c[3])
        : "r"(a[0]), "r"(a[1]), "r"(a[2]), "r"(a[3]), "r"(b[0]), "r"(b[1]));
}

// fp16 mma (GEMMs + attention PV)
__device__ __forceinline__ void mma16816h(float* c, const uint32_t* a, const uint32_t* b) {
    asm volatile("mma.sync.aligned.m16n8k16.row.col.f32.f16.f16.f32 "
        "{%0,%1,%2,%3}, {%4,%5,%6,%7}, {%8,%9}, {%0,%1,%2,%3};"
        : "+f"(c[0]), "+f"(c[1]), "+f"(c[2]), "+f"(c[3])
        : "r"(a[0]), "r"(a[1]), "r"(a[2]), "r"(a[3]), "r"(b[0]), "r"(b[1]));
}

__device__ __forceinline__ void split2(float a, float b, uint32_t& hi, uint32_t& lo) {
    __nv_bfloat16 ah = __float2bfloat16(a), bh = __float2bfloat16(b);
    float ar = a - __bfloat162float(ah), br = b - __bfloat162float(bh);
    __nv_bfloat162 h; h.x = ah; h.y = bh;
    __nv_bfloat162 l; l.x = __float2bfloat16(ar); l.y = __float2bfloat16(br);
    hi = *(uint32_t*)&h;
    lo = *(uint32_t*)&l;
}

__device__ __forceinline__ void split2h(float a, float b, uint32_t& hi, uint32_t& lo) {
    __half ah = __float2half_rn(a), bh = __float2half_rn(b);
    float ar = a - __half2float(ah), br = b - __half2float(bh);
    __half2 h = __halves2half2(ah, bh);
    __half2 l = __halves2half2(__float2half_rn(ar), __float2half_rn(br));
    hi = *(uint32_t*)&h;
    lo = *(uint32_t*)&l;
}

__device__ __forceinline__ uint32_t pack2h(float a, float b) {
    __half2 h = __halves2half2(__float2half_rn(a), __float2half_rn(b));
    return *(uint32_t*)&h;
}

// ---------------- combined input split kernel (2x work, uint4 stores) --------
__global__ void __launch_bounds__(256) split_all_kernel(
    const float* __restrict__ xr,  const float* __restrict__ xi,
    const float* __restrict__ wqr, const float* __restrict__ wqi,
    const float* __restrict__ wor, const float* __restrict__ woi)
{
    const int blk = blockIdx.x;
    const float* src; __half *hi, *lo = nullptr; int off;
    if      (blk <  1024) { src = xr;  hi = g_Xr; off = blk; }
    else if (blk <  2048) { src = xi;  hi = g_Xi; off = blk - 1024; }
    else if (blk <  3584) { src = wqr; hi = g_Wqr_h; lo = g_Wqr_l; off = blk - 2048; }
    else if (blk <  5120) { src = wqi; hi = g_Wqi_h; lo = g_Wqi_l; off = blk - 3584; }
    else if (blk <  5632) { src = wor; hi = g_Wor_h; lo = g_Wor_l; off = blk - 5120; }
    else                  { src = woi; hi = g_Woi_h; lo = g_Woi_l; off = blk - 5632; }
    const int i = (off * 256 + threadIdx.x) * 8;
    float4 x0 = *(const float4*)(src + i);
    float4 x1 = *(const float4*)(src + i + 4);
    if (lo) {
        uint32_t h0, l0, h1, l1, h2, l2, h3, l3;
        split2h(x0.x, x0.y, h0, l0);
        split2h(x0.z, x0.w, h1, l1);
        split2h(x1.x, x1.y, h2, l2);
        split2h(x1.z, x1.w, h3, l3);
        *(uint4*)(hi + i) = make_uint4(h0, h1, h2, h3);
        *(uint4*)(lo + i) = make_uint4(l0, l1, l2, l3);
    } else {
        *(uint4*)(hi + i) = make_uint4(pack2h(x0.x, x0.y), pack2h(x0.z, x0.w),
                                       pack2h(x1.x, x1.y), pack2h(x1.z, x1.w));
    }
}

// ---------------- fp16 2-term complex GEMM core ------------------------------
#define STG 51200
#define GEMM_SMEM (2 * STG)
#define NCHUNK (DIMM / 32)

__device__ __forceinline__ void stage_load(uint32_t sA,
    const __half* const* Av, const __half* const* Bv,
    int m0, int e0, int k0, int tid)
{
    #pragma unroll
    for (int v = 0; v < 2; v++) {
        const __half* srcA = Av[v] + (size_t)m0 * DIMM + k0;
        uint32_t dstA = sA + v * 5120u;
        #pragma unroll
        for (int t = 0; t < 2; t++) {
            int idx = tid + t * 128;
            int r = idx >> 2, c = idx & 3;
            CP16(dstA + r * 80 + c * 16, srcA + (size_t)r * DIMM + c * 8);
        }
    }
    #pragma unroll
    for (int v = 0; v < 4; v++) {
        const __half* srcB = Bv[v] + (size_t)e0 * DIMM + k0;
        uint32_t dstB = sA + 10240u + v * 10240u;
        #pragma unroll
        for (int t = 0; t < 4; t++) {
            int idx = tid + t * 128;
            int r = idx >> 2, c = idx & 3;
            CP16(dstB + r * 80 + c * 16, srcB + (size_t)r * DIMM + c * 8);
        }
    }
}

__device__ __forceinline__ void gemm_compute(uint32_t ss, int lane, int wm, int wn,
    float accR[2][8][4], float accI[2][8][4])
{
    const uint32_t aRow = (uint32_t)(lane & 15);
    const uint32_t aSel = (uint32_t)(lane >> 4);
    const uint32_t nl   = (uint32_t)((lane & 7) + ((lane >> 4) << 3));
    const uint32_t ksel = (uint32_t)((lane >> 3) & 1);

    #pragma unroll
    for (int ks = 0; ks < 2; ks++) {
        uint32_t Ar[2][4], Ai[2][4], nAi[2][4];
        #pragma unroll
        for (int mf = 0; mf < 2; mf++) {
            uint32_t addr = ss + (wm * 32 + mf * 16 + aRow) * 80u
                            + aSel * 16u + ks * 32u;
            ldm_x4(Ar[mf], addr);
            ldm_x4(Ai[mf], addr + 5120u);
            #pragma unroll
            for (int q = 0; q < 4; q++) nAi[mf][q] = Ai[mf][q] ^ 0x80008000u;
        }
        #pragma unroll
        for (int h = 0; h < 4; h++) {
            uint32_t Bf[4][4];
            const uint32_t ba = ss + 10240u
                + (wn * 64 + h * 16 + nl) * 80u + ksel * 16u + ks * 32u;
            #pragma unroll
            for (int v = 0; v < 4; v++) ldm_x4(Bf[v], ba + v * 10240u);
            #pragma unroll
            for (int mf = 0; mf < 2; mf++)
                #pragma unroll
                for (int sub = 0; sub < 2; sub++) {
                    const int nf = h * 2 + sub;
                    const uint32_t* Brh = &Bf[0][sub * 2];
                    const uint32_t* Brl = &Bf[1][sub * 2];
                    const uint32_t* Bih = &Bf[2][sub * 2];
                    const uint32_t* Bil = &Bf[3][sub * 2];
                    float* cr = accR[mf][nf];
                    float* ci = accI[mf][nf];
                    mma16816h(cr, Ar[mf],  Brh);
                    mma16816h(cr, Ar[mf],  Brl);
                    mma16816h(cr, nAi[mf], Bih);
                    mma16816h(cr, nAi[mf], Bil);
                    mma16816h(ci, Ar[mf],  Bih);
                    mma16816h(ci, Ar[mf],  Bil);
                    mma16816h(ci, Ai[mf],  Brh);
                    mma16816h(ci, Ai[mf],  Brl);
                }
        }
    }
}

// ---------------- qkv GEMM: epilogue writes Karatsuba operand sets -----------
__global__ void __launch_bounds__(128, 2) qkv_mma_kernel(
    const float* __restrict__ br, const float* __restrict__ bi,
    const float* __restrict__ fr, const float* __restrict__ fi)
{
    extern __shared__ char smrw[];
    const uint32_t sb = smem_u32(smrw);
    const int tid = threadIdx.x, lane = tid & 31, wid = tid >> 5;
    const int wm = wid >> 1, wn = wid & 1;
    const int e0 = blockIdx.x * 128, m0 = blockIdx.y * 64;

    const __half* Av[2] = {g_Xr, g_Xi};
    const __half* Bv[4] = {g_Wqr_h, g_Wqr_l, g_Wqi_h, g_Wqi_l};

    float accR[2][8][4] = {}, accI[2][8][4] = {};

    stage_load(sb, Av, Bv, m0, e0, 0, tid);
    CP_COMMIT();

    #pragma unroll 1
    for (int c = 0; c < NCHUNK; c++) {
        const int s = c & 1;
        if (c + 1 < NCHUNK) {
            stage_load(sb + (s ^ 1) * STG, Av, Bv, m0, e0, (c + 1) * 32, tid);
            CP_COMMIT();
            CP_WAIT(1);
        } else {
            CP_WAIT(0);
        }
        __syncthreads();
        gemm_compute(sb + s * STG, lane, wm, wn, accR, accI);
        __syncthreads();
    }

    // ---- stage accumulators to smem as [e 128][m pitch 68] fp32 ----
    float* smr = (float*)smrw;
    float* smi = smr + 128 * 68;
    #pragma unroll
    for (int mf = 0; mf < 2; mf++)
        #pragma unroll
        for (int nf = 0; nf < 8; nf++)
            #pragma unroll
            for (int rp = 0; rp < 2; rp++)
                #pragma unroll
                for (int cp = 0; cp < 2; cp++) {
                    const int el = wn * 64 + nf * 8 + (lane & 3) * 2 + cp;
                    const int ml = wm * 32 + mf * 16 + (lane >> 2) + rp * 8;
                    smr[el * 68 + ml] = accR[mf][nf][rp * 2 + cp];
                    smi[el * 68 + ml] = accI[mf][nf][rp * 2 + cp];
                }
    __syncthreads();

    // ---- each thread: one e-column, packed n-run stores ----
    const int el = tid;
    const int e = e0 + el;
    const int h = e / 192, rem = e % 192;
    const int d = rem / 3, which = rem % 3;
    const float bre = br[e], bie = bi[e];
    const int b = m0 >> 10, n0 = m0 & 1023;
    const int bh = b * HEADS + h;
    const size_t dbase = (size_t)(bh * HD + d) * Nn + n0;
    const float* smr_e = smr + el * 68;
    const float* smi_e = smi + el * 68;

    __nv_bfloat16 *dRh, *dRl, *dIh, *dIl, *dSh, *dSl;
    float sgn = 1.f;
    if (which == 0) {
        dRh = g_Qrh; dRl = g_Qrl; dIh = g_Qih; dIl = g_Qil;
        dSh = g_Qsh; dSl = g_Qsl;
    } else {
        dRh = g_Krh; dRl = g_Krl; dIh = g_Kih; dIl = g_Kil;
        dSh = g_Kdh; dSl = g_Kdl; sgn = -1.f;
    }

    #pragma unroll 1
    for (int mc = 0; mc < 16; mc++) {
        float4 srv = *(const float4*)(smr_e + mc * 4);
        float4 siv = *(const float4*)(smi_e + mc * 4);
        float vr[4] = {srv.x + bre, srv.y + bre, srv.z + bre, srv.w + bre};
        float vi[4] = {siv.x + bie, siv.y + bie, siv.z + bie, siv.w + bie};
        if (which == 2) {
            *(uint2*)(g_Vr + dbase + mc * 4) =
                make_uint2(pack2h(vr[0], vr[1]), pack2h(vr[2], vr[3]));
            *(uint2*)(g_Vi + dbase + mc * 4) =
                make_uint2(pack2h(vi[0], vi[1]), pack2h(vi[2], vi[3]));
        } else {
            float ss[4];
            #pragma unroll
            for (int j = 0; j < 4; j++) {
                const int n = n0 + mc * 4 + j;
                const float frv = fr[n * HD + d], fiv = fi[n * HD + d];
                const float rr = vr[j] * frv - vi[j] * fiv;
                vi[j] = vr[j] * fiv + vi[j] * frv;
                vr[j] = rr;
                ss[j] = vr[j] + sgn * vi[j];
            }
            uint32_t h01, l01, h23, l23;
            split2(vr[0], vr[1], h01, l01);
            split2(vr[2], vr[3], h23, l23);
            *(uint2*)(dRh + dbase + mc * 4) = make_uint2(h01, h23);
            *(uint2*)(dRl + dbase + mc * 4) = make_uint2(l01, l23);
            split2(vi[0], vi[1], h01, l01);
            split2(vi[2], vi[3], h23, l23);
            *(uint2*)(dIh + dbase + mc * 4) = make_uint2(h01, h23);
            *(uint2*)(dIl + dbase + mc * 4) = make_uint2(l01, l23);
            split2(ss[0], ss[1], h01, l01);
            split2(ss[2], ss[3], h23, l23);
            *(uint2*)(dSh + dbase + mc * 4) = make_uint2(h01, h23);
            *(uint2*)(dSl + dbase + mc * 4) = make_uint2(l01, l23);
        }
    }
}

// ---------------- output GEMM ------------------------------------------------
__global__ void __launch_bounds__(128, 2) out_mma_kernel(
    const float* __restrict__ br, const float* __restrict__ bi,
    float* __restrict__ out)
{
    extern __shared__ char smrw[];
    const uint32_t sb = smem_u32(smrw);
    const int tid = threadIdx.x, lane = tid & 31, wid = tid >> 5;
    const int wm = wid >> 1, wn = wid & 1;
    const int e0 = blockIdx.x * 128, m0 = blockIdx.y * 64;

    const __half* Av[2] = {g_Ar, g_Ai};
    const __half* Bv[4] = {g_Wor_h, g_Wor_l, g_Woi_h, g_Woi_l};

    float accR[2][8][4] = {}, accI[2][8][4] = {};

    stage_load(sb, Av, Bv, m0, e0, 0, tid);
    CP_COMMIT();

    #pragma unroll 1
    for (int c = 0; c < NCHUNK; c++) {
        const int s = c & 1;
        if (c + 1 < NCHUNK) {
            stage_load(sb + (s ^ 1) * STG, Av, Bv, m0, e0, (c + 1) * 32, tid);
            CP_COMMIT();
            CP_WAIT(1);
        } else {
            CP_WAIT(0);
        }
        __syncthreads();
        gemm_compute(sb + s * STG, lane, wm, wn, accR, accI);
        __syncthreads();
    }

    #pragma unroll
    for (int mf = 0; mf < 2; mf++)
        #pragma unroll
        for (int nf = 0; nf < 8; nf++)
            #pragma unroll
            for (int rp = 0; rp < 2; rp++) {
                const int m = m0 + wm * 32 + mf * 16 + (lane >> 2) + rp * 8;
                const int e = e0 + wn * 64 + nf * 8 + (lane & 3) * 2;
                float2 vr = make_float2(accR[mf][nf][rp * 2] + br[e],
                                        accR[mf][nf][rp * 2 + 1] + br[e + 1]);
                float2 vi = make_float2(accI[mf][nf][rp * 2] + bi[e],
                                        accI[mf][nf][rp * 2 + 1] + bi[e + 1]);
                *(float2*)&out[(size_t)m * DIMM + e] = vr;
                *(float2*)&out[(size_t)Mtot * DIMM + (size_t)m * DIMM + e] = vi;
            }
}

// ---------------- flash attention: Karatsuba QK (bf16) + single-P fp16 PV ----
#define PCHQ 272
#define VQ   17408
#define PCHK 144
#define VKV  9216
#define AK_OFF (6 * VQ)                 // 104448
#define AV_OFF (AK_OFF + 6 * VKV)       // 159744
#define ATTN_SMEM (AV_OFF + 2 * VKV)    // 178176

__device__ __forceinline__ void attn_load_k(uint32_t sK,
    const __nv_bfloat16* const* Kv, int k0, int tid)
{
    #pragma unroll
    for (int v = 0; v < 6; v++)
        #pragma unroll
        for (int t = 0; t < 2; t++) {
            int i = tid + t * 256;
            int r = i >> 3, c = i & 7;
            CP16(sK + v * VKV + r * PCHK + c * 16,
                 Kv[v] + (size_t)r * Nn + k0 + c * 8);
        }
}

__device__ __forceinline__ void attn_load_v(uint32_t sV,
    const __half* const* Vv, int k0, int tid)
{
    #pragma unroll
    for (int v = 0; v < 2; v++)
        #pragma unroll
        for (int t = 0; t < 2; t++) {
            int i = tid + t * 256;
            int r = i >> 3, c = i & 7;
            CP16(sV + v * VKV + r * PCHK + c * 16,
                 Vv[v] + (size_t)r * Nn + k0 + c * 8);
        }
}

__global__ void __launch_bounds__(256, 1) attn_mma_kernel()
{
    extern __shared__ char smrw[];
    const uint32_t sb = smem_u32(smrw);
    const int tid = threadIdx.x, lane = tid & 31, wid = tid >> 5;
    const int bh = blockIdx.y, q0 = blockIdx.x * 128;
    const size_t base = (size_t)bh * Nn * HD;

    const __nv_bfloat16* Qv[6] = {g_Qrh + base, g_Qrl + base, g_Qih + base,
                                  g_Qil + base, g_Qsh + base, g_Qsl + base};
    const __nv_bfloat16* Kv[6] = {g_Krh + base, g_Krl + base, g_Kih + base,
                                  g_Kil + base, g_Kdh + base, g_Kdl + base};
    const __half* Vv[2] = {g_Vr + base, g_Vi + base};

    #pragma unroll
    for (int v = 0; v < 6; v++)
        #pragma unroll
        for (int t = 0; t < 4; t++) {
            int i = tid + t * 256;
            int r = i >> 4, c = i & 15;
            CP16(sb + v * VQ + r * PCHQ + c * 16, Qv[v] + (size_t)r * Nn + q0 + c * 8);
        }
    attn_load_k(sb + AK_OFF, Kv, 0, tid);
    CP_COMMIT();
    attn_load_v(sb + AV_OFF, Vv, 0, tid);
    CP_COMMIT();

    float oR[8][4] = {}, oI[8][4] = {};
    float m0 = -1e30f, m1 = -1e30f, l0 = 0.f, l1 = 0.f;
    const int r0 = wid * 16;
    const uint32_t sK = sb + AK_OFF;
    const uint32_t sV = sb + AV_OFF;

    #pragma unroll 1
    for (int kt = 0; kt < 16; kt++) {
        CP_WAIT(1);
        __syncthreads();

        // ---- Karatsuba S = Q . conj(K): t1=QrKr, t2=QiKi, t3=Qs*Kd ----
        float t1[8][4] = {}, t2[8][4] = {}, t3[8][4] = {};
        #pragma unroll
        for (int ks = 0; ks < 4; ks++) {
            uint32_t Qf[6][4];
            const uint32_t qa = sb
                + (ks * 16 + (lane & 7) + ((lane >> 4) & 1) * 8) * PCHQ
                + (r0 + ((lane >> 3) & 1) * 8) * 2;
            #pragma unroll
            for (int v = 0; v < 6; v++) ldm_x4_t(Qf[v], qa + v * VQ);
            #pragma unroll
            for (int np = 0; np < 4; np++) {
                uint32_t Kf[6][4];
                const uint32_t ka = sK
                    + (ks * 16 + (lane & 7) + ((lane >> 3) & 1) * 8) * PCHK
                    + (np * 16 + ((lane >> 4) & 1) * 8) * 2;
                #pragma unroll
                for (int v = 0; v < 6; v++) ldm_x4_t(Kf[v], ka + v * VKV);
                #pragma unroll
                for (int sub = 0; sub < 2; sub++) {
                    const int nt = np * 2 + sub;
                    const uint32_t* Krh = &Kf[0][sub * 2];
                    const uint32_t* Krl = &Kf[1][sub * 2];
                    const uint32_t* Kih = &Kf[2][sub * 2];
                    const uint32_t* Kil = &Kf[3][sub * 2];
                    const uint32_t* Kdh = &Kf[4][sub * 2];
                    const uint32_t* Kdl = &Kf[5][sub * 2];
                    mma16816(t1[nt], Qf[0], Krh);
                    mma16816(t1[nt], Qf[0], Krl);
                    mma16816(t1[nt], Qf[1], Krh);
                    mma16816(t2[nt], Qf[2], Kih);
                    mma16816(t2[nt], Qf[2], Kil);
                    mma16816(t2[nt], Qf[3], Kih);
                    mma16816(t3[nt], Qf[4], Kdh);
                    mma16816(t3[nt], Qf[4], Kdl);
                    mma16816(t3[nt], Qf[5], Kdh);
                }
            }
        }

        __syncthreads();
        if (kt + 1 < 16) {
            attn_load_k(sK, Kv, (kt + 1) * 64, tid);
            CP_COMMIT();
        }

        // ---- recombine + scaled abs (approx sqrt): reuse t1 as P ----
        float vm0 = -1e30f, vm1 = -1e30f;
        #pragma unroll
        for (int nt = 0; nt < 8; nt++)
            #pragma unroll
            for (int p = 0; p < 4; p++) {
                const float re = t1[nt][p] + t2[nt][p];
                const float im = t3[nt][p] - t1[nt][p] + t2[nt][p];
                const float v = 0.125f * sqrt_approx(re * re + im * im);
                t1[nt][p] = v;
                if (p < 2) vm0 = fmaxf(vm0, v); else vm1 = fmaxf(vm1, v);
            }
        vm0 = fmaxf(vm0, __shfl_xor_sync(0xffffffffu, vm0, 1));
        vm0 = fmaxf(vm0, __shfl_xor_sync(0xffffffffu, vm0, 2));
        vm1 = fmaxf(vm1, __shfl_xor_sync(0xffffffffu, vm1, 1));
        vm1 = fmaxf(vm1, __shfl_xor_sync(0xffffffffu, vm1, 2));
        const float mn0 = fmaxf(m0, vm0), mn1 = fmaxf(m1, vm1);
        const float a0 = __expf(m0 - mn0), a1 = __expf(m1 - mn1);
        m0 = mn0; m1 = mn1;
        if (a0 != 1.0f || a1 != 1.0f) {        // bit-identical skip
            #pragma unroll
            for (int nt = 0; nt < 8; nt++)
                #pragma unroll
                for (int p = 0; p < 4; p++) {
                    const float al = (p < 2) ? a0 : a1;
                    oR[nt][p] *= al;
                    oI[nt][p] *= al;
                }
        }
        float s0 = 0.f, s1 = 0.f;
        #pragma unroll
        for (int nt = 0; nt < 8; nt++)
            #pragma unroll
            for (int p = 0; p < 4; p++) {
                const float pv = __expf(t1[nt][p] - ((p < 2) ? mn0 : mn1));
                t1[nt][p] = pv;
                if (p < 2) s0 += pv; else s1 += pv;
            }
        s0 += __shfl_xor_sync(0xffffffffu, s0, 1);
        s0 += __shfl_xor_sync(0xffffffffu, s0, 2);
        s1 += __shfl_xor_sync(0xffffffffu, s1, 1);
        s1 += __shfl_xor_sync(0xffffffffu, s1, 2);
        l0 = l0 * a0 + s0;
        l1 = l1 * a1 + s1;

        // ---- pack P into single-fp16 A-fragments ----
        uint32_t Pp[4][4];
        #pragma unroll
        for (int j = 0; j < 4; j++) {
            const int u0 = 2 * j, u1 = 2 * j + 1;
            Pp[j][0] = pack2h(t1[u0][0], t1[u0][1]);
            Pp[j][1] = pack2h(t1[u0][2], t1[u0][3]);
            Pp[j][2] = pack2h(t1[u1][0], t1[u1][1]);
            Pp[j][3] = pack2h(t1[u1][2], t1[u1][3]);
        }

        if (kt < 15) { CP_WAIT(1); } else { CP_WAIT(0); }
        __syncthreads();

        // ---- O += P @ V (single-P fp16) ----
        #pragma unroll
        for (int j = 0; j < 4; j++) {
            #pragma unroll
            for (int g = 0; g < 4; g++) {
                uint32_t Vrf[4], Vif[4];
                const uint32_t va = sV
                    + (g * 16 + (lane & 7) + ((lane >> 4) & 1) * 8) * PCHK
                    + j * 32 + ((lane >> 3) & 1) * 16;
                ldm_x4(Vrf, va);
                ldm_x4(Vif, va + VKV);
                #pragma unroll
                for (int sub = 0; sub < 2; sub++) {
                    const int nt = g * 2 + sub;
                    mma16816h(oR[nt], Pp[j], &Vrf[sub * 2]);
                    mma16816h(oI[nt], Pp[j], &Vif[sub * 2]);
                }
            }
        }

        __syncthreads();
        if (kt + 1 < 16) {
            attn_load_v(sV, Vv, (kt + 1) * 64, tid);
            CP_COMMIT();
        }
    }

    const float inv0 = 1.0f / l0, inv1 = 1.0f / l1;
    const int b = bh / HEADS, h = bh % HEADS;
    #pragma unroll
    for (int nt = 0; nt < 8; nt++)
        #pragma unroll
        for (int rp = 0; rp < 2; rp++) {
            const int n = q0 + r0 + (lane >> 2) + rp * 8;
            const int d0 = nt * 8 + (lane & 3) * 2;
            const float inv = (rp == 0) ? inv0 : inv1;
            const size_t idx = ((size_t)(b * Nn + n)) * DIMM + h * HD + d0;
            *(uint32_t*)(g_Ar + idx) =
                pack2h(oR[nt][rp * 2] * inv, oR[nt][rp * 2 + 1] * inv);
            *(uint32_t*)(g_Ai + idx) =
                pack2h(oI[nt][rp * 2] * inv, oI[nt][rp * 2 + 1] * inv);
        }
}

// ---------------- launch ------------------------------------------------------
extern "C" void kernel_launch(void* const* d_in, const int* in_sizes, int n_in,
                              void* d_out, int out_size)
{
    const float* xr  = (const float*)d_in[0];
    const float* xi  = (const float*)d_in[1];
    const float* fr  = (const float*)d_in[2];
    const float* fi  = (const float*)d_in[3];
    const float* wqr = (const float*)d_in[4];
    const float* wqi = (const float*)d_in[5];
    const float* bqr = (const float*)d_in[6];
    const float* bqi = (const float*)d_in[7];
    const float* wor = (const float*)d_in[8];
    const float* woi = (const float*)d_in[9];
    const float* bor = (const float*)d_in[10];
    const float* boi = (const float*)d_in[11];
    float* out = (float*)d_out;

    cudaFuncSetAttribute(qkv_mma_kernel,
                         cudaFuncAttributeMaxDynamicSharedMemorySize, GEMM_SMEM);
    cudaFuncSetAttribute(out_mma_kernel,
                         cudaFuncAttributeMaxDynamicSharedMemorySize, GEMM_SMEM);
    cudaFuncSetAttribute(attn_mma_kernel,
                         cudaFuncAttributeMaxDynamicSharedMemorySize, ATTN_SMEM);

    split_all_kernel<<<6144, 256>>>(xr, xi, wqr, wqi, wor, woi);
    qkv_mma_kernel<<<dim3(E3 / 128, Mtot / 64), 128, GEMM_SMEM>>>(bqr, bqi, fr, fi);
    attn_mma_kernel<<<dim3(Nn / 128, Bb * HEADS), 256, ATTN_SMEM>>>();
    out_mma_kernel<<<dim3(DIMM / 128, Mtot / 64), 128, GEMM_SMEM>>>(bor, boi, out);
}